// round 2
// baseline (speedup 1.0000x reference)
#include <cuda_runtime.h>
#include <math.h>

#define NN   50000
#define CC   256
#define HH   8
#define HDIM 32
#define MM   800000      // NN * 16 edges
#define HIDN 1024
#define QK_SCALE 0.17677669529663687f   // 32^-0.5
#define LN_EPS 1e-5f

// ---------------- scratch (static device globals; no allocation) -------------
__device__ __align__(16) float g_xn [NN * CC];          // LN1 output
__device__ __align__(16) float g_qkv[NN * 3 * CC];      // qkv projections
__device__ __align__(16) float g_att[NN * CC];          // attention output
__device__ __align__(16) float g_f2 [NN * CC];          // feats after proj+skip
__device__ __align__(16) float g_y  [NN * CC];          // LN2 output
__device__ __align__(16) float g_h1 [NN * HIDN];        // fc1+gelu output
__device__ int g_cnt[NN];
__device__ int g_rowptr[NN + 1];
__device__ int g_cursor[NN];
__device__ int g_bsums[128];
__device__ int g_nbr[MM];

// ---------------- CSR build --------------------------------------------------
// edge_index is int32 on device (JAX default x64-disabled downcasts int64).
__global__ void zero_cnt_kernel() {
    int i = blockIdx.x * blockDim.x + threadIdx.x;
    if (i < NN) g_cnt[i] = 0;
}

__global__ void count_kernel(const int* __restrict__ ei) {
    int e = blockIdx.x * blockDim.x + threadIdx.x;
    if (e < MM) atomicAdd(&g_cnt[ei[e]], 1);
}

#define SCAN_B 512
__global__ void scan1_kernel() {
    __shared__ int sh[SCAN_B];
    int tid = threadIdx.x;
    int i = blockIdx.x * SCAN_B + tid;
    int v = (i < NN) ? g_cnt[i] : 0;
    sh[tid] = v;
    __syncthreads();
    for (int off = 1; off < SCAN_B; off <<= 1) {
        int t = (tid >= off) ? sh[tid - off] : 0;
        __syncthreads();
        sh[tid] += t;
        __syncthreads();
    }
    if (i < NN) g_rowptr[i] = sh[tid] - v;     // exclusive within block
    if (tid == SCAN_B - 1) g_bsums[blockIdx.x] = sh[tid];
}

__global__ void scan2_kernel(int nb) {
    if (threadIdx.x == 0 && blockIdx.x == 0) {
        int a = 0;
        for (int i = 0; i < nb; i++) { int t = g_bsums[i]; g_bsums[i] = a; a += t; }
    }
}

__global__ void scan3_kernel() {
    int i = blockIdx.x * SCAN_B + threadIdx.x;
    if (i < NN) {
        int v = g_rowptr[i] + g_bsums[blockIdx.x];
        g_rowptr[i] = v;
        g_cursor[i] = v;
    }
    if (i == 0) g_rowptr[NN] = MM;
}

__global__ void scatter_kernel(const int* __restrict__ ei) {
    int e = blockIdx.x * blockDim.x + threadIdx.x;
    if (e < MM) {
        int n = ei[e];
        int p = atomicAdd(&g_cursor[n], 1);
        g_nbr[p] = ei[MM + e];
    }
}

// ---------------- LayerNorm (one warp per row, C=256) ------------------------
__global__ void ln_kernel(const float* __restrict__ x, const float* __restrict__ g,
                          const float* __restrict__ b, float* __restrict__ y)
{
    int row  = blockIdx.x * 8 + (threadIdx.x >> 5);
    int lane = threadIdx.x & 31;
    if (row >= NN) return;
    const float4* xr = (const float4*)(x + (size_t)row * CC);
    float4 a = xr[lane];
    float4 c = xr[lane + 32];
    float s = a.x + a.y + a.z + a.w + c.x + c.y + c.z + c.w;
    float q = a.x*a.x + a.y*a.y + a.z*a.z + a.w*a.w
            + c.x*c.x + c.y*c.y + c.z*c.z + c.w*c.w;
    #pragma unroll
    for (int o = 16; o; o >>= 1) {
        s += __shfl_xor_sync(0xffffffffu, s, o);
        q += __shfl_xor_sync(0xffffffffu, q, o);
    }
    float mean = s * (1.0f / CC);
    float var  = q * (1.0f / CC) - mean * mean;
    float rstd = rsqrtf(var + LN_EPS);
    const float4* gv = (const float4*)g;
    const float4* bv = (const float4*)b;
    float4 g1 = gv[lane], g2 = gv[lane + 32];
    float4 b1 = bv[lane], b2 = bv[lane + 32];
    float4 o1, o2;
    o1.x = (a.x - mean) * rstd * g1.x + b1.x;
    o1.y = (a.y - mean) * rstd * g1.y + b1.y;
    o1.z = (a.z - mean) * rstd * g1.z + b1.z;
    o1.w = (a.w - mean) * rstd * g1.w + b1.w;
    o2.x = (c.x - mean) * rstd * g2.x + b2.x;
    o2.y = (c.y - mean) * rstd * g2.y + b2.y;
    o2.z = (c.z - mean) * rstd * g2.z + b2.z;
    o2.w = (c.w - mean) * rstd * g2.w + b2.w;
    float4* yr = (float4*)(y + (size_t)row * CC);
    yr[lane]      = o1;
    yr[lane + 32] = o2;
}

// ---------------- SGEMM: C[M,N] = A[M,K] @ B[N,K]^T + bias (+epilogue) -------
#define BM 128
#define BN 128
#define BK 16
#define TM 8
#define TN 8

#define EPI_NONE 0
#define EPI_GELU 1
#define EPI_RES  2

__global__ __launch_bounds__(256, 2)
void sgemm_kernel(const float* __restrict__ A, const float* __restrict__ B,
                  const float* __restrict__ bias, const float* __restrict__ resid,
                  float* __restrict__ C, int M, int Nn, int Kk, int epi)
{
    __shared__ float As[BK][BM];
    __shared__ float Bs[BK][BN];
    const int tid  = threadIdx.x;
    const int row0 = blockIdx.y * BM;
    const int col0 = blockIdx.x * BN;
    const int tr = tid / 16;
    const int tc = tid % 16;
    const int lr = tid >> 2;          // 0..63
    const int lc = (tid & 3) << 2;    // 0,4,8,12

    float acc[TM][TN];
    #pragma unroll
    for (int i = 0; i < TM; i++)
        #pragma unroll
        for (int j = 0; j < TN; j++) acc[i][j] = 0.0f;

    for (int k0 = 0; k0 < Kk; k0 += BK) {
        #pragma unroll
        for (int i = 0; i < BM; i += 64) {
            int r = row0 + lr + i;
            float4 v = (r < M) ? *(const float4*)(&A[(size_t)r * Kk + k0 + lc])
                               : make_float4(0.f, 0.f, 0.f, 0.f);
            As[lc + 0][lr + i] = v.x;
            As[lc + 1][lr + i] = v.y;
            As[lc + 2][lr + i] = v.z;
            As[lc + 3][lr + i] = v.w;
        }
        #pragma unroll
        for (int i = 0; i < BN; i += 64) {
            int r = col0 + lr + i;              // N is always a multiple of 128
            float4 v = *(const float4*)(&B[(size_t)r * Kk + k0 + lc]);
            Bs[lc + 0][lr + i] = v.x;
            Bs[lc + 1][lr + i] = v.y;
            Bs[lc + 2][lr + i] = v.z;
            Bs[lc + 3][lr + i] = v.w;
        }
        __syncthreads();
        #pragma unroll
        for (int k = 0; k < BK; k++) {
            float rm[TM], rn[TN];
            #pragma unroll
            for (int i = 0; i < TM; i++) rm[i] = As[k][tr * TM + i];
            #pragma unroll
            for (int j = 0; j < TN; j++) rn[j] = Bs[k][tc * TN + j];
            #pragma unroll
            for (int i = 0; i < TM; i++)
                #pragma unroll
                for (int j = 0; j < TN; j++) acc[i][j] += rm[i] * rn[j];
        }
        __syncthreads();
    }

    #pragma unroll
    for (int i = 0; i < TM; i++) {
        int r = row0 + tr * TM + i;
        if (r >= M) continue;
        #pragma unroll
        for (int j = 0; j < TN; j++) {
            int c = col0 + tc * TN + j;
            float v = acc[i][j] + bias[c];
            if (epi == EPI_GELU) {
                v = 0.5f * v * (1.0f + erff(v * 0.70710678118654752f));
            } else if (epi == EPI_RES) {
                v += resid[(size_t)r * Nn + c];
            }
            C[(size_t)r * Nn + c] = v;
        }
    }
}

// ---------------- Edge-softmax attention: warp per (node, head) --------------
__global__ void attn_kernel(float* __restrict__ out)
{
    int n    = blockIdx.x;
    int h    = threadIdx.x >> 5;
    int lane = threadIdx.x & 31;
    const float* qr = g_qkv + (size_t)n * (3 * CC) + h * HDIM;
    float q = qr[lane] * QK_SCALE;
    int s = g_rowptr[n];
    int e = g_rowptr[n + 1];
    float m = -INFINITY, l = 0.0f, acc = 0.0f;
    for (int i = s; i < e; i++) {
        int j = g_nbr[i];
        const float* base = g_qkv + (size_t)j * (3 * CC) + h * HDIM;
        float kk = base[CC + lane];       // k
        float vv = base[2 * CC + lane];   // v
        float d = q * kk;
        #pragma unroll
        for (int o = 16; o; o >>= 1) d += __shfl_xor_sync(0xffffffffu, d, o);
        float mn = fmaxf(m, d);
        float sc = __expf(m - mn);        // first iter: exp(-inf)=0
        float p  = __expf(d - mn);
        l   = l * sc + p;
        acc = acc * sc + p * vv;
        m = mn;
    }
    float o = (l > 0.0f) ? acc / l : 0.0f;
    out[(size_t)n * CC + h * HDIM + lane] = o;
}

// ---------------- host launcher ---------------------------------------------
extern "C" void kernel_launch(void* const* d_in, const int* in_sizes, int n_in,
                              void* d_out, int out_size)
{
    const float* feats  = (const float*)d_in[0];
    const int*   ei     = (const int*)d_in[2];      // int32 (JAX x64 disabled)
    const float* ln1_g  = (const float*)d_in[3];
    const float* ln1_b  = (const float*)d_in[4];
    const float* qkv_w  = (const float*)d_in[5];
    const float* qkv_b  = (const float*)d_in[6];
    const float* proj_w = (const float*)d_in[7];
    const float* proj_b = (const float*)d_in[8];
    const float* ln2_g  = (const float*)d_in[9];
    const float* ln2_b  = (const float*)d_in[10];
    const float* fc1_w  = (const float*)d_in[11];
    const float* fc1_b  = (const float*)d_in[12];
    const float* fc2_w  = (const float*)d_in[13];
    const float* fc2_b  = (const float*)d_in[14];
    float* out = (float*)d_out;

    float *p_xn, *p_qkv, *p_att, *p_f2, *p_y, *p_h1;
    cudaGetSymbolAddress((void**)&p_xn,  g_xn);
    cudaGetSymbolAddress((void**)&p_qkv, g_qkv);
    cudaGetSymbolAddress((void**)&p_att, g_att);
    cudaGetSymbolAddress((void**)&p_f2,  g_f2);
    cudaGetSymbolAddress((void**)&p_y,   g_y);
    cudaGetSymbolAddress((void**)&p_h1,  g_h1);

    const int nscan = (NN + SCAN_B - 1) / SCAN_B;   // 98

    // CSR build
    zero_cnt_kernel<<<(NN + 255) / 256, 256>>>();
    count_kernel<<<(MM + 255) / 256, 256>>>(ei);
    scan1_kernel<<<nscan, SCAN_B>>>();
    scan2_kernel<<<1, 32>>>(nscan);
    scan3_kernel<<<nscan, SCAN_B>>>();
    scatter_kernel<<<(MM + 255) / 256, 256>>>(ei);

    // LN1
    ln_kernel<<<(NN + 7) / 8, 256>>>(feats, ln1_g, ln1_b, p_xn);

    // qkv = xn @ qkv_w^T + b   (M=NN, N=768, K=256)
    {
        dim3 grid(768 / BN, (NN + BM - 1) / BM);
        sgemm_kernel<<<grid, 256>>>(p_xn, qkv_w, qkv_b, nullptr, p_qkv,
                                    NN, 768, CC, EPI_NONE);
    }

    // attention
    attn_kernel<<<NN, 256>>>(p_att);

    // feats2 = feats + att @ proj_w^T + proj_b
    {
        dim3 grid(CC / BN, (NN + BM - 1) / BM);
        sgemm_kernel<<<grid, 256>>>(p_att, proj_w, proj_b, feats, p_f2,
                                    NN, CC, CC, EPI_RES);
    }

    // LN2
    ln_kernel<<<(NN + 7) / 8, 256>>>(p_f2, ln2_g, ln2_b, p_y);

    // h1 = gelu(y @ fc1_w^T + b)
    {
        dim3 grid(HIDN / BN, (NN + BM - 1) / BM);
        sgemm_kernel<<<grid, 256>>>(p_y, fc1_w, fc1_b, nullptr, p_h1,
                                    NN, HIDN, CC, EPI_GELU);
    }

    // out = feats2 + h1 @ fc2_w^T + b
    {
        dim3 grid(CC / BN, (NN + BM - 1) / BM);
        sgemm_kernel<<<grid, 256>>>(p_h1, fc2_w, fc2_b, p_f2, out,
                                    NN, CC, HIDN, EPI_RES);
    }
}

// round 4
// speedup vs baseline: 1.4362x; 1.4362x over previous
#include <cuda_runtime.h>
#include <cuda_bf16.h>
#include <math.h>

#define NN   50000
#define CC   256
#define HH   8
#define HDIM 32
#define MM   800000      // NN * 16 edges
#define HIDN 1024
#define QK_SCALE 0.17677669529663687f   // 32^-0.5
#define LN_EPS 1e-5f

// ---------------- scratch (static device globals; no allocation) -------------
__device__ __align__(16) float g_xn [NN * CC];          // LN1 output
__device__ __align__(16) float g_qkv[NN * 3 * CC];      // qkv projections
__device__ __align__(16) float g_att[NN * CC];          // attention output
__device__ __align__(16) float g_f2 [NN * CC];          // feats after proj+skip
__device__ __align__(16) float g_y  [NN * CC];          // LN2 output
__device__ __align__(16) float g_h1 [NN * HIDN];        // fc1+gelu output
__device__ int g_cnt[NN];
__device__ int g_rowptr[NN + 1];
__device__ int g_cursor[NN];
__device__ int g_bsums[128];
__device__ int g_nbr[MM];

// ---------------- CSR build --------------------------------------------------
__global__ void zero_cnt_kernel() {
    int i = blockIdx.x * blockDim.x + threadIdx.x;
    if (i < NN) g_cnt[i] = 0;
}

__global__ void count_kernel(const int* __restrict__ ei) {
    int e = blockIdx.x * blockDim.x + threadIdx.x;
    if (e < MM) atomicAdd(&g_cnt[ei[e]], 1);
}

#define SCAN_B 512
__global__ void scan1_kernel() {
    __shared__ int sh[SCAN_B];
    int tid = threadIdx.x;
    int i = blockIdx.x * SCAN_B + tid;
    int v = (i < NN) ? g_cnt[i] : 0;
    sh[tid] = v;
    __syncthreads();
    for (int off = 1; off < SCAN_B; off <<= 1) {
        int t = (tid >= off) ? sh[tid - off] : 0;
        __syncthreads();
        sh[tid] += t;
        __syncthreads();
    }
    if (i < NN) g_rowptr[i] = sh[tid] - v;
    if (tid == SCAN_B - 1) g_bsums[blockIdx.x] = sh[tid];
}

__global__ void scan2_kernel(int nb) {
    if (threadIdx.x == 0 && blockIdx.x == 0) {
        int a = 0;
        for (int i = 0; i < nb; i++) { int t = g_bsums[i]; g_bsums[i] = a; a += t; }
    }
}

__global__ void scan3_kernel() {
    int i = blockIdx.x * SCAN_B + threadIdx.x;
    if (i < NN) {
        int v = g_rowptr[i] + g_bsums[blockIdx.x];
        g_rowptr[i] = v;
        g_cursor[i] = v;
    }
    if (i == 0) g_rowptr[NN] = MM;
}

__global__ void scatter_kernel(const int* __restrict__ ei) {
    int e = blockIdx.x * blockDim.x + threadIdx.x;
    if (e < MM) {
        int n = ei[e];
        int p = atomicAdd(&g_cursor[n], 1);
        g_nbr[p] = ei[MM + e];
    }
}

// ---------------- LayerNorm (one warp per row, C=256) ------------------------
__global__ void ln_kernel(const float* __restrict__ x, const float* __restrict__ g,
                          const float* __restrict__ b, float* __restrict__ y)
{
    int row  = blockIdx.x * 8 + (threadIdx.x >> 5);
    int lane = threadIdx.x & 31;
    if (row >= NN) return;
    const float4* xr = (const float4*)(x + (size_t)row * CC);
    float4 a = xr[lane];
    float4 c = xr[lane + 32];
    float s = a.x + a.y + a.z + a.w + c.x + c.y + c.z + c.w;
    float q = a.x*a.x + a.y*a.y + a.z*a.z + a.w*a.w
            + c.x*c.x + c.y*c.y + c.z*c.z + c.w*c.w;
    #pragma unroll
    for (int o = 16; o; o >>= 1) {
        s += __shfl_xor_sync(0xffffffffu, s, o);
        q += __shfl_xor_sync(0xffffffffu, q, o);
    }
    float mean = s * (1.0f / CC);
    float var  = q * (1.0f / CC) - mean * mean;
    float rstd = rsqrtf(var + LN_EPS);
    const float4* gv = (const float4*)g;
    const float4* bv = (const float4*)b;
    float4 g1 = gv[lane], g2 = gv[lane + 32];
    float4 b1 = bv[lane], b2 = bv[lane + 32];
    float4 o1, o2;
    o1.x = (a.x - mean) * rstd * g1.x + b1.x;
    o1.y = (a.y - mean) * rstd * g1.y + b1.y;
    o1.z = (a.z - mean) * rstd * g1.z + b1.z;
    o1.w = (a.w - mean) * rstd * g1.w + b1.w;
    o2.x = (c.x - mean) * rstd * g2.x + b2.x;
    o2.y = (c.y - mean) * rstd * g2.y + b2.y;
    o2.z = (c.z - mean) * rstd * g2.z + b2.z;
    o2.w = (c.w - mean) * rstd * g2.w + b2.w;
    float4* yr = (float4*)(y + (size_t)row * CC);
    yr[lane]      = o1;
    yr[lane + 32] = o2;
}

// ---------------- bf16-split tensor-core GEMM --------------------------------
// C[M,N] = A[M,K] @ B[N,K]^T + bias (+epilogue), fp32 in/out.
// A,B split in smem: x = hi + lo (bf16 each).  C ~= hiA@hiB + hiA@loB + loA@hiB.
#define BM 128
#define BN 128
#define BK 32
#define BKP 36          // padded row length (bf16 elems) to dodge bank conflicts

#define EPI_NONE 0
#define EPI_GELU 1
#define EPI_RES  2

__device__ __forceinline__ void mma_bf16(float4& d,
    unsigned a0, unsigned a1, unsigned a2, unsigned a3,
    unsigned b0, unsigned b1)
{
    asm volatile(
        "mma.sync.aligned.m16n8k16.row.col.f32.bf16.bf16.f32 "
        "{%0,%1,%2,%3},{%4,%5,%6,%7},{%8,%9},{%0,%1,%2,%3};"
        : "+f"(d.x), "+f"(d.y), "+f"(d.z), "+f"(d.w)
        : "r"(a0), "r"(a1), "r"(a2), "r"(a3), "r"(b0), "r"(b1));
}

__global__ __launch_bounds__(256)
void gemm_bf16s_kernel(const float* __restrict__ A, const float* __restrict__ B,
                       const float* __restrict__ bias, const float* __restrict__ resid,
                       float* __restrict__ C, int M, int Nn, int Kk, int epi)
{
    __shared__ __nv_bfloat16 As_hi[BM][BKP];
    __shared__ __nv_bfloat16 As_lo[BM][BKP];
    __shared__ __nv_bfloat16 Bs_hi[BN][BKP];
    __shared__ __nv_bfloat16 Bs_lo[BN][BKP];

    const int tid  = threadIdx.x;
    const int row0 = blockIdx.y * BM;
    const int col0 = blockIdx.x * BN;
    const int warp   = tid >> 5;
    const int lane   = tid & 31;
    const int warp_m = warp >> 2;       // 0..1  (64 rows each)
    const int warp_n = warp & 3;        // 0..3  (32 cols each)
    const int g = lane >> 2;            // 0..7
    const int t = lane & 3;             // 0..3

    const int f    = tid & 7;           // float4 index within 32-wide k tile
    const int rloc = tid >> 3;          // 0..31

    float4 acc[4][4];
    #pragma unroll
    for (int i = 0; i < 4; i++)
        #pragma unroll
        for (int j = 0; j < 4; j++) acc[i][j] = make_float4(0.f, 0.f, 0.f, 0.f);

    for (int k0 = 0; k0 < Kk; k0 += BK) {
        // stage A (with M guard) and B, splitting fp32 -> hi/lo bf16
        #pragma unroll
        for (int i = 0; i < 4; i++) {
            int r = rloc + 32 * i;
            int gr = row0 + r;
            float4 v = (gr < M) ? *(const float4*)(&A[(size_t)gr * Kk + k0 + f * 4])
                                : make_float4(0.f, 0.f, 0.f, 0.f);
            __nv_bfloat16 h0 = __float2bfloat16_rn(v.x);
            __nv_bfloat16 h1 = __float2bfloat16_rn(v.y);
            __nv_bfloat16 h2 = __float2bfloat16_rn(v.z);
            __nv_bfloat16 h3 = __float2bfloat16_rn(v.w);
            __nv_bfloat16 l0 = __float2bfloat16_rn(v.x - __bfloat162float(h0));
            __nv_bfloat16 l1 = __float2bfloat16_rn(v.y - __bfloat162float(h1));
            __nv_bfloat16 l2 = __float2bfloat16_rn(v.z - __bfloat162float(h2));
            __nv_bfloat16 l3 = __float2bfloat16_rn(v.w - __bfloat162float(h3));
            As_hi[r][f*4+0] = h0; As_hi[r][f*4+1] = h1;
            As_hi[r][f*4+2] = h2; As_hi[r][f*4+3] = h3;
            As_lo[r][f*4+0] = l0; As_lo[r][f*4+1] = l1;
            As_lo[r][f*4+2] = l2; As_lo[r][f*4+3] = l3;
        }
        #pragma unroll
        for (int i = 0; i < 4; i++) {
            int r = rloc + 32 * i;
            int gr = col0 + r;          // N always multiple of 128
            float4 v = *(const float4*)(&B[(size_t)gr * Kk + k0 + f * 4]);
            __nv_bfloat16 h0 = __float2bfloat16_rn(v.x);
            __nv_bfloat16 h1 = __float2bfloat16_rn(v.y);
            __nv_bfloat16 h2 = __float2bfloat16_rn(v.z);
            __nv_bfloat16 h3 = __float2bfloat16_rn(v.w);
            __nv_bfloat16 l0 = __float2bfloat16_rn(v.x - __bfloat162float(h0));
            __nv_bfloat16 l1 = __float2bfloat16_rn(v.y - __bfloat162float(h1));
            __nv_bfloat16 l2 = __float2bfloat16_rn(v.z - __bfloat162float(h2));
            __nv_bfloat16 l3 = __float2bfloat16_rn(v.w - __bfloat162float(h3));
            Bs_hi[r][f*4+0] = h0; Bs_hi[r][f*4+1] = h1;
            Bs_hi[r][f*4+2] = h2; Bs_hi[r][f*4+3] = h3;
            Bs_lo[r][f*4+0] = l0; Bs_lo[r][f*4+1] = l1;
            Bs_lo[r][f*4+2] = l2; Bs_lo[r][f*4+3] = l3;
        }
        __syncthreads();

        #pragma unroll
        for (int s = 0; s < 2; s++) {   // two k16 steps
            const int c = s * 16 + 2 * t;
            unsigned bh[4][2], bl[4][2];
            #pragma unroll
            for (int ni = 0; ni < 4; ni++) {
                int n = warp_n * 32 + ni * 8 + g;
                bh[ni][0] = *(const unsigned*)&Bs_hi[n][c];
                bh[ni][1] = *(const unsigned*)&Bs_hi[n][c + 8];
                bl[ni][0] = *(const unsigned*)&Bs_lo[n][c];
                bl[ni][1] = *(const unsigned*)&Bs_lo[n][c + 8];
            }
            #pragma unroll
            for (int mi = 0; mi < 4; mi++) {
                int r = warp_m * 64 + mi * 16 + g;
                unsigned ah0 = *(const unsigned*)&As_hi[r    ][c];
                unsigned ah1 = *(const unsigned*)&As_hi[r + 8][c];
                unsigned ah2 = *(const unsigned*)&As_hi[r    ][c + 8];
                unsigned ah3 = *(const unsigned*)&As_hi[r + 8][c + 8];
                unsigned al0 = *(const unsigned*)&As_lo[r    ][c];
                unsigned al1 = *(const unsigned*)&As_lo[r + 8][c];
                unsigned al2 = *(const unsigned*)&As_lo[r    ][c + 8];
                unsigned al3 = *(const unsigned*)&As_lo[r + 8][c + 8];
                #pragma unroll
                for (int ni = 0; ni < 4; ni++) {
                    mma_bf16(acc[mi][ni], ah0, ah1, ah2, ah3, bh[ni][0], bh[ni][1]);
                    mma_bf16(acc[mi][ni], ah0, ah1, ah2, ah3, bl[ni][0], bl[ni][1]);
                    mma_bf16(acc[mi][ni], al0, al1, al2, al3, bh[ni][0], bh[ni][1]);
                }
            }
        }
        __syncthreads();
    }

    // epilogue: acc[mi][ni] -> rows (r, r+8), cols (c, c+1)
    #pragma unroll
    for (int mi = 0; mi < 4; mi++) {
        int r = row0 + warp_m * 64 + mi * 16 + g;
        #pragma unroll
        for (int ni = 0; ni < 4; ni++) {
            int c = col0 + warp_n * 32 + ni * 8 + 2 * t;
            float bx = bias[c], by = bias[c + 1];
            float4 d = acc[mi][ni];
            float v0 = d.x + bx, v1 = d.y + by;
            float v2 = d.z + bx, v3 = d.w + by;
            if (epi == EPI_GELU) {
                v0 = 0.5f * v0 * (1.0f + erff(v0 * 0.70710678f));
                v1 = 0.5f * v1 * (1.0f + erff(v1 * 0.70710678f));
                v2 = 0.5f * v2 * (1.0f + erff(v2 * 0.70710678f));
                v3 = 0.5f * v3 * (1.0f + erff(v3 * 0.70710678f));
            }
            if (r < M) {
                if (epi == EPI_RES) {
                    v0 += resid[(size_t)r * Nn + c];
                    v1 += resid[(size_t)r * Nn + c + 1];
                }
                C[(size_t)r * Nn + c]     = v0;
                C[(size_t)r * Nn + c + 1] = v1;
            }
            if (r + 8 < M) {
                if (epi == EPI_RES) {
                    v2 += resid[(size_t)(r + 8) * Nn + c];
                    v3 += resid[(size_t)(r + 8) * Nn + c + 1];
                }
                C[(size_t)(r + 8) * Nn + c]     = v2;
                C[(size_t)(r + 8) * Nn + c + 1] = v3;
            }
        }
    }
}

// ---------------- Edge-softmax attention: warp per (node, head) --------------
__global__ void attn_kernel(float* __restrict__ out)
{
    int n    = blockIdx.x;
    int h    = threadIdx.x >> 5;
    int lane = threadIdx.x & 31;
    const float* qr = g_qkv + (size_t)n * (3 * CC) + h * HDIM;
    float q = qr[lane] * QK_SCALE;
    int s = g_rowptr[n];
    int e = g_rowptr[n + 1];
    float m = -INFINITY, l = 0.0f, acc = 0.0f;
    for (int i = s; i < e; i++) {
        int j = g_nbr[i];
        const float* base = g_qkv + (size_t)j * (3 * CC) + h * HDIM;
        float kk = base[CC + lane];       // k
        float vv = base[2 * CC + lane];   // v
        float d = q * kk;
        #pragma unroll
        for (int o = 16; o; o >>= 1) d += __shfl_xor_sync(0xffffffffu, d, o);
        float mn = fmaxf(m, d);
        float sc = __expf(m - mn);
        float p  = __expf(d - mn);
        l   = l * sc + p;
        acc = acc * sc + p * vv;
        m = mn;
    }
    float o = (l > 0.0f) ? acc / l : 0.0f;
    out[(size_t)n * CC + h * HDIM + lane] = o;
}

// ---------------- host launcher ---------------------------------------------
extern "C" void kernel_launch(void* const* d_in, const int* in_sizes, int n_in,
                              void* d_out, int out_size)
{
    const float* feats  = (const float*)d_in[0];
    const int*   ei     = (const int*)d_in[2];
    const float* ln1_g  = (const float*)d_in[3];
    const float* ln1_b  = (const float*)d_in[4];
    const float* qkv_w  = (const float*)d_in[5];
    const float* qkv_b  = (const float*)d_in[6];
    const float* proj_w = (const float*)d_in[7];
    const float* proj_b = (const float*)d_in[8];
    const float* ln2_g  = (const float*)d_in[9];
    const float* ln2_b  = (const float*)d_in[10];
    const float* fc1_w  = (const float*)d_in[11];
    const float* fc1_b  = (const float*)d_in[12];
    const float* fc2_w  = (const float*)d_in[13];
    const float* fc2_b  = (const float*)d_in[14];
    float* out = (float*)d_out;

    float *p_xn, *p_qkv, *p_att, *p_f2, *p_y, *p_h1;
    cudaGetSymbolAddress((void**)&p_xn,  g_xn);
    cudaGetSymbolAddress((void**)&p_qkv, g_qkv);
    cudaGetSymbolAddress((void**)&p_att, g_att);
    cudaGetSymbolAddress((void**)&p_f2,  g_f2);
    cudaGetSymbolAddress((void**)&p_y,   g_y);
    cudaGetSymbolAddress((void**)&p_h1,  g_h1);

    const int nscan = (NN + SCAN_B - 1) / SCAN_B;

    // CSR build
    zero_cnt_kernel<<<(NN + 255) / 256, 256>>>();
    count_kernel<<<(MM + 255) / 256, 256>>>(ei);
    scan1_kernel<<<nscan, SCAN_B>>>();
    scan2_kernel<<<1, 32>>>(nscan);
    scan3_kernel<<<nscan, SCAN_B>>>();
    scatter_kernel<<<(MM + 255) / 256, 256>>>(ei);

    // LN1
    ln_kernel<<<(NN + 7) / 8, 256>>>(feats, ln1_g, ln1_b, p_xn);

    // qkv = xn @ qkv_w^T + b   (M=NN, N=768, K=256)
    {
        dim3 grid(768 / BN, (NN + BM - 1) / BM);
        gemm_bf16s_kernel<<<grid, 256>>>(p_xn, qkv_w, qkv_b, nullptr, p_qkv,
                                         NN, 768, CC, EPI_NONE);
    }

    // attention
    attn_kernel<<<NN, 256>>>(p_att);

    // feats2 = feats + att @ proj_w^T + proj_b
    {
        dim3 grid(CC / BN, (NN + BM - 1) / BM);
        gemm_bf16s_kernel<<<grid, 256>>>(p_att, proj_w, proj_b, feats, p_f2,
                                         NN, CC, CC, EPI_RES);
    }

    // LN2
    ln_kernel<<<(NN + 7) / 8, 256>>>(p_f2, ln2_g, ln2_b, p_y);

    // h1 = gelu(y @ fc1_w^T + b)
    {
        dim3 grid(HIDN / BN, (NN + BM - 1) / BM);
        gemm_bf16s_kernel<<<grid, 256>>>(p_y, fc1_w, fc1_b, nullptr, p_h1,
                                         NN, HIDN, CC, EPI_GELU);
    }

    // out = feats2 + h1 @ fc2_w^T + b
    {
        dim3 grid(CC / BN, (NN + BM - 1) / BM);
        gemm_bf16s_kernel<<<grid, 256>>>(p_h1, fc2_w, fc2_b, p_f2, out,
                                         NN, CC, HIDN, EPI_RES);
    }
}

// round 5
// speedup vs baseline: 1.6480x; 1.1475x over previous
#include <cuda_runtime.h>
#include <cuda_bf16.h>
#include <math.h>

#define NN   50000
#define CC   256
#define HH   8
#define HDIM 32
#define MM   800000      // NN * 16 edges
#define HIDN 1024
#define QK_SCALE 0.17677669529663687f   // 32^-0.5
#define LN_EPS 1e-5f

// ---------------- scratch (static device globals; no allocation) -------------
__device__ __align__(16) float g_qkv[NN * 3 * CC];      // qkv projections (fp32)
__device__ __align__(16) float g_f2 [NN * CC];          // feats after proj+skip
// split activations (bf16 hi/lo)
__device__ __align__(16) __nv_bfloat16 g_xn_h[NN * CC],  g_xn_l[NN * CC];
__device__ __align__(16) __nv_bfloat16 g_at_h[NN * CC],  g_at_l[NN * CC];
__device__ __align__(16) __nv_bfloat16 g_y_h [NN * CC],  g_y_l [NN * CC];
__device__ __align__(16) __nv_bfloat16 g_h1_h[NN * HIDN], g_h1_l[NN * HIDN];
// split weights
__device__ __align__(16) __nv_bfloat16 g_wqkv_h[3*CC*CC], g_wqkv_l[3*CC*CC];
__device__ __align__(16) __nv_bfloat16 g_wprj_h[CC*CC],   g_wprj_l[CC*CC];
__device__ __align__(16) __nv_bfloat16 g_wfc1_h[HIDN*CC], g_wfc1_l[HIDN*CC];
__device__ __align__(16) __nv_bfloat16 g_wfc2_h[CC*HIDN], g_wfc2_l[CC*HIDN];
// CSR
__device__ int g_cnt[NN];
__device__ int g_rowptr[NN + 1];
__device__ int g_cursor[NN];
__device__ int g_bsums[128];
__device__ int g_nbr[MM];

// ---------------- fp32 -> bf16 hi/lo split -----------------------------------
__global__ void split_kernel(const float* __restrict__ w,
                             __nv_bfloat16* __restrict__ wh,
                             __nv_bfloat16* __restrict__ wl, int n)
{
    int i = blockIdx.x * blockDim.x + threadIdx.x;
    if (i < n) {
        float v = w[i];
        __nv_bfloat16 h = __float2bfloat16_rn(v);
        wh[i] = h;
        wl[i] = __float2bfloat16_rn(v - __bfloat162float(h));
    }
}

// ---------------- CSR build --------------------------------------------------
__global__ void zero_cnt_kernel() {
    int i = blockIdx.x * blockDim.x + threadIdx.x;
    if (i < NN) g_cnt[i] = 0;
}

__global__ void count_kernel(const int* __restrict__ ei) {
    int e = blockIdx.x * blockDim.x + threadIdx.x;
    if (e < MM) atomicAdd(&g_cnt[ei[e]], 1);
}

#define SCAN_B 512
__global__ void scan1_kernel() {
    __shared__ int sh[SCAN_B];
    int tid = threadIdx.x;
    int i = blockIdx.x * SCAN_B + tid;
    int v = (i < NN) ? g_cnt[i] : 0;
    sh[tid] = v;
    __syncthreads();
    for (int off = 1; off < SCAN_B; off <<= 1) {
        int t = (tid >= off) ? sh[tid - off] : 0;
        __syncthreads();
        sh[tid] += t;
        __syncthreads();
    }
    if (i < NN) g_rowptr[i] = sh[tid] - v;
    if (tid == SCAN_B - 1) g_bsums[blockIdx.x] = sh[tid];
}

__global__ void scan2_kernel(int nb) {
    if (threadIdx.x == 0 && blockIdx.x == 0) {
        int a = 0;
        for (int i = 0; i < nb; i++) { int t = g_bsums[i]; g_bsums[i] = a; a += t; }
    }
}

__global__ void scan3_kernel() {
    int i = blockIdx.x * SCAN_B + threadIdx.x;
    if (i < NN) {
        int v = g_rowptr[i] + g_bsums[blockIdx.x];
        g_rowptr[i] = v;
        g_cursor[i] = v;
    }
    if (i == 0) g_rowptr[NN] = MM;
}

__global__ void scatter_kernel(const int* __restrict__ ei) {
    int e = blockIdx.x * blockDim.x + threadIdx.x;
    if (e < MM) {
        int n = ei[e];
        int p = atomicAdd(&g_cursor[n], 1);
        g_nbr[p] = ei[MM + e];
    }
}

// ---------------- LayerNorm -> split bf16 output (one warp per row) ----------
__global__ void ln_split_kernel(const float* __restrict__ x, const float* __restrict__ g,
                                const float* __restrict__ b,
                                __nv_bfloat16* __restrict__ yh,
                                __nv_bfloat16* __restrict__ yl)
{
    int row  = blockIdx.x * 8 + (threadIdx.x >> 5);
    int lane = threadIdx.x & 31;
    if (row >= NN) return;
    const float4* xr = (const float4*)(x + (size_t)row * CC);
    float4 a = xr[lane];
    float4 c = xr[lane + 32];
    float s = a.x + a.y + a.z + a.w + c.x + c.y + c.z + c.w;
    float q = a.x*a.x + a.y*a.y + a.z*a.z + a.w*a.w
            + c.x*c.x + c.y*c.y + c.z*c.z + c.w*c.w;
    #pragma unroll
    for (int o = 16; o; o >>= 1) {
        s += __shfl_xor_sync(0xffffffffu, s, o);
        q += __shfl_xor_sync(0xffffffffu, q, o);
    }
    float mean = s * (1.0f / CC);
    float var  = q * (1.0f / CC) - mean * mean;
    float rstd = rsqrtf(var + LN_EPS);
    const float4* gv = (const float4*)g;
    const float4* bv = (const float4*)b;
    float4 g1 = gv[lane], g2 = gv[lane + 32];
    float4 b1 = bv[lane], b2 = bv[lane + 32];
    float o1[4], o2[4];
    o1[0] = (a.x - mean) * rstd * g1.x + b1.x;
    o1[1] = (a.y - mean) * rstd * g1.y + b1.y;
    o1[2] = (a.z - mean) * rstd * g1.z + b1.z;
    o1[3] = (a.w - mean) * rstd * g1.w + b1.w;
    o2[0] = (c.x - mean) * rstd * g2.x + b2.x;
    o2[1] = (c.y - mean) * rstd * g2.y + b2.y;
    o2[2] = (c.z - mean) * rstd * g2.z + b2.z;
    o2[3] = (c.w - mean) * rstd * g2.w + b2.w;

    __nv_bfloat16 h1[4], l1[4], h2[4], l2[4];
    #pragma unroll
    for (int i = 0; i < 4; i++) {
        h1[i] = __float2bfloat16_rn(o1[i]);
        l1[i] = __float2bfloat16_rn(o1[i] - __bfloat162float(h1[i]));
        h2[i] = __float2bfloat16_rn(o2[i]);
        l2[i] = __float2bfloat16_rn(o2[i] - __bfloat162float(h2[i]));
    }
    size_t base = (size_t)row * CC;
    *(uint2*)&yh[base + lane * 4]       = *(uint2*)h1;
    *(uint2*)&yh[base + 128 + lane * 4] = *(uint2*)h2;
    *(uint2*)&yl[base + lane * 4]       = *(uint2*)l1;
    *(uint2*)&yl[base + 128 + lane * 4] = *(uint2*)l2;
}

// ---------------- bf16-split tensor-core GEMM, cp.async double-buffered ------
// C[M,N] = A[M,K] @ B[N,K]^T + bias (+epilogue).  A,B pre-split hi/lo bf16.
#define BM 128
#define BN 128
#define BK 32
#define BKP 40               // padded row (bf16 elems); 80B row stride, 16B-aligned
#define TILE (BM * BKP)      // elems per (array, stage)

#define EPI_NONE 0
#define EPI_GELU 1           // gelu, write split bf16
#define EPI_RES  2           // residual add, write fp32

__device__ __forceinline__ void cp16(void* dst, const void* src) {
    unsigned d = (unsigned)__cvta_generic_to_shared(dst);
    asm volatile("cp.async.ca.shared.global [%0],[%1],16;\n" :: "r"(d), "l"(src));
}

__device__ __forceinline__ void mma_bf16(float4& d,
    unsigned a0, unsigned a1, unsigned a2, unsigned a3,
    unsigned b0, unsigned b1)
{
    asm volatile(
        "mma.sync.aligned.m16n8k16.row.col.f32.bf16.bf16.f32 "
        "{%0,%1,%2,%3},{%4,%5,%6,%7},{%8,%9},{%0,%1,%2,%3};"
        : "+f"(d.x), "+f"(d.y), "+f"(d.z), "+f"(d.w)
        : "r"(a0), "r"(a1), "r"(a2), "r"(a3), "r"(b0), "r"(b1));
}

__global__ __launch_bounds__(256, 2)
void gemm_sp_kernel(const __nv_bfloat16* __restrict__ Ah, const __nv_bfloat16* __restrict__ Al,
                    const __nv_bfloat16* __restrict__ Bh, const __nv_bfloat16* __restrict__ Bl,
                    const float* __restrict__ bias, const float* __restrict__ resid,
                    float* __restrict__ Cf,
                    __nv_bfloat16* __restrict__ Ch, __nv_bfloat16* __restrict__ Cl,
                    int M, int Nn, int Kk, int epi)
{
    extern __shared__ __nv_bfloat16 smem[];
    // stage st: [Ah | Al | Bh | Bl], each TILE elems
    const int tid  = threadIdx.x;
    const int row0 = blockIdx.y * BM;
    const int col0 = blockIdx.x * BN;
    const int warp   = tid >> 5;
    const int lane   = tid & 31;
    const int warp_m = warp >> 2;       // 0..1
    const int warp_n = warp & 3;        // 0..3
    const int g = lane >> 2;            // 0..7
    const int t = lane & 3;             // 0..3

    // staging map: 512 16B-chunks per (array); thread does 2 chunks per array
    const int ch0 = tid * 2;            // chunk ids ch0, ch0+1
    const int nKiter = Kk / BK;

    float4 acc[4][4];
    #pragma unroll
    for (int i = 0; i < 4; i++)
        #pragma unroll
        for (int j = 0; j < 4; j++) acc[i][j] = make_float4(0.f, 0.f, 0.f, 0.f);

    auto stage = [&](int st, int k0) {
        __nv_bfloat16* sAh = smem + (size_t)st * 4 * TILE;
        __nv_bfloat16* sAl = sAh + TILE;
        __nv_bfloat16* sBh = sAl + TILE;
        __nv_bfloat16* sBl = sBh + TILE;
        #pragma unroll
        for (int q = 0; q < 2; q++) {
            int idx = ch0 + q;          // 0..511
            int r    = idx >> 2;        // 0..127
            int c16  = idx & 3;         // 16B chunk within row
            int ar = row0 + r; if (ar >= M) ar = M - 1;   // clamp; epilogue guards
            size_t aoff = (size_t)ar * Kk + k0 + c16 * 8;
            int br = col0 + r;                            // N multiple of 128
            size_t boff = (size_t)br * Kk + k0 + c16 * 8;
            int d = r * BKP + c16 * 8;
            cp16(sAh + d, Ah + aoff);
            cp16(sAl + d, Al + aoff);
            cp16(sBh + d, Bh + boff);
            cp16(sBl + d, Bl + boff);
        }
    };

    stage(0, 0);
    asm volatile("cp.async.commit_group;\n");

    for (int it = 0; it < nKiter; it++) {
        if (it + 1 < nKiter) {
            stage((it + 1) & 1, (it + 1) * BK);
            asm volatile("cp.async.commit_group;\n");
            asm volatile("cp.async.wait_group 1;\n");
        } else {
            asm volatile("cp.async.wait_group 0;\n");
        }
        __syncthreads();

        const int st = it & 1;
        const __nv_bfloat16* sAh = smem + (size_t)st * 4 * TILE;
        const __nv_bfloat16* sAl = sAh + TILE;
        const __nv_bfloat16* sBh = sAl + TILE;
        const __nv_bfloat16* sBl = sBh + TILE;

        #pragma unroll
        for (int s = 0; s < 2; s++) {   // two k16 steps
            const int c = s * 16 + 2 * t;
            unsigned bh[4][2], bl[4][2];
            #pragma unroll
            for (int ni = 0; ni < 4; ni++) {
                int n = warp_n * 32 + ni * 8 + g;
                bh[ni][0] = *(const unsigned*)&sBh[n * BKP + c];
                bh[ni][1] = *(const unsigned*)&sBh[n * BKP + c + 8];
                bl[ni][0] = *(const unsigned*)&sBl[n * BKP + c];
                bl[ni][1] = *(const unsigned*)&sBl[n * BKP + c + 8];
            }
            #pragma unroll
            for (int mi = 0; mi < 4; mi++) {
                int r = warp_m * 64 + mi * 16 + g;
                unsigned ah0 = *(const unsigned*)&sAh[(r    ) * BKP + c];
                unsigned ah1 = *(const unsigned*)&sAh[(r + 8) * BKP + c];
                unsigned ah2 = *(const unsigned*)&sAh[(r    ) * BKP + c + 8];
                unsigned ah3 = *(const unsigned*)&sAh[(r + 8) * BKP + c + 8];
                unsigned al0 = *(const unsigned*)&sAl[(r    ) * BKP + c];
                unsigned al1 = *(const unsigned*)&sAl[(r + 8) * BKP + c];
                unsigned al2 = *(const unsigned*)&sAl[(r    ) * BKP + c + 8];
                unsigned al3 = *(const unsigned*)&sAl[(r + 8) * BKP + c + 8];
                #pragma unroll
                for (int ni = 0; ni < 4; ni++) {
                    mma_bf16(acc[mi][ni], ah0, ah1, ah2, ah3, bh[ni][0], bh[ni][1]);
                    mma_bf16(acc[mi][ni], ah0, ah1, ah2, ah3, bl[ni][0], bl[ni][1]);
                    mma_bf16(acc[mi][ni], al0, al1, al2, al3, bh[ni][0], bh[ni][1]);
                }
            }
        }
        __syncthreads();
    }

    // epilogue: acc[mi][ni] -> rows (r, r+8), cols (c, c+1)
    #pragma unroll
    for (int mi = 0; mi < 4; mi++) {
        int r = row0 + warp_m * 64 + mi * 16 + g;
        #pragma unroll
        for (int ni = 0; ni < 4; ni++) {
            int c = col0 + warp_n * 32 + ni * 8 + 2 * t;
            float bx = bias[c], by = bias[c + 1];
            float4 d = acc[mi][ni];
            float v0 = d.x + bx, v1 = d.y + by;
            float v2 = d.z + bx, v3 = d.w + by;
            if (epi == EPI_GELU) {
                v0 = 0.5f * v0 * (1.0f + erff(v0 * 0.70710678f));
                v1 = 0.5f * v1 * (1.0f + erff(v1 * 0.70710678f));
                v2 = 0.5f * v2 * (1.0f + erff(v2 * 0.70710678f));
                v3 = 0.5f * v3 * (1.0f + erff(v3 * 0.70710678f));
                if (r < M) {
                    size_t o = (size_t)r * Nn + c;
                    __nv_bfloat16 h0 = __float2bfloat16_rn(v0);
                    __nv_bfloat16 h1 = __float2bfloat16_rn(v1);
                    Ch[o] = h0; Ch[o + 1] = h1;
                    Cl[o]     = __float2bfloat16_rn(v0 - __bfloat162float(h0));
                    Cl[o + 1] = __float2bfloat16_rn(v1 - __bfloat162float(h1));
                }
                if (r + 8 < M) {
                    size_t o = (size_t)(r + 8) * Nn + c;
                    __nv_bfloat16 h2 = __float2bfloat16_rn(v2);
                    __nv_bfloat16 h3 = __float2bfloat16_rn(v3);
                    Ch[o] = h2; Ch[o + 1] = h3;
                    Cl[o]     = __float2bfloat16_rn(v2 - __bfloat162float(h2));
                    Cl[o + 1] = __float2bfloat16_rn(v3 - __bfloat162float(h3));
                }
            } else {
                if (r < M) {
                    size_t o = (size_t)r * Nn + c;
                    if (epi == EPI_RES) { v0 += resid[o]; v1 += resid[o + 1]; }
                    Cf[o] = v0; Cf[o + 1] = v1;
                }
                if (r + 8 < M) {
                    size_t o = (size_t)(r + 8) * Nn + c;
                    if (epi == EPI_RES) { v2 += resid[o]; v3 += resid[o + 1]; }
                    Cf[o] = v2; Cf[o + 1] = v3;
                }
            }
        }
    }
}

// ---------------- Edge-softmax attention: warp per (node, head) --------------
__global__ void attn_kernel(__nv_bfloat16* __restrict__ oh, __nv_bfloat16* __restrict__ ol)
{
    int n    = blockIdx.x;
    int h    = threadIdx.x >> 5;
    int lane = threadIdx.x & 31;
    const float* qr = g_qkv + (size_t)n * (3 * CC) + h * HDIM;
    float q = qr[lane] * QK_SCALE;
    int s = g_rowptr[n];
    int e = g_rowptr[n + 1];
    float m = -INFINITY, l = 0.0f, acc = 0.0f;
    int j = (s < e) ? g_nbr[s] : 0;
    for (int i = s; i < e; i++) {
        const float* base = g_qkv + (size_t)j * (3 * CC) + h * HDIM;
        float kk = base[CC + lane];
        float vv = base[2 * CC + lane];
        int jn = (i + 1 < e) ? g_nbr[i + 1] : 0;   // prefetch next index
        float d = q * kk;
        #pragma unroll
        for (int o = 16; o; o >>= 1) d += __shfl_xor_sync(0xffffffffu, d, o);
        float mn = fmaxf(m, d);
        float sc = __expf(m - mn);
        float p  = __expf(d - mn);
        l   = l * sc + p;
        acc = acc * sc + p * vv;
        m = mn;
        j = jn;
    }
    float o = (l > 0.0f) ? acc / l : 0.0f;
    size_t idx = (size_t)n * CC + h * HDIM + lane;
    __nv_bfloat16 hh = __float2bfloat16_rn(o);
    oh[idx] = hh;
    ol[idx] = __float2bfloat16_rn(o - __bfloat162float(hh));
}

// ---------------- host launcher ---------------------------------------------
extern "C" void kernel_launch(void* const* d_in, const int* in_sizes, int n_in,
                              void* d_out, int out_size)
{
    const float* feats  = (const float*)d_in[0];
    const int*   ei     = (const int*)d_in[2];
    const float* ln1_g  = (const float*)d_in[3];
    const float* ln1_b  = (const float*)d_in[4];
    const float* qkv_w  = (const float*)d_in[5];
    const float* qkv_b  = (const float*)d_in[6];
    const float* proj_w = (const float*)d_in[7];
    const float* proj_b = (const float*)d_in[8];
    const float* ln2_g  = (const float*)d_in[9];
    const float* ln2_b  = (const float*)d_in[10];
    const float* fc1_w  = (const float*)d_in[11];
    const float* fc1_b  = (const float*)d_in[12];
    const float* fc2_w  = (const float*)d_in[13];
    const float* fc2_b  = (const float*)d_in[14];
    float* out = (float*)d_out;

    float *p_qkv, *p_f2;
    cudaGetSymbolAddress((void**)&p_qkv, g_qkv);
    cudaGetSymbolAddress((void**)&p_f2,  g_f2);
    __nv_bfloat16 *p_xn_h, *p_xn_l, *p_at_h, *p_at_l, *p_y_h, *p_y_l, *p_h1_h, *p_h1_l;
    cudaGetSymbolAddress((void**)&p_xn_h, g_xn_h);
    cudaGetSymbolAddress((void**)&p_xn_l, g_xn_l);
    cudaGetSymbolAddress((void**)&p_at_h, g_at_h);
    cudaGetSymbolAddress((void**)&p_at_l, g_at_l);
    cudaGetSymbolAddress((void**)&p_y_h,  g_y_h);
    cudaGetSymbolAddress((void**)&p_y_l,  g_y_l);
    cudaGetSymbolAddress((void**)&p_h1_h, g_h1_h);
    cudaGetSymbolAddress((void**)&p_h1_l, g_h1_l);
    __nv_bfloat16 *p_wqkv_h, *p_wqkv_l, *p_wprj_h, *p_wprj_l,
                  *p_wfc1_h, *p_wfc1_l, *p_wfc2_h, *p_wfc2_l;
    cudaGetSymbolAddress((void**)&p_wqkv_h, g_wqkv_h);
    cudaGetSymbolAddress((void**)&p_wqkv_l, g_wqkv_l);
    cudaGetSymbolAddress((void**)&p_wprj_h, g_wprj_h);
    cudaGetSymbolAddress((void**)&p_wprj_l, g_wprj_l);
    cudaGetSymbolAddress((void**)&p_wfc1_h, g_wfc1_h);
    cudaGetSymbolAddress((void**)&p_wfc1_l, g_wfc1_l);
    cudaGetSymbolAddress((void**)&p_wfc2_h, g_wfc2_h);
    cudaGetSymbolAddress((void**)&p_wfc2_l, g_wfc2_l);

    const int SMEM_BYTES = 2 * 4 * TILE * (int)sizeof(__nv_bfloat16);   // 81920
    static int smem_set = 0;
    if (!smem_set) {
        cudaFuncSetAttribute(gemm_sp_kernel,
                             cudaFuncAttributeMaxDynamicSharedMemorySize, SMEM_BYTES);
        smem_set = 1;
    }

    const int nscan = (NN + SCAN_B - 1) / SCAN_B;

    // weight splits (cheap; overlapped with nothing but tiny)
    split_kernel<<<(3*CC*CC + 255)/256, 256>>>(qkv_w, p_wqkv_h, p_wqkv_l, 3*CC*CC);
    split_kernel<<<(CC*CC   + 255)/256, 256>>>(proj_w, p_wprj_h, p_wprj_l, CC*CC);
    split_kernel<<<(HIDN*CC + 255)/256, 256>>>(fc1_w, p_wfc1_h, p_wfc1_l, HIDN*CC);
    split_kernel<<<(CC*HIDN + 255)/256, 256>>>(fc2_w, p_wfc2_h, p_wfc2_l, CC*HIDN);

    // CSR build
    zero_cnt_kernel<<<(NN + 255) / 256, 256>>>();
    count_kernel<<<(MM + 255) / 256, 256>>>(ei);
    scan1_kernel<<<nscan, SCAN_B>>>();
    scan2_kernel<<<1, 32>>>(nscan);
    scan3_kernel<<<nscan, SCAN_B>>>();
    scatter_kernel<<<(MM + 255) / 256, 256>>>(ei);

    // LN1 -> split
    ln_split_kernel<<<(NN + 7) / 8, 256>>>(feats, ln1_g, ln1_b, p_xn_h, p_xn_l);

    // qkv = xn @ qkv_w^T + b   (fp32 out)
    {
        dim3 grid(768 / BN, (NN + BM - 1) / BM);
        gemm_sp_kernel<<<grid, 256, SMEM_BYTES>>>(p_xn_h, p_xn_l, p_wqkv_h, p_wqkv_l,
                                                  qkv_b, nullptr, p_qkv, nullptr, nullptr,
                                                  NN, 768, CC, EPI_NONE);
    }

    // attention -> split att
    attn_kernel<<<NN, 256>>>(p_at_h, p_at_l);

    // f2 = feats + att @ proj_w^T + b   (fp32 out)
    {
        dim3 grid(CC / BN, (NN + BM - 1) / BM);
        gemm_sp_kernel<<<grid, 256, SMEM_BYTES>>>(p_at_h, p_at_l, p_wprj_h, p_wprj_l,
                                                  proj_b, feats, p_f2, nullptr, nullptr,
                                                  NN, CC, CC, EPI_RES);
    }

    // LN2 -> split
    ln_split_kernel<<<(NN + 7) / 8, 256>>>(p_f2, ln2_g, ln2_b, p_y_h, p_y_l);

    // h1 = gelu(y @ fc1_w^T + b)  (split out)
    {
        dim3 grid(HIDN / BN, (NN + BM - 1) / BM);
        gemm_sp_kernel<<<grid, 256, SMEM_BYTES>>>(p_y_h, p_y_l, p_wfc1_h, p_wfc1_l,
                                                  fc1_b, nullptr, nullptr, p_h1_h, p_h1_l,
                                                  NN, HIDN, CC, EPI_GELU);
    }

    // out = f2 + h1 @ fc2_w^T + b  (fp32 out)
    {
        dim3 grid(CC / BN, (NN + BM - 1) / BM);
        gemm_sp_kernel<<<grid, 256, SMEM_BYTES>>>(p_h1_h, p_h1_l, p_wfc2_h, p_wfc2_l,
                                                  fc2_b, p_f2, out, nullptr, nullptr,
                                                  NN, CC, HIDN, EPI_RES);
    }
}

// round 7
// speedup vs baseline: 1.8519x; 1.1237x over previous
#include <cuda_runtime.h>
#include <cuda_bf16.h>
#include <cstdint>
#include <math.h>

#define NN   50000
#define CC   256
#define HH   8
#define HDIM 32
#define MM   800000
#define HIDN 1024
#define QK_SCALE 0.17677669529663687f
#define LN_EPS 1e-5f

// ---------------- scratch (static device globals; no allocation) -------------
__device__ __align__(16) float g_qkv[NN * 3 * CC];
__device__ __align__(16) float g_f2 [NN * CC];
__device__ __align__(16) __nv_bfloat16 g_xn_h[NN * CC],  g_xn_l[NN * CC];
__device__ __align__(16) __nv_bfloat16 g_at_h[NN * CC],  g_at_l[NN * CC];
__device__ __align__(16) __nv_bfloat16 g_y_h [NN * CC],  g_y_l [NN * CC];
__device__ __align__(16) __nv_bfloat16 g_h1_h[NN * HIDN], g_h1_l[NN * HIDN];
__device__ __align__(16) __nv_bfloat16 g_wqkv_h[3*CC*CC], g_wqkv_l[3*CC*CC];
__device__ __align__(16) __nv_bfloat16 g_wprj_h[CC*CC],   g_wprj_l[CC*CC];
__device__ __align__(16) __nv_bfloat16 g_wfc1_h[HIDN*CC], g_wfc1_l[HIDN*CC];
__device__ __align__(16) __nv_bfloat16 g_wfc2_h[CC*HIDN], g_wfc2_l[CC*HIDN];
__device__ int g_cnt[NN];
__device__ int g_rowptr[NN + 1];
__device__ int g_cursor[NN];
__device__ int g_bsums[128];
__device__ int g_nbr[MM];

// ---------------- fp32 -> bf16 hi/lo split -----------------------------------
__global__ void split_kernel(const float* __restrict__ w,
                             __nv_bfloat16* __restrict__ wh,
                             __nv_bfloat16* __restrict__ wl, int n)
{
    int i = blockIdx.x * blockDim.x + threadIdx.x;
    if (i < n) {
        float v = w[i];
        __nv_bfloat16 h = __float2bfloat16_rn(v);
        wh[i] = h;
        wl[i] = __float2bfloat16_rn(v - __bfloat162float(h));
    }
}

// ---------------- CSR build --------------------------------------------------
__global__ void zero_cnt_kernel() {
    int i = blockIdx.x * blockDim.x + threadIdx.x;
    if (i < NN) g_cnt[i] = 0;
}

__global__ void count_kernel(const int* __restrict__ ei) {
    int e = blockIdx.x * blockDim.x + threadIdx.x;
    if (e < MM) atomicAdd(&g_cnt[ei[e]], 1);
}

#define SCAN_B 512
__global__ void scan1_kernel() {
    __shared__ int sh[SCAN_B];
    int tid = threadIdx.x;
    int i = blockIdx.x * SCAN_B + tid;
    int v = (i < NN) ? g_cnt[i] : 0;
    sh[tid] = v;
    __syncthreads();
    for (int off = 1; off < SCAN_B; off <<= 1) {
        int t = (tid >= off) ? sh[tid - off] : 0;
        __syncthreads();
        sh[tid] += t;
        __syncthreads();
    }
    if (i < NN) g_rowptr[i] = sh[tid] - v;
    if (tid == SCAN_B - 1) g_bsums[blockIdx.x] = sh[tid];
}

__global__ void scan2_kernel(int nb) {
    if (threadIdx.x == 0 && blockIdx.x == 0) {
        int a = 0;
        for (int i = 0; i < nb; i++) { int t = g_bsums[i]; g_bsums[i] = a; a += t; }
    }
}

__global__ void scan3_kernel() {
    int i = blockIdx.x * SCAN_B + threadIdx.x;
    if (i < NN) {
        int v = g_rowptr[i] + g_bsums[blockIdx.x];
        g_rowptr[i] = v;
        g_cursor[i] = v;
    }
    if (i == 0) g_rowptr[NN] = MM;
}

__global__ void scatter_kernel(const int* __restrict__ ei) {
    int e = blockIdx.x * blockDim.x + threadIdx.x;
    if (e < MM) {
        int n = ei[e];
        int p = atomicAdd(&g_cursor[n], 1);
        g_nbr[p] = ei[MM + e];
    }
}

// ---------------- LayerNorm -> split bf16 output -----------------------------
__global__ void ln_split_kernel(const float* __restrict__ x, const float* __restrict__ g,
                                const float* __restrict__ b,
                                __nv_bfloat16* __restrict__ yh,
                                __nv_bfloat16* __restrict__ yl)
{
    int row  = blockIdx.x * 8 + (threadIdx.x >> 5);
    int lane = threadIdx.x & 31;
    if (row >= NN) return;
    const float4* xr = (const float4*)(x + (size_t)row * CC);
    float4 a = xr[lane];
    float4 c = xr[lane + 32];
    float s = a.x + a.y + a.z + a.w + c.x + c.y + c.z + c.w;
    float q = a.x*a.x + a.y*a.y + a.z*a.z + a.w*a.w
            + c.x*c.x + c.y*c.y + c.z*c.z + c.w*c.w;
    #pragma unroll
    for (int o = 16; o; o >>= 1) {
        s += __shfl_xor_sync(0xffffffffu, s, o);
        q += __shfl_xor_sync(0xffffffffu, q, o);
    }
    float mean = s * (1.0f / CC);
    float var  = q * (1.0f / CC) - mean * mean;
    float rstd = rsqrtf(var + LN_EPS);
    const float4* gv = (const float4*)g;
    const float4* bv = (const float4*)b;
    float4 g1 = gv[lane], g2 = gv[lane + 32];
    float4 b1 = bv[lane], b2 = bv[lane + 32];
    float o1[4], o2[4];
    o1[0] = (a.x - mean) * rstd * g1.x + b1.x;
    o1[1] = (a.y - mean) * rstd * g1.y + b1.y;
    o1[2] = (a.z - mean) * rstd * g1.z + b1.z;
    o1[3] = (a.w - mean) * rstd * g1.w + b1.w;
    o2[0] = (c.x - mean) * rstd * g2.x + b2.x;
    o2[1] = (c.y - mean) * rstd * g2.y + b2.y;
    o2[2] = (c.z - mean) * rstd * g2.z + b2.z;
    o2[3] = (c.w - mean) * rstd * g2.w + b2.w;

    __nv_bfloat16 h1[4], l1[4], h2[4], l2[4];
    #pragma unroll
    for (int i = 0; i < 4; i++) {
        h1[i] = __float2bfloat16_rn(o1[i]);
        l1[i] = __float2bfloat16_rn(o1[i] - __bfloat162float(h1[i]));
        h2[i] = __float2bfloat16_rn(o2[i]);
        l2[i] = __float2bfloat16_rn(o2[i] - __bfloat162float(h2[i]));
    }
    size_t base = (size_t)row * CC;
    *(uint2*)&yh[base + lane * 4]       = *(uint2*)h1;
    *(uint2*)&yh[base + 128 + lane * 4] = *(uint2*)h2;
    *(uint2*)&yl[base + lane * 4]       = *(uint2*)l1;
    *(uint2*)&yl[base + 128 + lane * 4] = *(uint2*)l2;
}

// ---------------- bf16-split tensor-core GEMM, ldmatrix + cp.async -----------
// C[M,N] = A[M,K] @ B[N,K]^T + bias (+epilogue).  A,B pre-split hi/lo bf16.
#define BM 128
#define BN 128
#define BK 32
#define BKP 40                    // padded row (bf16); 80B stride, 16B aligned
#define TILE (BM * BKP)           // elems per array per stage
#define ARRB (TILE * 2)           // bytes per array (10240)
#define STAGEB (4 * ARRB)         // bytes per stage  (40960)

#define EPI_NONE 0
#define EPI_GELU 1
#define EPI_RES  2

__device__ __forceinline__ uint32_t smem_u32(const void* p) {
    uint32_t a;
    asm("{ .reg .u64 t; cvta.to.shared.u64 t, %1; cvt.u32.u64 %0, t; }" : "=r"(a) : "l"(p));
    return a;
}

__device__ __forceinline__ void cp16(uint32_t dst, const void* src) {
    asm volatile("cp.async.cg.shared.global [%0],[%1],16;\n" :: "r"(dst), "l"(src));
}
#define CP_COMMIT() asm volatile("cp.async.commit_group;\n")
#define CP_WAIT(n)  asm volatile("cp.async.wait_group %0;\n" :: "n"(n))

__device__ __forceinline__ void ldsm4(unsigned& r0, unsigned& r1, unsigned& r2,
                                      unsigned& r3, uint32_t addr)
{
    asm volatile("ldmatrix.sync.aligned.m8n8.x4.shared.b16 {%0,%1,%2,%3}, [%4];"
                 : "=r"(r0), "=r"(r1), "=r"(r2), "=r"(r3) : "r"(addr));
}

__device__ __forceinline__ void mma_bf16(float4& d,
    unsigned a0, unsigned a1, unsigned a2, unsigned a3,
    unsigned b0, unsigned b1)
{
    asm volatile(
        "mma.sync.aligned.m16n8k16.row.col.f32.bf16.bf16.f32 "
        "{%0,%1,%2,%3},{%4,%5,%6,%7},{%8,%9},{%0,%1,%2,%3};"
        : "+f"(d.x), "+f"(d.y), "+f"(d.z), "+f"(d.w)
        : "r"(a0), "r"(a1), "r"(a2), "r"(a3), "r"(b0), "r"(b1));
}

__global__ __launch_bounds__(256, 2)
void gemm_sp_kernel(const __nv_bfloat16* __restrict__ Ah, const __nv_bfloat16* __restrict__ Al,
                    const __nv_bfloat16* __restrict__ Bh, const __nv_bfloat16* __restrict__ Bl,
                    const float* __restrict__ bias, const float* __restrict__ resid,
                    float* __restrict__ Cf,
                    __nv_bfloat16* __restrict__ Ch, __nv_bfloat16* __restrict__ Cl,
                    int M, int Nn, int Kk, int epi)
{
    extern __shared__ __nv_bfloat16 smem[];
    const uint32_t sb0 = smem_u32(smem);

    const int tid  = threadIdx.x;
    const int row0 = blockIdx.y * BM;
    const int col0 = blockIdx.x * BN;
    const int warp   = tid >> 5;
    const int lane   = tid & 31;
    const int warp_m = warp >> 2;       // 0..1
    const int warp_n = warp & 3;        // 0..3
    const int g = lane >> 2;            // 0..7
    const int t = lane & 3;             // 0..3

    // ldmatrix per-lane byte offsets (within an array)
    const int rowA = warp_m * 64 + (lane & 15);
    const int colA = 8 * (lane >> 4);
    const uint32_t offA = (uint32_t)(rowA * BKP + colA) * 2;
    const int rowB = warp_n * 32 + (lane & 7) + 8 * ((lane >> 4) & 1);
    const int colB = 8 * ((lane >> 3) & 1);
    const uint32_t offB = (uint32_t)(rowB * BKP + colB) * 2;

    // staging: 512 16B-chunks per array-set; thread handles chunks tid*2, tid*2+1
    const int ch0 = tid * 2;
    const int nKiter = Kk / BK;

    float4 acc[4][4];
    #pragma unroll
    for (int i = 0; i < 4; i++)
        #pragma unroll
        for (int j = 0; j < 4; j++) acc[i][j] = make_float4(0.f, 0.f, 0.f, 0.f);

    auto stage = [&](int st, int k0) {
        uint32_t base = sb0 + st * STAGEB;
        #pragma unroll
        for (int q = 0; q < 2; q++) {
            int idx = ch0 + q;          // 0..511
            int r    = idx >> 2;        // 0..127
            int c16  = idx & 3;
            int ar = row0 + r; if (ar >= M) ar = M - 1;
            size_t aoff = (size_t)ar * Kk + k0 + c16 * 8;
            int br = col0 + r;
            size_t boff = (size_t)br * Kk + k0 + c16 * 8;
            uint32_t d = (uint32_t)(r * BKP + c16 * 8) * 2;
            cp16(base + 0 * ARRB + d, Ah + aoff);
            cp16(base + 1 * ARRB + d, Al + aoff);
            cp16(base + 2 * ARRB + d, Bh + boff);
            cp16(base + 3 * ARRB + d, Bl + boff);
        }
    };

    stage(0, 0);
    CP_COMMIT();

    for (int it = 0; it < nKiter; it++) {
        if (it + 1 < nKiter) {
            stage((it + 1) & 1, (it + 1) * BK);
            CP_COMMIT();
            CP_WAIT(1);
        } else {
            CP_WAIT(0);
        }
        __syncthreads();

        const uint32_t base = sb0 + (it & 1) * STAGEB;
        const uint32_t aAh = base + offA;
        const uint32_t aAl = base + ARRB + offA;
        const uint32_t aBh = base + 2 * ARRB + offB;
        const uint32_t aBl = base + 3 * ARRB + offB;

        #pragma unroll
        for (int s = 0; s < 2; s++) {   // two k16 steps, +32B each
            unsigned bh[4][2], bl[4][2];
            ldsm4(bh[0][0], bh[0][1], bh[1][0], bh[1][1], aBh + s * 32);
            ldsm4(bh[2][0], bh[2][1], bh[3][0], bh[3][1], aBh + 16 * BKP * 2 + s * 32);
            ldsm4(bl[0][0], bl[0][1], bl[1][0], bl[1][1], aBl + s * 32);
            ldsm4(bl[2][0], bl[2][1], bl[3][0], bl[3][1], aBl + 16 * BKP * 2 + s * 32);
            #pragma unroll
            for (int mi = 0; mi < 4; mi++) {
                unsigned ah0, ah1, ah2, ah3, al0, al1, al2, al3;
                ldsm4(ah0, ah1, ah2, ah3, aAh + mi * (16 * BKP * 2) + s * 32);
                ldsm4(al0, al1, al2, al3, aAl + mi * (16 * BKP * 2) + s * 32);
                #pragma unroll
                for (int ni = 0; ni < 4; ni++) {
                    mma_bf16(acc[mi][ni], ah0, ah1, ah2, ah3, bh[ni][0], bh[ni][1]);
                    mma_bf16(acc[mi][ni], ah0, ah1, ah2, ah3, bl[ni][0], bl[ni][1]);
                    mma_bf16(acc[mi][ni], al0, al1, al2, al3, bh[ni][0], bh[ni][1]);
                }
            }
        }
        __syncthreads();
    }

    // epilogue: acc[mi][ni] -> rows (r, r+8), cols (c, c+1)
    #pragma unroll
    for (int mi = 0; mi < 4; mi++) {
        int r = row0 + warp_m * 64 + mi * 16 + g;
        #pragma unroll
        for (int ni = 0; ni < 4; ni++) {
            int c = col0 + warp_n * 32 + ni * 8 + 2 * t;
            float bx = bias[c], by = bias[c + 1];
            float4 d = acc[mi][ni];
            float v0 = d.x + bx, v1 = d.y + by;
            float v2 = d.z + bx, v3 = d.w + by;
            if (epi == EPI_GELU) {
                v0 = 0.5f * v0 * (1.0f + erff(v0 * 0.70710678f));
                v1 = 0.5f * v1 * (1.0f + erff(v1 * 0.70710678f));
                v2 = 0.5f * v2 * (1.0f + erff(v2 * 0.70710678f));
                v3 = 0.5f * v3 * (1.0f + erff(v3 * 0.70710678f));
                if (r < M) {
                    size_t o = (size_t)r * Nn + c;
                    __nv_bfloat16 h0 = __float2bfloat16_rn(v0);
                    __nv_bfloat16 h1 = __float2bfloat16_rn(v1);
                    Ch[o] = h0; Ch[o + 1] = h1;
                    Cl[o]     = __float2bfloat16_rn(v0 - __bfloat162float(h0));
                    Cl[o + 1] = __float2bfloat16_rn(v1 - __bfloat162float(h1));
                }
                if (r + 8 < M) {
                    size_t o = (size_t)(r + 8) * Nn + c;
                    __nv_bfloat16 h2 = __float2bfloat16_rn(v2);
                    __nv_bfloat16 h3 = __float2bfloat16_rn(v3);
                    Ch[o] = h2; Ch[o + 1] = h3;
                    Cl[o]     = __float2bfloat16_rn(v2 - __bfloat162float(h2));
                    Cl[o + 1] = __float2bfloat16_rn(v3 - __bfloat162float(h3));
                }
            } else {
                if (r < M) {
                    size_t o = (size_t)r * Nn + c;
                    if (epi == EPI_RES) { v0 += resid[o]; v1 += resid[o + 1]; }
                    Cf[o] = v0; Cf[o + 1] = v1;
                }
                if (r + 8 < M) {
                    size_t o = (size_t)(r + 8) * Nn + c;
                    if (epi == EPI_RES) { v2 += resid[o]; v3 += resid[o + 1]; }
                    Cf[o] = v2; Cf[o + 1] = v3;
                }
            }
        }
    }
}

// ---------------- Edge-softmax attention (warp/(node,head), 2-edge unroll) ---
__global__ void attn_kernel(__nv_bfloat16* __restrict__ oh, __nv_bfloat16* __restrict__ ol)
{
    int n    = blockIdx.x;
    int h    = threadIdx.x >> 5;
    int lane = threadIdx.x & 31;
    const float* qr = g_qkv + (size_t)n * (3 * CC) + h * HDIM;
    float q = qr[lane] * QK_SCALE;
    int s = g_rowptr[n];
    int e = g_rowptr[n + 1];
    float m = -INFINITY, l = 0.0f, acc = 0.0f;

    int i = s;
    for (; i + 1 < e; i += 2) {
        int j0 = g_nbr[i];
        int j1 = g_nbr[i + 1];
        const float* b0 = g_qkv + (size_t)j0 * (3 * CC) + h * HDIM;
        const float* b1 = g_qkv + (size_t)j1 * (3 * CC) + h * HDIM;
        float k0 = b0[CC + lane];
        float k1 = b1[CC + lane];
        float v0 = b0[2 * CC + lane];
        float v1 = b1[2 * CC + lane];
        float d0 = q * k0;
        float d1 = q * k1;
        #pragma unroll
        for (int o = 16; o; o >>= 1) {
            d0 += __shfl_xor_sync(0xffffffffu, d0, o);
            d1 += __shfl_xor_sync(0xffffffffu, d1, o);
        }
        float mn = fmaxf(m, d0);
        float sc = __expf(m - mn);
        float p  = __expf(d0 - mn);
        l   = l * sc + p;
        acc = acc * sc + p * v0;
        m = mn;
        mn = fmaxf(m, d1);
        sc = __expf(m - mn);
        p  = __expf(d1 - mn);
        l   = l * sc + p;
        acc = acc * sc + p * v1;
        m = mn;
    }
    if (i < e) {
        int j = g_nbr[i];
        const float* b0 = g_qkv + (size_t)j * (3 * CC) + h * HDIM;
        float kk = b0[CC + lane];
        float vv = b0[2 * CC + lane];
        float d = q * kk;
        #pragma unroll
        for (int o = 16; o; o >>= 1) d += __shfl_xor_sync(0xffffffffu, d, o);
        float mn = fmaxf(m, d);
        float sc = __expf(m - mn);
        float p  = __expf(d - mn);
        l   = l * sc + p;
        acc = acc * sc + p * vv;
        m = mn;
    }
    float o = (l > 0.0f) ? acc / l : 0.0f;
    size_t idx = (size_t)n * CC + h * HDIM + lane;
    __nv_bfloat16 hh = __float2bfloat16_rn(o);
    oh[idx] = hh;
    ol[idx] = __float2bfloat16_rn(o - __bfloat162float(hh));
}

// ---------------- host launcher ---------------------------------------------
extern "C" void kernel_launch(void* const* d_in, const int* in_sizes, int n_in,
                              void* d_out, int out_size)
{
    const float* feats  = (const float*)d_in[0];
    const int*   ei     = (const int*)d_in[2];
    const float* ln1_g  = (const float*)d_in[3];
    const float* ln1_b  = (const float*)d_in[4];
    const float* qkv_w  = (const float*)d_in[5];
    const float* qkv_b  = (const float*)d_in[6];
    const float* proj_w = (const float*)d_in[7];
    const float* proj_b = (const float*)d_in[8];
    const float* ln2_g  = (const float*)d_in[9];
    const float* ln2_b  = (const float*)d_in[10];
    const float* fc1_w  = (const float*)d_in[11];
    const float* fc1_b  = (const float*)d_in[12];
    const float* fc2_w  = (const float*)d_in[13];
    const float* fc2_b  = (const float*)d_in[14];
    float* out = (float*)d_out;

    float *p_qkv, *p_f2;
    cudaGetSymbolAddress((void**)&p_qkv, g_qkv);
    cudaGetSymbolAddress((void**)&p_f2,  g_f2);
    __nv_bfloat16 *p_xn_h, *p_xn_l, *p_at_h, *p_at_l, *p_y_h, *p_y_l, *p_h1_h, *p_h1_l;
    cudaGetSymbolAddress((void**)&p_xn_h, g_xn_h);
    cudaGetSymbolAddress((void**)&p_xn_l, g_xn_l);
    cudaGetSymbolAddress((void**)&p_at_h, g_at_h);
    cudaGetSymbolAddress((void**)&p_at_l, g_at_l);
    cudaGetSymbolAddress((void**)&p_y_h,  g_y_h);
    cudaGetSymbolAddress((void**)&p_y_l,  g_y_l);
    cudaGetSymbolAddress((void**)&p_h1_h, g_h1_h);
    cudaGetSymbolAddress((void**)&p_h1_l, g_h1_l);
    __nv_bfloat16 *p_wqkv_h, *p_wqkv_l, *p_wprj_h, *p_wprj_l,
                  *p_wfc1_h, *p_wfc1_l, *p_wfc2_h, *p_wfc2_l;
    cudaGetSymbolAddress((void**)&p_wqkv_h, g_wqkv_h);
    cudaGetSymbolAddress((void**)&p_wqkv_l, g_wqkv_l);
    cudaGetSymbolAddress((void**)&p_wprj_h, g_wprj_h);
    cudaGetSymbolAddress((void**)&p_wprj_l, g_wprj_l);
    cudaGetSymbolAddress((void**)&p_wfc1_h, g_wfc1_h);
    cudaGetSymbolAddress((void**)&p_wfc1_l, g_wfc1_l);
    cudaGetSymbolAddress((void**)&p_wfc2_h, g_wfc2_h);
    cudaGetSymbolAddress((void**)&p_wfc2_l, g_wfc2_l);

    const int SMEM_BYTES = 2 * STAGEB;   // 81920
    static int smem_set = 0;
    if (!smem_set) {
        cudaFuncSetAttribute(gemm_sp_kernel,
                             cudaFuncAttributeMaxDynamicSharedMemorySize, SMEM_BYTES);
        smem_set = 1;
    }

    const int nscan = (NN + SCAN_B - 1) / SCAN_B;

    // weight splits
    split_kernel<<<(3*CC*CC + 255)/256, 256>>>(qkv_w, p_wqkv_h, p_wqkv_l, 3*CC*CC);
    split_kernel<<<(CC*CC   + 255)/256, 256>>>(proj_w, p_wprj_h, p_wprj_l, CC*CC);
    split_kernel<<<(HIDN*CC + 255)/256, 256>>>(fc1_w, p_wfc1_h, p_wfc1_l, HIDN*CC);
    split_kernel<<<(CC*HIDN + 255)/256, 256>>>(fc2_w, p_wfc2_h, p_wfc2_l, CC*HIDN);

    // CSR build
    zero_cnt_kernel<<<(NN + 255) / 256, 256>>>();
    count_kernel<<<(MM + 255) / 256, 256>>>(ei);
    scan1_kernel<<<nscan, SCAN_B>>>();
    scan2_kernel<<<1, 32>>>(nscan);
    scan3_kernel<<<nscan, SCAN_B>>>();
    scatter_kernel<<<(MM + 255) / 256, 256>>>(ei);

    // LN1 -> split
    ln_split_kernel<<<(NN + 7) / 8, 256>>>(feats, ln1_g, ln1_b, p_xn_h, p_xn_l);

    // qkv = xn @ qkv_w^T + b   (fp32 out)
    {
        dim3 grid(768 / BN, (NN + BM - 1) / BM);
        gemm_sp_kernel<<<grid, 256, SMEM_BYTES>>>(p_xn_h, p_xn_l, p_wqkv_h, p_wqkv_l,
                                                  qkv_b, nullptr, p_qkv, nullptr, nullptr,
                                                  NN, 768, CC, EPI_NONE);
    }

    // attention -> split att
    attn_kernel<<<NN, 256>>>(p_at_h, p_at_l);

    // f2 = feats + att @ proj_w^T + b   (fp32 out)
    {
        dim3 grid(CC / BN, (NN + BM - 1) / BM);
        gemm_sp_kernel<<<grid, 256, SMEM_BYTES>>>(p_at_h, p_at_l, p_wprj_h, p_wprj_l,
                                                  proj_b, feats, p_f2, nullptr, nullptr,
                                                  NN, CC, CC, EPI_RES);
    }

    // LN2 -> split
    ln_split_kernel<<<(NN + 7) / 8, 256>>>(p_f2, ln2_g, ln2_b, p_y_h, p_y_l);

    // h1 = gelu(y @ fc1_w^T + b)  (split out)
    {
        dim3 grid(HIDN / BN, (NN + BM - 1) / BM);
        gemm_sp_kernel<<<grid, 256, SMEM_BYTES>>>(p_y_h, p_y_l, p_wfc1_h, p_wfc1_l,
                                                  fc1_b, nullptr, nullptr, p_h1_h, p_h1_l,
                                                  NN, HIDN, CC, EPI_GELU);
    }

    // out = f2 + h1 @ fc2_w^T + b  (fp32 out)
    {
        dim3 grid(CC / BN, (NN + BM - 1) / BM);
        gemm_sp_kernel<<<grid, 256, SMEM_BYTES>>>(p_h1_h, p_h1_l, p_wfc2_h, p_wfc2_l,
                                                  fc2_b, p_f2, out, nullptr, nullptr,
                                                  NN, CC, HIDN, EPI_RES);
    }
}

// round 8
// speedup vs baseline: 1.8973x; 1.0245x over previous
#include <cuda_runtime.h>
#include <cuda_bf16.h>
#include <cstdint>
#include <math.h>

#define NN   50000
#define CC   256
#define HH   8
#define HDIM 32
#define MM   800000
#define HIDN 1024
#define QK_SCALE 0.17677669529663687f
#define LN_EPS 1e-5f

// ---------------- scratch (static device globals; no allocation) -------------
__device__ __align__(16) float g_qkv[NN * 3 * CC];
__device__ __align__(16) float g_f2 [NN * CC];
__device__ __align__(16) __nv_bfloat16 g_xn_h[NN * CC],  g_xn_l[NN * CC];
__device__ __align__(16) __nv_bfloat16 g_at_h[NN * CC],  g_at_l[NN * CC];
__device__ __align__(16) __nv_bfloat16 g_y_h [NN * CC],  g_y_l [NN * CC];
__device__ __align__(16) __nv_bfloat16 g_h1_h[NN * HIDN], g_h1_l[NN * HIDN];
__device__ __align__(16) __nv_bfloat16 g_wqkv_h[3*CC*CC], g_wqkv_l[3*CC*CC];
__device__ __align__(16) __nv_bfloat16 g_wprj_h[CC*CC],   g_wprj_l[CC*CC];
__device__ __align__(16) __nv_bfloat16 g_wfc1_h[HIDN*CC], g_wfc1_l[HIDN*CC];
__device__ __align__(16) __nv_bfloat16 g_wfc2_h[CC*HIDN], g_wfc2_l[CC*HIDN];
__device__ int g_cnt[NN];
__device__ int g_rowptr[NN + 1];
__device__ int g_cursor[NN];
__device__ int g_bsums[128];
__device__ int g_nbr[MM];

// ---------------- fp32 -> bf16 hi/lo split -----------------------------------
__global__ void split_kernel(const float* __restrict__ w,
                             __nv_bfloat16* __restrict__ wh,
                             __nv_bfloat16* __restrict__ wl, int n)
{
    int i = blockIdx.x * blockDim.x + threadIdx.x;
    if (i < n) {
        float v = w[i];
        __nv_bfloat16 h = __float2bfloat16_rn(v);
        wh[i] = h;
        wl[i] = __float2bfloat16_rn(v - __bfloat162float(h));
    }
}

// ---------------- CSR build --------------------------------------------------
__global__ void zero_cnt_kernel() {
    int i = blockIdx.x * blockDim.x + threadIdx.x;
    if (i < NN) g_cnt[i] = 0;
}

__global__ void count_kernel(const int* __restrict__ ei) {
    int e = blockIdx.x * blockDim.x + threadIdx.x;
    if (e < MM) atomicAdd(&g_cnt[ei[e]], 1);
}

#define SCAN_B 512
__global__ void scan1_kernel() {
    __shared__ int sh[SCAN_B];
    int tid = threadIdx.x;
    int i = blockIdx.x * SCAN_B + tid;
    int v = (i < NN) ? g_cnt[i] : 0;
    sh[tid] = v;
    __syncthreads();
    for (int off = 1; off < SCAN_B; off <<= 1) {
        int t = (tid >= off) ? sh[tid - off] : 0;
        __syncthreads();
        sh[tid] += t;
        __syncthreads();
    }
    if (i < NN) g_rowptr[i] = sh[tid] - v;
    if (tid == SCAN_B - 1) g_bsums[blockIdx.x] = sh[tid];
}

__global__ void scan2_kernel(int nb) {
    if (threadIdx.x == 0 && blockIdx.x == 0) {
        int a = 0;
        for (int i = 0; i < nb; i++) { int t = g_bsums[i]; g_bsums[i] = a; a += t; }
    }
}

__global__ void scan3_kernel() {
    int i = blockIdx.x * SCAN_B + threadIdx.x;
    if (i < NN) {
        int v = g_rowptr[i] + g_bsums[blockIdx.x];
        g_rowptr[i] = v;
        g_cursor[i] = v;
    }
    if (i == 0) g_rowptr[NN] = MM;
}

__global__ void scatter_kernel(const int* __restrict__ ei) {
    int e = blockIdx.x * blockDim.x + threadIdx.x;
    if (e < MM) {
        int n = ei[e];
        int p = atomicAdd(&g_cursor[n], 1);
        g_nbr[p] = ei[MM + e];
    }
}

// ---------------- LayerNorm -> split bf16 output -----------------------------
__global__ void ln_split_kernel(const float* __restrict__ x, const float* __restrict__ g,
                                const float* __restrict__ b,
                                __nv_bfloat16* __restrict__ yh,
                                __nv_bfloat16* __restrict__ yl)
{
    int row  = blockIdx.x * 8 + (threadIdx.x >> 5);
    int lane = threadIdx.x & 31;
    if (row >= NN) return;
    const float4* xr = (const float4*)(x + (size_t)row * CC);
    float4 a = xr[lane];
    float4 c = xr[lane + 32];
    float s = a.x + a.y + a.z + a.w + c.x + c.y + c.z + c.w;
    float q = a.x*a.x + a.y*a.y + a.z*a.z + a.w*a.w
            + c.x*c.x + c.y*c.y + c.z*c.z + c.w*c.w;
    #pragma unroll
    for (int o = 16; o; o >>= 1) {
        s += __shfl_xor_sync(0xffffffffu, s, o);
        q += __shfl_xor_sync(0xffffffffu, q, o);
    }
    float mean = s * (1.0f / CC);
    float var  = q * (1.0f / CC) - mean * mean;
    float rstd = rsqrtf(var + LN_EPS);
    const float4* gv = (const float4*)g;
    const float4* bv = (const float4*)b;
    float4 g1 = gv[lane], g2 = gv[lane + 32];
    float4 b1 = bv[lane], b2 = bv[lane + 32];
    float o1[4], o2[4];
    o1[0] = (a.x - mean) * rstd * g1.x + b1.x;
    o1[1] = (a.y - mean) * rstd * g1.y + b1.y;
    o1[2] = (a.z - mean) * rstd * g1.z + b1.z;
    o1[3] = (a.w - mean) * rstd * g1.w + b1.w;
    o2[0] = (c.x - mean) * rstd * g2.x + b2.x;
    o2[1] = (c.y - mean) * rstd * g2.y + b2.y;
    o2[2] = (c.z - mean) * rstd * g2.z + b2.z;
    o2[3] = (c.w - mean) * rstd * g2.w + b2.w;

    __nv_bfloat16 h1[4], l1[4], h2[4], l2[4];
    #pragma unroll
    for (int i = 0; i < 4; i++) {
        h1[i] = __float2bfloat16_rn(o1[i]);
        l1[i] = __float2bfloat16_rn(o1[i] - __bfloat162float(h1[i]));
        h2[i] = __float2bfloat16_rn(o2[i]);
        l2[i] = __float2bfloat16_rn(o2[i] - __bfloat162float(h2[i]));
    }
    size_t base = (size_t)row * CC;
    *(uint2*)&yh[base + lane * 4]       = *(uint2*)h1;
    *(uint2*)&yh[base + 128 + lane * 4] = *(uint2*)h2;
    *(uint2*)&yl[base + lane * 4]       = *(uint2*)l1;
    *(uint2*)&yl[base + 128 + lane * 4] = *(uint2*)l2;
}

// ---------------- bf16-split tensor-core GEMM, ldmatrix + cp.async -----------
#define BM 128
#define BN 128
#define BK 32
#define BKP 40
#define TILE (BM * BKP)
#define ARRB (TILE * 2)           // 10240 B per array
#define STAGEB (4 * ARRB)         // 40960 B per stage

#define EPI_NONE 0
#define EPI_GELU 1
#define EPI_RES  2

__device__ __forceinline__ uint32_t smem_u32(const void* p) {
    uint32_t a;
    asm("{ .reg .u64 t; cvta.to.shared.u64 t, %1; cvt.u32.u64 %0, t; }" : "=r"(a) : "l"(p));
    return a;
}

__device__ __forceinline__ void cp16(uint32_t dst, const void* src) {
    asm volatile("cp.async.cg.shared.global [%0],[%1],16;\n" :: "r"(dst), "l"(src));
}
#define CP_COMMIT() asm volatile("cp.async.commit_group;\n")
#define CP_WAIT(n)  asm volatile("cp.async.wait_group %0;\n" :: "n"(n))

__device__ __forceinline__ void ldsm4(unsigned& r0, unsigned& r1, unsigned& r2,
                                      unsigned& r3, uint32_t addr)
{
    asm volatile("ldmatrix.sync.aligned.m8n8.x4.shared.b16 {%0,%1,%2,%3}, [%4];"
                 : "=r"(r0), "=r"(r1), "=r"(r2), "=r"(r3) : "r"(addr));
}

__device__ __forceinline__ void mma_bf16(float4& d,
    unsigned a0, unsigned a1, unsigned a2, unsigned a3,
    unsigned b0, unsigned b1)
{
    asm volatile(
        "mma.sync.aligned.m16n8k16.row.col.f32.bf16.bf16.f32 "
        "{%0,%1,%2,%3},{%4,%5,%6,%7},{%8,%9},{%0,%1,%2,%3};"
        : "+f"(d.x), "+f"(d.y), "+f"(d.z), "+f"(d.w)
        : "r"(a0), "r"(a1), "r"(a2), "r"(a3), "r"(b0), "r"(b1));
}

__global__ __launch_bounds__(256, 2)
void gemm_sp_kernel(const __nv_bfloat16* __restrict__ Ah, const __nv_bfloat16* __restrict__ Al,
                    const __nv_bfloat16* __restrict__ Bh, const __nv_bfloat16* __restrict__ Bl,
                    const float* __restrict__ bias, const float* __restrict__ resid,
                    float* __restrict__ Cf,
                    __nv_bfloat16* __restrict__ Ch, __nv_bfloat16* __restrict__ Cl,
                    int M, int Nn, int Kk, int epi)
{
    extern __shared__ __nv_bfloat16 smem[];
    const uint32_t sb0 = smem_u32(smem);

    const int tid  = threadIdx.x;
    const int row0 = blockIdx.y * BM;
    const int col0 = blockIdx.x * BN;
    const int warp   = tid >> 5;
    const int lane   = tid & 31;
    const int warp_m = warp >> 2;
    const int warp_n = warp & 3;
    const int g = lane >> 2;
    const int t = lane & 3;

    const int rowA = warp_m * 64 + (lane & 15);
    const int colA = 8 * (lane >> 4);
    const uint32_t offA = (uint32_t)(rowA * BKP + colA) * 2;
    const int rowB = warp_n * 32 + (lane & 7) + 8 * ((lane >> 4) & 1);
    const int colB = 8 * ((lane >> 3) & 1);
    const uint32_t offB = (uint32_t)(rowB * BKP + colB) * 2;

    const int ch0 = tid * 2;
    const int nKiter = Kk / BK;

    float4 acc[4][4];
    #pragma unroll
    for (int i = 0; i < 4; i++)
        #pragma unroll
        for (int j = 0; j < 4; j++) acc[i][j] = make_float4(0.f, 0.f, 0.f, 0.f);

    auto stage = [&](int st, int k0) {
        uint32_t base = sb0 + st * STAGEB;
        #pragma unroll
        for (int q = 0; q < 2; q++) {
            int idx = ch0 + q;
            int r    = idx >> 2;
            int c16  = idx & 3;
            int ar = row0 + r; if (ar >= M) ar = M - 1;
            size_t aoff = (size_t)ar * Kk + k0 + c16 * 8;
            int br = col0 + r;
            size_t boff = (size_t)br * Kk + k0 + c16 * 8;
            uint32_t d = (uint32_t)(r * BKP + c16 * 8) * 2;
            cp16(base + 0 * ARRB + d, Ah + aoff);
            cp16(base + 1 * ARRB + d, Al + aoff);
            cp16(base + 2 * ARRB + d, Bh + boff);
            cp16(base + 3 * ARRB + d, Bl + boff);
        }
    };

    stage(0, 0);
    CP_COMMIT();

    for (int it = 0; it < nKiter; it++) {
        if (it + 1 < nKiter) {
            stage((it + 1) & 1, (it + 1) * BK);
            CP_COMMIT();
            CP_WAIT(1);
        } else {
            CP_WAIT(0);
        }
        __syncthreads();

        const uint32_t base = sb0 + (it & 1) * STAGEB;
        const uint32_t aAh = base + offA;
        const uint32_t aAl = base + ARRB + offA;
        const uint32_t aBh = base + 2 * ARRB + offB;
        const uint32_t aBl = base + 3 * ARRB + offB;

        #pragma unroll
        for (int s = 0; s < 2; s++) {
            unsigned bh[4][2], bl[4][2];
            ldsm4(bh[0][0], bh[0][1], bh[1][0], bh[1][1], aBh + s * 32);
            ldsm4(bh[2][0], bh[2][1], bh[3][0], bh[3][1], aBh + 16 * BKP * 2 + s * 32);
            ldsm4(bl[0][0], bl[0][1], bl[1][0], bl[1][1], aBl + s * 32);
            ldsm4(bl[2][0], bl[2][1], bl[3][0], bl[3][1], aBl + 16 * BKP * 2 + s * 32);
            #pragma unroll
            for (int mi = 0; mi < 4; mi++) {
                unsigned ah0, ah1, ah2, ah3, al0, al1, al2, al3;
                ldsm4(ah0, ah1, ah2, ah3, aAh + mi * (16 * BKP * 2) + s * 32);
                ldsm4(al0, al1, al2, al3, aAl + mi * (16 * BKP * 2) + s * 32);
                // term-major: same-acc reuse distance = 4 mmas (covers HMMA latency)
                #pragma unroll
                for (int ni = 0; ni < 4; ni++)
                    mma_bf16(acc[mi][ni], ah0, ah1, ah2, ah3, bh[ni][0], bh[ni][1]);
                #pragma unroll
                for (int ni = 0; ni < 4; ni++)
                    mma_bf16(acc[mi][ni], ah0, ah1, ah2, ah3, bl[ni][0], bl[ni][1]);
                #pragma unroll
                for (int ni = 0; ni < 4; ni++)
                    mma_bf16(acc[mi][ni], al0, al1, al2, al3, bh[ni][0], bh[ni][1]);
            }
        }
        __syncthreads();
    }

    #pragma unroll
    for (int mi = 0; mi < 4; mi++) {
        int r = row0 + warp_m * 64 + mi * 16 + g;
        #pragma unroll
        for (int ni = 0; ni < 4; ni++) {
            int c = col0 + warp_n * 32 + ni * 8 + 2 * t;
            float bx = bias[c], by = bias[c + 1];
            float4 d = acc[mi][ni];
            float v0 = d.x + bx, v1 = d.y + by;
            float v2 = d.z + bx, v3 = d.w + by;
            if (epi == EPI_GELU) {
                v0 = 0.5f * v0 * (1.0f + erff(v0 * 0.70710678f));
                v1 = 0.5f * v1 * (1.0f + erff(v1 * 0.70710678f));
                v2 = 0.5f * v2 * (1.0f + erff(v2 * 0.70710678f));
                v3 = 0.5f * v3 * (1.0f + erff(v3 * 0.70710678f));
                if (r < M) {
                    size_t o = (size_t)r * Nn + c;
                    __nv_bfloat16 h0 = __float2bfloat16_rn(v0);
                    __nv_bfloat16 h1 = __float2bfloat16_rn(v1);
                    Ch[o] = h0; Ch[o + 1] = h1;
                    Cl[o]     = __float2bfloat16_rn(v0 - __bfloat162float(h0));
                    Cl[o + 1] = __float2bfloat16_rn(v1 - __bfloat162float(h1));
                }
                if (r + 8 < M) {
                    size_t o = (size_t)(r + 8) * Nn + c;
                    __nv_bfloat16 h2 = __float2bfloat16_rn(v2);
                    __nv_bfloat16 h3 = __float2bfloat16_rn(v3);
                    Ch[o] = h2; Ch[o + 1] = h3;
                    Cl[o]     = __float2bfloat16_rn(v2 - __bfloat162float(h2));
                    Cl[o + 1] = __float2bfloat16_rn(v3 - __bfloat162float(h3));
                }
            } else {
                if (r < M) {
                    size_t o = (size_t)r * Nn + c;
                    if (epi == EPI_RES) { v0 += resid[o]; v1 += resid[o + 1]; }
                    Cf[o] = v0; Cf[o + 1] = v1;
                }
                if (r + 8 < M) {
                    size_t o = (size_t)(r + 8) * Nn + c;
                    if (epi == EPI_RES) { v2 += resid[o]; v3 += resid[o + 1]; }
                    Cf[o] = v2; Cf[o + 1] = v3;
                }
            }
        }
    }
}

// ---------------- Edge-softmax attention (warp/(node,head), 4-edge batch) ----
__global__ void attn_kernel(__nv_bfloat16* __restrict__ oh, __nv_bfloat16* __restrict__ ol)
{
    int n    = blockIdx.x;
    int h    = threadIdx.x >> 5;
    int lane = threadIdx.x & 31;
    const float* qr = g_qkv + (size_t)n * (3 * CC) + h * HDIM;
    float q = qr[lane] * QK_SCALE;
    int s = g_rowptr[n];
    int e = g_rowptr[n + 1];
    float m = -INFINITY, l = 0.0f, acc = 0.0f;

    int i = s;
    for (; i + 3 < e; i += 4) {
        int   j[4];
        float kk[4], vv[4], d[4];
        #pragma unroll
        for (int u = 0; u < 4; u++) j[u] = g_nbr[i + u];
        #pragma unroll
        for (int u = 0; u < 4; u++) {
            const float* b = g_qkv + (size_t)j[u] * (3 * CC) + h * HDIM;
            kk[u] = b[CC + lane];
            vv[u] = b[2 * CC + lane];
        }
        #pragma unroll
        for (int u = 0; u < 4; u++) d[u] = q * kk[u];
        #pragma unroll
        for (int o = 16; o; o >>= 1) {
            #pragma unroll
            for (int u = 0; u < 4; u++)
                d[u] += __shfl_xor_sync(0xffffffffu, d[u], o);
        }
        // batched online-softmax update
        float mb = fmaxf(fmaxf(d[0], d[1]), fmaxf(d[2], d[3]));
        float mn = fmaxf(m, mb);
        float sc = __expf(m - mn);
        float p0 = __expf(d[0] - mn);
        float p1 = __expf(d[1] - mn);
        float p2 = __expf(d[2] - mn);
        float p3 = __expf(d[3] - mn);
        l   = l * sc + (p0 + p1 + p2 + p3);
        acc = acc * sc + p0 * vv[0] + p1 * vv[1] + p2 * vv[2] + p3 * vv[3];
        m = mn;
    }
    for (; i < e; i++) {
        int j = g_nbr[i];
        const float* b0 = g_qkv + (size_t)j * (3 * CC) + h * HDIM;
        float kk = b0[CC + lane];
        float vv = b0[2 * CC + lane];
        float d = q * kk;
        #pragma unroll
        for (int o = 16; o; o >>= 1) d += __shfl_xor_sync(0xffffffffu, d, o);
        float mn = fmaxf(m, d);
        float sc = __expf(m - mn);
        float p  = __expf(d - mn);
        l   = l * sc + p;
        acc = acc * sc + p * vv;
        m = mn;
    }
    float o = (l > 0.0f) ? acc / l : 0.0f;
    size_t idx = (size_t)n * CC + h * HDIM + lane;
    __nv_bfloat16 hh = __float2bfloat16_rn(o);
    oh[idx] = hh;
    ol[idx] = __float2bfloat16_rn(o - __bfloat162float(hh));
}

// ---------------- host launcher ---------------------------------------------
extern "C" void kernel_launch(void* const* d_in, const int* in_sizes, int n_in,
                              void* d_out, int out_size)
{
    const float* feats  = (const float*)d_in[0];
    const int*   ei     = (const int*)d_in[2];
    const float* ln1_g  = (const float*)d_in[3];
    const float* ln1_b  = (const float*)d_in[4];
    const float* qkv_w  = (const float*)d_in[5];
    const float* qkv_b  = (const float*)d_in[6];
    const float* proj_w = (const float*)d_in[7];
    const float* proj_b = (const float*)d_in[8];
    const float* ln2_g  = (const float*)d_in[9];
    const float* ln2_b  = (const float*)d_in[10];
    const float* fc1_w  = (const float*)d_in[11];
    const float* fc1_b  = (const float*)d_in[12];
    const float* fc2_w  = (const float*)d_in[13];
    const float* fc2_b  = (const float*)d_in[14];
    float* out = (float*)d_out;

    float *p_qkv, *p_f2;
    cudaGetSymbolAddress((void**)&p_qkv, g_qkv);
    cudaGetSymbolAddress((void**)&p_f2,  g_f2);
    __nv_bfloat16 *p_xn_h, *p_xn_l, *p_at_h, *p_at_l, *p_y_h, *p_y_l, *p_h1_h, *p_h1_l;
    cudaGetSymbolAddress((void**)&p_xn_h, g_xn_h);
    cudaGetSymbolAddress((void**)&p_xn_l, g_xn_l);
    cudaGetSymbolAddress((void**)&p_at_h, g_at_h);
    cudaGetSymbolAddress((void**)&p_at_l, g_at_l);
    cudaGetSymbolAddress((void**)&p_y_h,  g_y_h);
    cudaGetSymbolAddress((void**)&p_y_l,  g_y_l);
    cudaGetSymbolAddress((void**)&p_h1_h, g_h1_h);
    cudaGetSymbolAddress((void**)&p_h1_l, g_h1_l);
    __nv_bfloat16 *p_wqkv_h, *p_wqkv_l, *p_wprj_h, *p_wprj_l,
                  *p_wfc1_h, *p_wfc1_l, *p_wfc2_h, *p_wfc2_l;
    cudaGetSymbolAddress((void**)&p_wqkv_h, g_wqkv_h);
    cudaGetSymbolAddress((void**)&p_wqkv_l, g_wqkv_l);
    cudaGetSymbolAddress((void**)&p_wprj_h, g_wprj_h);
    cudaGetSymbolAddress((void**)&p_wprj_l, g_wprj_l);
    cudaGetSymbolAddress((void**)&p_wfc1_h, g_wfc1_h);
    cudaGetSymbolAddress((void**)&p_wfc1_l, g_wfc1_l);
    cudaGetSymbolAddress((void**)&p_wfc2_h, g_wfc2_h);
    cudaGetSymbolAddress((void**)&p_wfc2_l, g_wfc2_l);

    const int SMEM_BYTES = 2 * STAGEB;
    static int smem_set = 0;
    if (!smem_set) {
        cudaFuncSetAttribute(gemm_sp_kernel,
                             cudaFuncAttributeMaxDynamicSharedMemorySize, SMEM_BYTES);
        smem_set = 1;
    }

    const int nscan = (NN + SCAN_B - 1) / SCAN_B;

    split_kernel<<<(3*CC*CC + 255)/256, 256>>>(qkv_w, p_wqkv_h, p_wqkv_l, 3*CC*CC);
    split_kernel<<<(CC*CC   + 255)/256, 256>>>(proj_w, p_wprj_h, p_wprj_l, CC*CC);
    split_kernel<<<(HIDN*CC + 255)/256, 256>>>(fc1_w, p_wfc1_h, p_wfc1_l, HIDN*CC);
    split_kernel<<<(CC*HIDN + 255)/256, 256>>>(fc2_w, p_wfc2_h, p_wfc2_l, CC*HIDN);

    zero_cnt_kernel<<<(NN + 255) / 256, 256>>>();
    count_kernel<<<(MM + 255) / 256, 256>>>(ei);
    scan1_kernel<<<nscan, SCAN_B>>>();
    scan2_kernel<<<1, 32>>>(nscan);
    scan3_kernel<<<nscan, SCAN_B>>>();
    scatter_kernel<<<(MM + 255) / 256, 256>>>(ei);

    ln_split_kernel<<<(NN + 7) / 8, 256>>>(feats, ln1_g, ln1_b, p_xn_h, p_xn_l);

    {
        dim3 grid(768 / BN, (NN + BM - 1) / BM);
        gemm_sp_kernel<<<grid, 256, SMEM_BYTES>>>(p_xn_h, p_xn_l, p_wqkv_h, p_wqkv_l,
                                                  qkv_b, nullptr, p_qkv, nullptr, nullptr,
                                                  NN, 768, CC, EPI_NONE);
    }

    attn_kernel<<<NN, 256>>>(p_at_h, p_at_l);

    {
        dim3 grid(CC / BN, (NN + BM - 1) / BM);
        gemm_sp_kernel<<<grid, 256, SMEM_BYTES>>>(p_at_h, p_at_l, p_wprj_h, p_wprj_l,
                                                  proj_b, feats, p_f2, nullptr, nullptr,
                                                  NN, CC, CC, EPI_RES);
    }

    ln_split_kernel<<<(NN + 7) / 8, 256>>>(p_f2, ln2_g, ln2_b, p_y_h, p_y_l);

    {
        dim3 grid(HIDN / BN, (NN + BM - 1) / BM);
        gemm_sp_kernel<<<grid, 256, SMEM_BYTES>>>(p_y_h, p_y_l, p_wfc1_h, p_wfc1_l,
                                                  fc1_b, nullptr, nullptr, p_h1_h, p_h1_l,
                                                  NN, HIDN, CC, EPI_GELU);
    }

    {
        dim3 grid(CC / BN, (NN + BM - 1) / BM);
        gemm_sp_kernel<<<grid, 256, SMEM_BYTES>>>(p_h1_h, p_h1_l, p_wfc2_h, p_wfc2_l,
                                                  fc2_b, p_f2, out, nullptr, nullptr,
                                                  NN, CC, HIDN, EPI_RES);
    }
}

// round 9
// speedup vs baseline: 2.3184x; 1.2219x over previous
#include <cuda_runtime.h>
#include <cuda_fp16.h>
#include <cstdint>
#include <math.h>

#define NN   50000
#define CC   256
#define HH   8
#define HDIM 32
#define MM   800000
#define HIDN 1024
#define QK_SCALE 0.17677669529663687f
#define LN_EPS 1e-5f

// ---------------- scratch (static device globals; no allocation) -------------
__device__ __align__(16) float g_q  [NN * CC];            // scaled q (fp32)
__device__ __align__(16) __half g_kv[NN * HH * 64];       // [n][h][k32|v32] fp16
__device__ __align__(16) float g_f2 [NN * CC];
__device__ __align__(16) __half g_xn_h[NN * CC],  g_xn_l[NN * CC];
__device__ __align__(16) __half g_at_h[NN * CC],  g_at_l[NN * CC];
__device__ __align__(16) __half g_y_h [NN * CC],  g_y_l [NN * CC];
__device__ __align__(16) __half g_h1_h[NN * HIDN], g_h1_l[NN * HIDN];
__device__ __align__(16) __half g_wqkv[3*CC*CC];
__device__ __align__(16) __half g_wprj[CC*CC];
__device__ __align__(16) __half g_wfc1[HIDN*CC];
__device__ __align__(16) __half g_wfc2[CC*HIDN];
__device__ int g_cnt[NN];
__device__ int g_rowptr[NN + 1];
__device__ int g_cursor[NN];
__device__ int g_bsums[128];
__device__ int g_nbr[MM];

// ---------------- fp32 -> fp16 weight round ----------------------------------
__global__ void round_kernel(const float* __restrict__ w,
                             __half* __restrict__ wh, int n)
{
    int i = blockIdx.x * blockDim.x + threadIdx.x;
    if (i < n) wh[i] = __float2half_rn(w[i]);
}

// ---------------- CSR build --------------------------------------------------
__global__ void zero_cnt_kernel() {
    int i = blockIdx.x * blockDim.x + threadIdx.x;
    if (i < NN) g_cnt[i] = 0;
}

__global__ void count_kernel(const int* __restrict__ ei) {
    int e = blockIdx.x * blockDim.x + threadIdx.x;
    if (e < MM) atomicAdd(&g_cnt[ei[e]], 1);
}

#define SCAN_B 512
__global__ void scan1_kernel() {
    __shared__ int sh[SCAN_B];
    int tid = threadIdx.x;
    int i = blockIdx.x * SCAN_B + tid;
    int v = (i < NN) ? g_cnt[i] : 0;
    sh[tid] = v;
    __syncthreads();
    for (int off = 1; off < SCAN_B; off <<= 1) {
        int t = (tid >= off) ? sh[tid - off] : 0;
        __syncthreads();
        sh[tid] += t;
        __syncthreads();
    }
    if (i < NN) g_rowptr[i] = sh[tid] - v;
    if (tid == SCAN_B - 1) g_bsums[blockIdx.x] = sh[tid];
}

__global__ void scan2_kernel(int nb) {
    __shared__ int sh[128];
    int tid = threadIdx.x;
    int v = (tid < nb) ? g_bsums[tid] : 0;
    sh[tid] = v;
    __syncthreads();
    for (int off = 1; off < 128; off <<= 1) {
        int t = (tid >= off) ? sh[tid - off] : 0;
        __syncthreads();
        sh[tid] += t;
        __syncthreads();
    }
    if (tid < nb) g_bsums[tid] = sh[tid] - v;   // exclusive
}

__global__ void scan3_kernel() {
    int i = blockIdx.x * SCAN_B + threadIdx.x;
    if (i < NN) {
        int v = g_rowptr[i] + g_bsums[blockIdx.x];
        g_rowptr[i] = v;
        g_cursor[i] = v;
    }
    if (i == 0) g_rowptr[NN] = MM;
}

__global__ void scatter_kernel(const int* __restrict__ ei) {
    int e = blockIdx.x * blockDim.x + threadIdx.x;
    if (e < MM) {
        int n = ei[e];
        int p = atomicAdd(&g_cursor[n], 1);
        g_nbr[p] = ei[MM + e];
    }
}

// ---------------- LayerNorm -> split fp16 output ------------------------------
__global__ void ln_split_kernel(const float* __restrict__ x, const float* __restrict__ g,
                                const float* __restrict__ b,
                                __half* __restrict__ yh, __half* __restrict__ yl)
{
    int row  = blockIdx.x * 8 + (threadIdx.x >> 5);
    int lane = threadIdx.x & 31;
    if (row >= NN) return;
    const float4* xr = (const float4*)(x + (size_t)row * CC);
    float4 a = xr[lane];
    float4 c = xr[lane + 32];
    float s = a.x + a.y + a.z + a.w + c.x + c.y + c.z + c.w;
    float q = a.x*a.x + a.y*a.y + a.z*a.z + a.w*a.w
            + c.x*c.x + c.y*c.y + c.z*c.z + c.w*c.w;
    #pragma unroll
    for (int o = 16; o; o >>= 1) {
        s += __shfl_xor_sync(0xffffffffu, s, o);
        q += __shfl_xor_sync(0xffffffffu, q, o);
    }
    float mean = s * (1.0f / CC);
    float var  = q * (1.0f / CC) - mean * mean;
    float rstd = rsqrtf(var + LN_EPS);
    const float4* gv = (const float4*)g;
    const float4* bv = (const float4*)b;
    float4 g1 = gv[lane], g2 = gv[lane + 32];
    float4 b1 = bv[lane], b2 = bv[lane + 32];
    float o1[4], o2[4];
    o1[0] = (a.x - mean) * rstd * g1.x + b1.x;
    o1[1] = (a.y - mean) * rstd * g1.y + b1.y;
    o1[2] = (a.z - mean) * rstd * g1.z + b1.z;
    o1[3] = (a.w - mean) * rstd * g1.w + b1.w;
    o2[0] = (c.x - mean) * rstd * g2.x + b2.x;
    o2[1] = (c.y - mean) * rstd * g2.y + b2.y;
    o2[2] = (c.z - mean) * rstd * g2.z + b2.z;
    o2[3] = (c.w - mean) * rstd * g2.w + b2.w;

    __half h1[4], l1[4], h2[4], l2[4];
    #pragma unroll
    for (int i = 0; i < 4; i++) {
        h1[i] = __float2half_rn(o1[i]);
        l1[i] = __float2half_rn(o1[i] - __half2float(h1[i]));
        h2[i] = __float2half_rn(o2[i]);
        l2[i] = __float2half_rn(o2[i] - __half2float(h2[i]));
    }
    size_t base = (size_t)row * CC;
    *(uint2*)&yh[base + lane * 4]       = *(uint2*)h1;
    *(uint2*)&yh[base + 128 + lane * 4] = *(uint2*)h2;
    *(uint2*)&yl[base + lane * 4]       = *(uint2*)l1;
    *(uint2*)&yl[base + 128 + lane * 4] = *(uint2*)l2;
}

// ---------------- fp16 2-mma compensated GEMM --------------------------------
// C[M,N] = (Ah+Al)[M,K] @ Bh[N,K]^T + bias (+epilogue)
#define BM 128
#define BN 128
#define BK 32
#define BKP 40
#define TILE (BM * BKP)
#define ARRB (TILE * 2)           // 10240 B per array
#define STAGEB (3 * ARRB)         // 30720 B per stage (Ah, Al, Bh)

#define EPI_QKV  0
#define EPI_GELU 1
#define EPI_RES  2

__device__ __forceinline__ uint32_t smem_u32(const void* p) {
    uint32_t a;
    asm("{ .reg .u64 t; cvta.to.shared.u64 t, %1; cvt.u32.u64 %0, t; }" : "=r"(a) : "l"(p));
    return a;
}

__device__ __forceinline__ void cp16(uint32_t dst, const void* src) {
    asm volatile("cp.async.cg.shared.global [%0],[%1],16;\n" :: "r"(dst), "l"(src));
}
#define CP_COMMIT() asm volatile("cp.async.commit_group;\n")
#define CP_WAIT(n)  asm volatile("cp.async.wait_group %0;\n" :: "n"(n))

__device__ __forceinline__ void ldsm4(unsigned& r0, unsigned& r1, unsigned& r2,
                                      unsigned& r3, uint32_t addr)
{
    asm volatile("ldmatrix.sync.aligned.m8n8.x4.shared.b16 {%0,%1,%2,%3}, [%4];"
                 : "=r"(r0), "=r"(r1), "=r"(r2), "=r"(r3) : "r"(addr));
}

__device__ __forceinline__ void mma_f16(float4& d,
    unsigned a0, unsigned a1, unsigned a2, unsigned a3,
    unsigned b0, unsigned b1)
{
    asm volatile(
        "mma.sync.aligned.m16n8k16.row.col.f32.f16.f16.f32 "
        "{%0,%1,%2,%3},{%4,%5,%6,%7},{%8,%9},{%0,%1,%2,%3};"
        : "+f"(d.x), "+f"(d.y), "+f"(d.z), "+f"(d.w)
        : "r"(a0), "r"(a1), "r"(a2), "r"(a3), "r"(b0), "r"(b1));
}

__global__ __launch_bounds__(256, 2)
void gemm_sp_kernel(const __half* __restrict__ Ah, const __half* __restrict__ Al,
                    const __half* __restrict__ Bh,
                    const float* __restrict__ bias, const float* __restrict__ resid,
                    float* __restrict__ Cf,
                    __half* __restrict__ Ch, __half* __restrict__ Cl,
                    int M, int Nn, int Kk, int epi)
{
    extern __shared__ __half smem[];
    const uint32_t sb0 = smem_u32(smem);

    const int tid  = threadIdx.x;
    const int row0 = blockIdx.y * BM;
    const int col0 = blockIdx.x * BN;
    const int warp   = tid >> 5;
    const int lane   = tid & 31;
    const int warp_m = warp >> 2;
    const int warp_n = warp & 3;
    const int g = lane >> 2;
    const int t = lane & 3;

    const int rowA = warp_m * 64 + (lane & 15);
    const int colA = 8 * (lane >> 4);
    const uint32_t offA = (uint32_t)(rowA * BKP + colA) * 2;
    const int rowB = warp_n * 32 + (lane & 7) + 8 * ((lane >> 4) & 1);
    const int colB = 8 * ((lane >> 3) & 1);
    const uint32_t offB = (uint32_t)(rowB * BKP + colB) * 2;

    const int ch0 = tid * 2;
    const int nKiter = Kk / BK;

    float4 acc[4][4];
    #pragma unroll
    for (int i = 0; i < 4; i++)
        #pragma unroll
        for (int j = 0; j < 4; j++) acc[i][j] = make_float4(0.f, 0.f, 0.f, 0.f);

    auto stage = [&](int st, int k0) {
        uint32_t base = sb0 + st * STAGEB;
        #pragma unroll
        for (int q = 0; q < 2; q++) {
            int idx = ch0 + q;
            int r    = idx >> 2;
            int c16  = idx & 3;
            int ar = row0 + r; if (ar >= M) ar = M - 1;
            size_t aoff = (size_t)ar * Kk + k0 + c16 * 8;
            int br = col0 + r;
            size_t boff = (size_t)br * Kk + k0 + c16 * 8;
            uint32_t d = (uint32_t)(r * BKP + c16 * 8) * 2;
            cp16(base + 0 * ARRB + d, Ah + aoff);
            cp16(base + 1 * ARRB + d, Al + aoff);
            cp16(base + 2 * ARRB + d, Bh + boff);
        }
    };

    stage(0, 0);
    CP_COMMIT();

    for (int it = 0; it < nKiter; it++) {
        if (it + 1 < nKiter) {
            stage((it + 1) & 1, (it + 1) * BK);
            CP_COMMIT();
            CP_WAIT(1);
        } else {
            CP_WAIT(0);
        }
        __syncthreads();

        const uint32_t base = sb0 + (it & 1) * STAGEB;
        const uint32_t aAh = base + offA;
        const uint32_t aAl = base + ARRB + offA;
        const uint32_t aBh = base + 2 * ARRB + offB;

        #pragma unroll
        for (int s = 0; s < 2; s++) {
            unsigned bh[4][2];
            ldsm4(bh[0][0], bh[0][1], bh[1][0], bh[1][1], aBh + s * 32);
            ldsm4(bh[2][0], bh[2][1], bh[3][0], bh[3][1], aBh + 16 * BKP * 2 + s * 32);
            #pragma unroll
            for (int mi = 0; mi < 4; mi++) {
                unsigned ah0, ah1, ah2, ah3, al0, al1, al2, al3;
                ldsm4(ah0, ah1, ah2, ah3, aAh + mi * (16 * BKP * 2) + s * 32);
                ldsm4(al0, al1, al2, al3, aAl + mi * (16 * BKP * 2) + s * 32);
                #pragma unroll
                for (int ni = 0; ni < 4; ni++)
                    mma_f16(acc[mi][ni], ah0, ah1, ah2, ah3, bh[ni][0], bh[ni][1]);
                #pragma unroll
                for (int ni = 0; ni < 4; ni++)
                    mma_f16(acc[mi][ni], al0, al1, al2, al3, bh[ni][0], bh[ni][1]);
            }
        }
        __syncthreads();
    }

    const int region = col0 >> 8;     // for EPI_QKV: 0=q, 1=k, 2=v
    #pragma unroll
    for (int mi = 0; mi < 4; mi++) {
        int r = row0 + warp_m * 64 + mi * 16 + g;
        #pragma unroll
        for (int ni = 0; ni < 4; ni++) {
            int c = col0 + warp_n * 32 + ni * 8 + 2 * t;
            float bx = bias[c], by = bias[c + 1];
            float4 d = acc[mi][ni];
            float v0 = d.x + bx, v1 = d.y + by;
            float v2 = d.z + bx, v3 = d.w + by;
            if (epi == EPI_QKV) {
                int local = c & 255;
                if (region == 0) {
                    if (r < M) {
                        g_q[(size_t)r * CC + local]     = v0 * QK_SCALE;
                        g_q[(size_t)r * CC + local + 1] = v1 * QK_SCALE;
                    }
                    if (r + 8 < M) {
                        g_q[(size_t)(r + 8) * CC + local]     = v2 * QK_SCALE;
                        g_q[(size_t)(r + 8) * CC + local + 1] = v3 * QK_SCALE;
                    }
                } else {
                    int h  = local >> 5;
                    int dd = (local & 31) + (region == 2 ? 32 : 0);
                    if (r < M) {
                        __half2 p; p.x = __float2half_rn(v0); p.y = __float2half_rn(v1);
                        *(__half2*)&g_kv[((size_t)r * HH + h) * 64 + dd] = p;
                    }
                    if (r + 8 < M) {
                        __half2 p; p.x = __float2half_rn(v2); p.y = __float2half_rn(v3);
                        *(__half2*)&g_kv[((size_t)(r + 8) * HH + h) * 64 + dd] = p;
                    }
                }
            } else if (epi == EPI_GELU) {
                v0 = 0.5f * v0 * (1.0f + erff(v0 * 0.70710678f));
                v1 = 0.5f * v1 * (1.0f + erff(v1 * 0.70710678f));
                v2 = 0.5f * v2 * (1.0f + erff(v2 * 0.70710678f));
                v3 = 0.5f * v3 * (1.0f + erff(v3 * 0.70710678f));
                if (r < M) {
                    size_t o = (size_t)r * Nn + c;
                    __half h0 = __float2half_rn(v0);
                    __half h1 = __float2half_rn(v1);
                    Ch[o] = h0; Ch[o + 1] = h1;
                    Cl[o]     = __float2half_rn(v0 - __half2float(h0));
                    Cl[o + 1] = __float2half_rn(v1 - __half2float(h1));
                }
                if (r + 8 < M) {
                    size_t o = (size_t)(r + 8) * Nn + c;
                    __half h2 = __float2half_rn(v2);
                    __half h3 = __float2half_rn(v3);
                    Ch[o] = h2; Ch[o + 1] = h3;
                    Cl[o]     = __float2half_rn(v2 - __half2float(h2));
                    Cl[o + 1] = __float2half_rn(v3 - __half2float(h3));
                }
            } else {
                if (r < M) {
                    size_t o = (size_t)r * Nn + c;
                    float r0 = resid[o], r1 = resid[o + 1];
                    Cf[o] = v0 + r0; Cf[o + 1] = v1 + r1;
                }
                if (r + 8 < M) {
                    size_t o = (size_t)(r + 8) * Nn + c;
                    float r2 = resid[o], r3 = resid[o + 1];
                    Cf[o] = v2 + r2; Cf[o + 1] = v3 + r3;
                }
            }
        }
    }
}

// ---------------- Edge-softmax attention (warp/(node,head), 4-edge batch) ----
__global__ void attn_kernel(__half* __restrict__ oh, __half* __restrict__ ol)
{
    int n    = blockIdx.x;
    int h    = threadIdx.x >> 5;
    int lane = threadIdx.x & 31;
    float q = g_q[(size_t)n * CC + h * HDIM + lane];   // pre-scaled
    int s = g_rowptr[n];
    int e = g_rowptr[n + 1];
    float m = -INFINITY, l = 0.0f, acc = 0.0f;

    int i = s;
    for (; i + 3 < e; i += 4) {
        int j[4];
        float kk[4], vv[4], d[4];
        #pragma unroll
        for (int u = 0; u < 4; u++) j[u] = g_nbr[i + u];
        #pragma unroll
        for (int u = 0; u < 4; u++) {
            const __half* b = g_kv + ((size_t)j[u] * HH + h) * 64;
            kk[u] = __half2float(b[lane]);
            vv[u] = __half2float(b[32 + lane]);
        }
        #pragma unroll
        for (int u = 0; u < 4; u++) d[u] = q * kk[u];
        #pragma unroll
        for (int o = 16; o; o >>= 1) {
            #pragma unroll
            for (int u = 0; u < 4; u++)
                d[u] += __shfl_xor_sync(0xffffffffu, d[u], o);
        }
        float mb = fmaxf(fmaxf(d[0], d[1]), fmaxf(d[2], d[3]));
        float mn = fmaxf(m, mb);
        float sc = __expf(m - mn);
        float p0 = __expf(d[0] - mn);
        float p1 = __expf(d[1] - mn);
        float p2 = __expf(d[2] - mn);
        float p3 = __expf(d[3] - mn);
        l   = l * sc + (p0 + p1 + p2 + p3);
        acc = acc * sc + p0 * vv[0] + p1 * vv[1] + p2 * vv[2] + p3 * vv[3];
        m = mn;
    }
    for (; i < e; i++) {
        int j = g_nbr[i];
        const __half* b = g_kv + ((size_t)j * HH + h) * 64;
        float kk = __half2float(b[lane]);
        float vv = __half2float(b[32 + lane]);
        float d = q * kk;
        #pragma unroll
        for (int o = 16; o; o >>= 1) d += __shfl_xor_sync(0xffffffffu, d, o);
        float mn = fmaxf(m, d);
        float sc = __expf(m - mn);
        float p  = __expf(d - mn);
        l   = l * sc + p;
        acc = acc * sc + p * vv;
        m = mn;
    }
    float o = (l > 0.0f) ? acc / l : 0.0f;
    size_t idx = (size_t)n * CC + h * HDIM + lane;
    __half hh = __float2half_rn(o);
    oh[idx] = hh;
    ol[idx] = __float2half_rn(o - __half2float(hh));
}

// ---------------- host launcher ---------------------------------------------
extern "C" void kernel_launch(void* const* d_in, const int* in_sizes, int n_in,
                              void* d_out, int out_size)
{
    const float* feats  = (const float*)d_in[0];
    const int*   ei     = (const int*)d_in[2];
    const float* ln1_g  = (const float*)d_in[3];
    const float* ln1_b  = (const float*)d_in[4];
    const float* qkv_w  = (const float*)d_in[5];
    const float* qkv_b  = (const float*)d_in[6];
    const float* proj_w = (const float*)d_in[7];
    const float* proj_b = (const float*)d_in[8];
    const float* ln2_g  = (const float*)d_in[9];
    const float* ln2_b  = (const float*)d_in[10];
    const float* fc1_w  = (const float*)d_in[11];
    const float* fc1_b  = (const float*)d_in[12];
    const float* fc2_w  = (const float*)d_in[13];
    const float* fc2_b  = (const float*)d_in[14];
    float* out = (float*)d_out;

    float *p_f2;
    cudaGetSymbolAddress((void**)&p_f2,  g_f2);
    __half *p_xn_h, *p_xn_l, *p_at_h, *p_at_l, *p_y_h, *p_y_l, *p_h1_h, *p_h1_l;
    cudaGetSymbolAddress((void**)&p_xn_h, g_xn_h);
    cudaGetSymbolAddress((void**)&p_xn_l, g_xn_l);
    cudaGetSymbolAddress((void**)&p_at_h, g_at_h);
    cudaGetSymbolAddress((void**)&p_at_l, g_at_l);
    cudaGetSymbolAddress((void**)&p_y_h,  g_y_h);
    cudaGetSymbolAddress((void**)&p_y_l,  g_y_l);
    cudaGetSymbolAddress((void**)&p_h1_h, g_h1_h);
    cudaGetSymbolAddress((void**)&p_h1_l, g_h1_l);
    __half *p_wqkv, *p_wprj, *p_wfc1, *p_wfc2;
    cudaGetSymbolAddress((void**)&p_wqkv, g_wqkv);
    cudaGetSymbolAddress((void**)&p_wprj, g_wprj);
    cudaGetSymbolAddress((void**)&p_wfc1, g_wfc1);
    cudaGetSymbolAddress((void**)&p_wfc2, g_wfc2);

    const int SMEM_BYTES = 2 * STAGEB;   // 61440
    static int smem_set = 0;
    if (!smem_set) {
        cudaFuncSetAttribute(gemm_sp_kernel,
                             cudaFuncAttributeMaxDynamicSharedMemorySize, SMEM_BYTES);
        smem_set = 1;
    }

    const int nscan = (NN + SCAN_B - 1) / SCAN_B;

    round_kernel<<<(3*CC*CC + 255)/256, 256>>>(qkv_w, p_wqkv, 3*CC*CC);
    round_kernel<<<(CC*CC   + 255)/256, 256>>>(proj_w, p_wprj, CC*CC);
    round_kernel<<<(HIDN*CC + 255)/256, 256>>>(fc1_w, p_wfc1, HIDN*CC);
    round_kernel<<<(CC*HIDN + 255)/256, 256>>>(fc2_w, p_wfc2, CC*HIDN);

    zero_cnt_kernel<<<(NN + 255) / 256, 256>>>();
    count_kernel<<<(MM + 255) / 256, 256>>>(ei);
    scan1_kernel<<<nscan, SCAN_B>>>();
    scan2_kernel<<<1, 128>>>(nscan);
    scan3_kernel<<<nscan, SCAN_B>>>();
    scatter_kernel<<<(MM + 255) / 256, 256>>>(ei);

    ln_split_kernel<<<(NN + 7) / 8, 256>>>(feats, ln1_g, ln1_b, p_xn_h, p_xn_l);

    // qkv: writes g_q (scaled fp32) + g_kv (fp16 packed) directly
    {
        dim3 grid(768 / BN, (NN + BM - 1) / BM);
        gemm_sp_kernel<<<grid, 256, SMEM_BYTES>>>(p_xn_h, p_xn_l, p_wqkv,
                                                  qkv_b, nullptr, nullptr, nullptr, nullptr,
                                                  NN, 768, CC, EPI_QKV);
    }

    attn_kernel<<<NN, 256>>>(p_at_h, p_at_l);

    {
        dim3 grid(CC / BN, (NN + BM - 1) / BM);
        gemm_sp_kernel<<<grid, 256, SMEM_BYTES>>>(p_at_h, p_at_l, p_wprj,
                                                  proj_b, feats, p_f2, nullptr, nullptr,
                                                  NN, CC, CC, EPI_RES);
    }

    ln_split_kernel<<<(NN + 7) / 8, 256>>>(p_f2, ln2_g, ln2_b, p_y_h, p_y_l);

    {
        dim3 grid(HIDN / BN, (NN + BM - 1) / BM);
        gemm_sp_kernel<<<grid, 256, SMEM_BYTES>>>(p_y_h, p_y_l, p_wfc1,
                                                  fc1_b, nullptr, nullptr, p_h1_h, p_h1_l,
                                                  NN, HIDN, CC, EPI_GELU);
    }

    {
        dim3 grid(CC / BN, (NN + BM - 1) / BM);
        gemm_sp_kernel<<<grid, 256, SMEM_BYTES>>>(p_h1_h, p_h1_l, p_wfc2,
                                                  fc2_b, p_f2, out, nullptr, nullptr,
                                                  NN, CC, HIDN, EPI_RES);
    }
}

// round 10
// speedup vs baseline: 2.7965x; 1.2062x over previous
#include <cuda_runtime.h>
#include <cuda_fp16.h>
#include <cstdint>
#include <math.h>

#define NN   50000
#define CC   256
#define HH   8
#define HDIM 32
#define MM   800000
#define HIDN 1024
#define QK_SCALE 0.17677669529663687f
#define LN_EPS 1e-5f

// ---------------- scratch (static device globals; no allocation) -------------
__device__ __align__(16) float g_q  [NN * CC];            // scaled q (fp32)
__device__ __align__(16) __half g_kv[NN * HH * 64];       // [n][h][k32|v32] fp16
__device__ __align__(16) float g_f2 [NN * CC];
__device__ __align__(16) __half g_xn_h[NN * CC],  g_xn_l[NN * CC];
__device__ __align__(16) __half g_at_h[NN * CC];
__device__ __align__(16) __half g_y_h [NN * CC];
__device__ __align__(16) __half g_h1_h[NN * HIDN];
__device__ __align__(16) __half g_wqkv[3*CC*CC];
__device__ __align__(16) __half g_wprj[CC*CC];
__device__ __align__(16) __half g_wfc1[HIDN*CC];
__device__ __align__(16) __half g_wfc2[CC*HIDN];
__device__ int g_cnt[NN];
__device__ int g_rowptr[NN + 1];
__device__ int g_cursor[NN];
__device__ int g_bsums[128];
__device__ int g_nbr[MM];

// ---------------- fp32 -> fp16 weight round ----------------------------------
__global__ void round_kernel(const float* __restrict__ w,
                             __half* __restrict__ wh, int n)
{
    int i = blockIdx.x * blockDim.x + threadIdx.x;
    if (i < n) wh[i] = __float2half_rn(w[i]);
}

// ---------------- CSR build --------------------------------------------------
__global__ void zero_cnt_kernel() {
    int i = blockIdx.x * blockDim.x + threadIdx.x;
    if (i < NN) g_cnt[i] = 0;
}

__global__ void count_kernel(const int* __restrict__ ei) {
    int e = blockIdx.x * blockDim.x + threadIdx.x;
    if (e < MM) atomicAdd(&g_cnt[ei[e]], 1);
}

#define SCAN_B 512
__global__ void scan1_kernel() {
    __shared__ int sh[SCAN_B];
    int tid = threadIdx.x;
    int i = blockIdx.x * SCAN_B + tid;
    int v = (i < NN) ? g_cnt[i] : 0;
    sh[tid] = v;
    __syncthreads();
    for (int off = 1; off < SCAN_B; off <<= 1) {
        int t = (tid >= off) ? sh[tid - off] : 0;
        __syncthreads();
        sh[tid] += t;
        __syncthreads();
    }
    if (i < NN) g_rowptr[i] = sh[tid] - v;
    if (tid == SCAN_B - 1) g_bsums[blockIdx.x] = sh[tid];
}

__global__ void scan2_kernel(int nb) {
    __shared__ int sh[128];
    int tid = threadIdx.x;
    int v = (tid < nb) ? g_bsums[tid] : 0;
    sh[tid] = v;
    __syncthreads();
    for (int off = 1; off < 128; off <<= 1) {
        int t = (tid >= off) ? sh[tid - off] : 0;
        __syncthreads();
        sh[tid] += t;
        __syncthreads();
    }
    if (tid < nb) g_bsums[tid] = sh[tid] - v;   // exclusive
}

__global__ void scan3_kernel() {
    int i = blockIdx.x * SCAN_B + threadIdx.x;
    if (i < NN) {
        int v = g_rowptr[i] + g_bsums[blockIdx.x];
        g_rowptr[i] = v;
        g_cursor[i] = v;
    }
    if (i == 0) g_rowptr[NN] = MM;
}

__global__ void scatter_kernel(const int* __restrict__ ei) {
    int e = blockIdx.x * blockDim.x + threadIdx.x;
    if (e < MM) {
        int n = ei[e];
        int p = atomicAdd(&g_cursor[n], 1);
        g_nbr[p] = ei[MM + e];
    }
}

// ---------------- LayerNorm -> fp16 (optionally split) ------------------------
__global__ void ln_split_kernel(const float* __restrict__ x, const float* __restrict__ g,
                                const float* __restrict__ b,
                                __half* __restrict__ yh, __half* __restrict__ yl)
{
    int row  = blockIdx.x * 8 + (threadIdx.x >> 5);
    int lane = threadIdx.x & 31;
    if (row >= NN) return;
    const float4* xr = (const float4*)(x + (size_t)row * CC);
    float4 a = xr[lane];
    float4 c = xr[lane + 32];
    float s = a.x + a.y + a.z + a.w + c.x + c.y + c.z + c.w;
    float q = a.x*a.x + a.y*a.y + a.z*a.z + a.w*a.w
            + c.x*c.x + c.y*c.y + c.z*c.z + c.w*c.w;
    #pragma unroll
    for (int o = 16; o; o >>= 1) {
        s += __shfl_xor_sync(0xffffffffu, s, o);
        q += __shfl_xor_sync(0xffffffffu, q, o);
    }
    float mean = s * (1.0f / CC);
    float var  = q * (1.0f / CC) - mean * mean;
    float rstd = rsqrtf(var + LN_EPS);
    const float4* gv = (const float4*)g;
    const float4* bv = (const float4*)b;
    float4 g1 = gv[lane], g2 = gv[lane + 32];
    float4 b1 = bv[lane], b2 = bv[lane + 32];
    float o1[4], o2[4];
    o1[0] = (a.x - mean) * rstd * g1.x + b1.x;
    o1[1] = (a.y - mean) * rstd * g1.y + b1.y;
    o1[2] = (a.z - mean) * rstd * g1.z + b1.z;
    o1[3] = (a.w - mean) * rstd * g1.w + b1.w;
    o2[0] = (c.x - mean) * rstd * g2.x + b2.x;
    o2[1] = (c.y - mean) * rstd * g2.y + b2.y;
    o2[2] = (c.z - mean) * rstd * g2.z + b2.z;
    o2[3] = (c.w - mean) * rstd * g2.w + b2.w;

    __half h1[4], h2[4];
    #pragma unroll
    for (int i = 0; i < 4; i++) {
        h1[i] = __float2half_rn(o1[i]);
        h2[i] = __float2half_rn(o2[i]);
    }
    size_t base = (size_t)row * CC;
    *(uint2*)&yh[base + lane * 4]       = *(uint2*)h1;
    *(uint2*)&yh[base + 128 + lane * 4] = *(uint2*)h2;
    if (yl) {
        __half l1[4], l2[4];
        #pragma unroll
        for (int i = 0; i < 4; i++) {
            l1[i] = __float2half_rn(o1[i] - __half2float(h1[i]));
            l2[i] = __float2half_rn(o2[i] - __half2float(h2[i]));
        }
        *(uint2*)&yl[base + lane * 4]       = *(uint2*)l1;
        *(uint2*)&yl[base + 128 + lane * 4] = *(uint2*)l2;
    }
}

// ---------------- fp16 compensated GEMM (1 or 2 mma terms) --------------------
// C[M,N] = (Ah[+Al])[M,K] @ Bh[N,K]^T + bias (+epilogue)
#define BM 128
#define BN 128
#define BK 32
#define BKP 40
#define TILE (BM * BKP)
#define ARRB (TILE * 2)           // 10240 B per array
#define STAGEB (3 * ARRB)         // 30720 B per stage (Ah, Al, Bh)

#define EPI_QKV  0
#define EPI_GELU 1
#define EPI_RES  2

__device__ __forceinline__ uint32_t smem_u32(const void* p) {
    uint32_t a;
    asm("{ .reg .u64 t; cvta.to.shared.u64 t, %1; cvt.u32.u64 %0, t; }" : "=r"(a) : "l"(p));
    return a;
}

__device__ __forceinline__ void cp16(uint32_t dst, const void* src) {
    asm volatile("cp.async.cg.shared.global [%0],[%1],16;\n" :: "r"(dst), "l"(src));
}
#define CP_COMMIT() asm volatile("cp.async.commit_group;\n")
#define CP_WAIT(n)  asm volatile("cp.async.wait_group %0;\n" :: "n"(n))

__device__ __forceinline__ void ldsm4(unsigned& r0, unsigned& r1, unsigned& r2,
                                      unsigned& r3, uint32_t addr)
{
    asm volatile("ldmatrix.sync.aligned.m8n8.x4.shared.b16 {%0,%1,%2,%3}, [%4];"
                 : "=r"(r0), "=r"(r1), "=r"(r2), "=r"(r3) : "r"(addr));
}

__device__ __forceinline__ void mma_f16(float4& d,
    unsigned a0, unsigned a1, unsigned a2, unsigned a3,
    unsigned b0, unsigned b1)
{
    asm volatile(
        "mma.sync.aligned.m16n8k16.row.col.f32.f16.f16.f32 "
        "{%0,%1,%2,%3},{%4,%5,%6,%7},{%8,%9},{%0,%1,%2,%3};"
        : "+f"(d.x), "+f"(d.y), "+f"(d.z), "+f"(d.w)
        : "r"(a0), "r"(a1), "r"(a2), "r"(a3), "r"(b0), "r"(b1));
}

__global__ __launch_bounds__(256, 2)
void gemm_sp_kernel(const __half* __restrict__ Ah, const __half* __restrict__ Al,
                    const __half* __restrict__ Bh,
                    const float* __restrict__ bias, const float* __restrict__ resid,
                    float* __restrict__ Cf, __half* __restrict__ Ch,
                    int M, int Nn, int Kk, int epi, int two_term)
{
    extern __shared__ __half smem[];
    const uint32_t sb0 = smem_u32(smem);

    const int tid  = threadIdx.x;
    const int row0 = blockIdx.y * BM;
    const int col0 = blockIdx.x * BN;
    const int warp   = tid >> 5;
    const int lane   = tid & 31;
    const int warp_m = warp >> 2;
    const int warp_n = warp & 3;
    const int g = lane >> 2;
    const int t = lane & 3;

    const int rowA = warp_m * 64 + (lane & 15);
    const int colA = 8 * (lane >> 4);
    const uint32_t offA = (uint32_t)(rowA * BKP + colA) * 2;
    const int rowB = warp_n * 32 + (lane & 7) + 8 * ((lane >> 4) & 1);
    const int colB = 8 * ((lane >> 3) & 1);
    const uint32_t offB = (uint32_t)(rowB * BKP + colB) * 2;

    const int ch0 = tid * 2;
    const int nKiter = Kk / BK;

    float4 acc[4][4];
    #pragma unroll
    for (int i = 0; i < 4; i++)
        #pragma unroll
        for (int j = 0; j < 4; j++) acc[i][j] = make_float4(0.f, 0.f, 0.f, 0.f);

    auto stage = [&](int st, int k0) {
        uint32_t base = sb0 + st * STAGEB;
        #pragma unroll
        for (int q = 0; q < 2; q++) {
            int idx = ch0 + q;
            int r    = idx >> 2;
            int c16  = idx & 3;
            int ar = row0 + r; if (ar >= M) ar = M - 1;
            size_t aoff = (size_t)ar * Kk + k0 + c16 * 8;
            int br = col0 + r;
            size_t boff = (size_t)br * Kk + k0 + c16 * 8;
            uint32_t d = (uint32_t)(r * BKP + c16 * 8) * 2;
            cp16(base + 0 * ARRB + d, Ah + aoff);
            if (two_term) cp16(base + 1 * ARRB + d, Al + aoff);
            cp16(base + 2 * ARRB + d, Bh + boff);
        }
    };

    stage(0, 0);
    CP_COMMIT();

    for (int it = 0; it < nKiter; it++) {
        if (it + 1 < nKiter) {
            stage((it + 1) & 1, (it + 1) * BK);
            CP_COMMIT();
            CP_WAIT(1);
        } else {
            CP_WAIT(0);
        }
        __syncthreads();

        const uint32_t base = sb0 + (it & 1) * STAGEB;
        const uint32_t aAh = base + offA;
        const uint32_t aAl = base + ARRB + offA;
        const uint32_t aBh = base + 2 * ARRB + offB;

        #pragma unroll
        for (int s = 0; s < 2; s++) {
            unsigned bh[4][2];
            ldsm4(bh[0][0], bh[0][1], bh[1][0], bh[1][1], aBh + s * 32);
            ldsm4(bh[2][0], bh[2][1], bh[3][0], bh[3][1], aBh + 16 * BKP * 2 + s * 32);
            #pragma unroll
            for (int mi = 0; mi < 4; mi++) {
                unsigned ah0, ah1, ah2, ah3;
                ldsm4(ah0, ah1, ah2, ah3, aAh + mi * (16 * BKP * 2) + s * 32);
                #pragma unroll
                for (int ni = 0; ni < 4; ni++)
                    mma_f16(acc[mi][ni], ah0, ah1, ah2, ah3, bh[ni][0], bh[ni][1]);
                if (two_term) {
                    unsigned al0, al1, al2, al3;
                    ldsm4(al0, al1, al2, al3, aAl + mi * (16 * BKP * 2) + s * 32);
                    #pragma unroll
                    for (int ni = 0; ni < 4; ni++)
                        mma_f16(acc[mi][ni], al0, al1, al2, al3, bh[ni][0], bh[ni][1]);
                }
            }
        }
        __syncthreads();
    }

    const int region = col0 >> 8;     // for EPI_QKV: 0=q, 1=k, 2=v
    #pragma unroll
    for (int mi = 0; mi < 4; mi++) {
        int r = row0 + warp_m * 64 + mi * 16 + g;
        #pragma unroll
        for (int ni = 0; ni < 4; ni++) {
            int c = col0 + warp_n * 32 + ni * 8 + 2 * t;
            float bx = bias[c], by = bias[c + 1];
            float4 d = acc[mi][ni];
            float v0 = d.x + bx, v1 = d.y + by;
            float v2 = d.z + bx, v3 = d.w + by;
            if (epi == EPI_QKV) {
                int local = c & 255;
                if (region == 0) {
                    if (r < M) {
                        g_q[(size_t)r * CC + local]     = v0 * QK_SCALE;
                        g_q[(size_t)r * CC + local + 1] = v1 * QK_SCALE;
                    }
                    if (r + 8 < M) {
                        g_q[(size_t)(r + 8) * CC + local]     = v2 * QK_SCALE;
                        g_q[(size_t)(r + 8) * CC + local + 1] = v3 * QK_SCALE;
                    }
                } else {
                    int h  = local >> 5;
                    int dd = (local & 31) + (region == 2 ? 32 : 0);
                    if (r < M) {
                        __half2 p; p.x = __float2half_rn(v0); p.y = __float2half_rn(v1);
                        *(__half2*)&g_kv[((size_t)r * HH + h) * 64 + dd] = p;
                    }
                    if (r + 8 < M) {
                        __half2 p; p.x = __float2half_rn(v2); p.y = __float2half_rn(v3);
                        *(__half2*)&g_kv[((size_t)(r + 8) * HH + h) * 64 + dd] = p;
                    }
                }
            } else if (epi == EPI_GELU) {
                v0 = 0.5f * v0 * (1.0f + erff(v0 * 0.70710678f));
                v1 = 0.5f * v1 * (1.0f + erff(v1 * 0.70710678f));
                v2 = 0.5f * v2 * (1.0f + erff(v2 * 0.70710678f));
                v3 = 0.5f * v3 * (1.0f + erff(v3 * 0.70710678f));
                if (r < M) {
                    size_t o = (size_t)r * Nn + c;
                    __half2 p; p.x = __float2half_rn(v0); p.y = __float2half_rn(v1);
                    *(__half2*)&Ch[o] = p;
                }
                if (r + 8 < M) {
                    size_t o = (size_t)(r + 8) * Nn + c;
                    __half2 p; p.x = __float2half_rn(v2); p.y = __float2half_rn(v3);
                    *(__half2*)&Ch[o] = p;
                }
            } else {
                if (r < M) {
                    size_t o = (size_t)r * Nn + c;
                    float r0 = resid[o], r1 = resid[o + 1];
                    Cf[o] = v0 + r0; Cf[o + 1] = v1 + r1;
                }
                if (r + 8 < M) {
                    size_t o = (size_t)(r + 8) * Nn + c;
                    float r2 = resid[o], r3 = resid[o + 1];
                    Cf[o] = v2 + r2; Cf[o + 1] = v3 + r3;
                }
            }
        }
    }
}

// ---------------- Edge-softmax attention (warp/(node,head), 4-edge batch) ----
__global__ void attn_kernel(__half* __restrict__ oh)
{
    int n    = blockIdx.x;
    int h    = threadIdx.x >> 5;
    int lane = threadIdx.x & 31;
    float q = g_q[(size_t)n * CC + h * HDIM + lane];   // pre-scaled
    int s = g_rowptr[n];
    int e = g_rowptr[n + 1];
    float m = -INFINITY, l = 0.0f, acc = 0.0f;

    int i = s;
    for (; i + 3 < e; i += 4) {
        int j[4];
        float kk[4], vv[4], d[4];
        #pragma unroll
        for (int u = 0; u < 4; u++) j[u] = g_nbr[i + u];
        #pragma unroll
        for (int u = 0; u < 4; u++) {
            const __half* b = g_kv + ((size_t)j[u] * HH + h) * 64;
            kk[u] = __half2float(b[lane]);
            vv[u] = __half2float(b[32 + lane]);
        }
        #pragma unroll
        for (int u = 0; u < 4; u++) d[u] = q * kk[u];
        #pragma unroll
        for (int o = 16; o; o >>= 1) {
            #pragma unroll
            for (int u = 0; u < 4; u++)
                d[u] += __shfl_xor_sync(0xffffffffu, d[u], o);
        }
        float mb = fmaxf(fmaxf(d[0], d[1]), fmaxf(d[2], d[3]));
        float mn = fmaxf(m, mb);
        float sc = __expf(m - mn);
        float p0 = __expf(d[0] - mn);
        float p1 = __expf(d[1] - mn);
        float p2 = __expf(d[2] - mn);
        float p3 = __expf(d[3] - mn);
        l   = l * sc + (p0 + p1 + p2 + p3);
        acc = acc * sc + p0 * vv[0] + p1 * vv[1] + p2 * vv[2] + p3 * vv[3];
        m = mn;
    }
    for (; i < e; i++) {
        int j = g_nbr[i];
        const __half* b = g_kv + ((size_t)j * HH + h) * 64;
        float kk = __half2float(b[lane]);
        float vv = __half2float(b[32 + lane]);
        float d = q * kk;
        #pragma unroll
        for (int o = 16; o; o >>= 1) d += __shfl_xor_sync(0xffffffffu, d, o);
        float mn = fmaxf(m, d);
        float sc = __expf(m - mn);
        float p  = __expf(d - mn);
        l   = l * sc + p;
        acc = acc * sc + p * vv;
        m = mn;
    }
    float o = (l > 0.0f) ? acc / l : 0.0f;
    oh[(size_t)n * CC + h * HDIM + lane] = __float2half_rn(o);
}

// ---------------- host launcher ---------------------------------------------
extern "C" void kernel_launch(void* const* d_in, const int* in_sizes, int n_in,
                              void* d_out, int out_size)
{
    const float* feats  = (const float*)d_in[0];
    const int*   ei     = (const int*)d_in[2];
    const float* ln1_g  = (const float*)d_in[3];
    const float* ln1_b  = (const float*)d_in[4];
    const float* qkv_w  = (const float*)d_in[5];
    const float* qkv_b  = (const float*)d_in[6];
    const float* proj_w = (const float*)d_in[7];
    const float* proj_b = (const float*)d_in[8];
    const float* ln2_g  = (const float*)d_in[9];
    const float* ln2_b  = (const float*)d_in[10];
    const float* fc1_w  = (const float*)d_in[11];
    const float* fc1_b  = (const float*)d_in[12];
    const float* fc2_w  = (const float*)d_in[13];
    const float* fc2_b  = (const float*)d_in[14];
    float* out = (float*)d_out;

    float *p_f2;
    cudaGetSymbolAddress((void**)&p_f2,  g_f2);
    __half *p_xn_h, *p_xn_l, *p_at_h, *p_y_h, *p_h1_h;
    cudaGetSymbolAddress((void**)&p_xn_h, g_xn_h);
    cudaGetSymbolAddress((void**)&p_xn_l, g_xn_l);
    cudaGetSymbolAddress((void**)&p_at_h, g_at_h);
    cudaGetSymbolAddress((void**)&p_y_h,  g_y_h);
    cudaGetSymbolAddress((void**)&p_h1_h, g_h1_h);
    __half *p_wqkv, *p_wprj, *p_wfc1, *p_wfc2;
    cudaGetSymbolAddress((void**)&p_wqkv, g_wqkv);
    cudaGetSymbolAddress((void**)&p_wprj, g_wprj);
    cudaGetSymbolAddress((void**)&p_wfc1, g_wfc1);
    cudaGetSymbolAddress((void**)&p_wfc2, g_wfc2);

    const int SMEM_BYTES = 2 * STAGEB;   // 61440
    static int smem_set = 0;
    if (!smem_set) {
        cudaFuncSetAttribute(gemm_sp_kernel,
                             cudaFuncAttributeMaxDynamicSharedMemorySize, SMEM_BYTES);
        smem_set = 1;
    }

    const int nscan = (NN + SCAN_B - 1) / SCAN_B;

    round_kernel<<<(3*CC*CC + 255)/256, 256>>>(qkv_w, p_wqkv, 3*CC*CC);
    round_kernel<<<(CC*CC   + 255)/256, 256>>>(proj_w, p_wprj, CC*CC);
    round_kernel<<<(HIDN*CC + 255)/256, 256>>>(fc1_w, p_wfc1, HIDN*CC);
    round_kernel<<<(CC*HIDN + 255)/256, 256>>>(fc2_w, p_wfc2, CC*HIDN);

    zero_cnt_kernel<<<(NN + 255) / 256, 256>>>();
    count_kernel<<<(MM + 255) / 256, 256>>>(ei);
    scan1_kernel<<<nscan, SCAN_B>>>();
    scan2_kernel<<<1, 128>>>(nscan);
    scan3_kernel<<<nscan, SCAN_B>>>();
    scatter_kernel<<<(MM + 255) / 256, 256>>>(ei);

    // LN1 -> split fp16 (2-term qkv GEMM)
    ln_split_kernel<<<(NN + 7) / 8, 256>>>(feats, ln1_g, ln1_b, p_xn_h, p_xn_l);

    // qkv: 2-term; writes g_q (scaled fp32) + g_kv (fp16 packed)
    {
        dim3 grid(768 / BN, (NN + BM - 1) / BM);
        gemm_sp_kernel<<<grid, 256, SMEM_BYTES>>>(p_xn_h, p_xn_l, p_wqkv,
                                                  qkv_b, nullptr, nullptr, nullptr,
                                                  NN, 768, CC, EPI_QKV, 1);
    }

    attn_kernel<<<NN, 256>>>(p_at_h);

    // proj: 1-term
    {
        dim3 grid(CC / BN, (NN + BM - 1) / BM);
        gemm_sp_kernel<<<grid, 256, SMEM_BYTES>>>(p_at_h, nullptr, p_wprj,
                                                  proj_b, feats, p_f2, nullptr,
                                                  NN, CC, CC, EPI_RES, 0);
    }

    // LN2 -> fp16 (hi only)
    ln_split_kernel<<<(NN + 7) / 8, 256>>>(p_f2, ln2_g, ln2_b, p_y_h, nullptr);

    // fc1 + gelu: 1-term
    {
        dim3 grid(HIDN / BN, (NN + BM - 1) / BM);
        gemm_sp_kernel<<<grid, 256, SMEM_BYTES>>>(p_y_h, nullptr, p_wfc1,
                                                  fc1_b, nullptr, nullptr, p_h1_h,
                                                  NN, HIDN, CC, EPI_GELU, 0);
    }

    // fc2 + residual: 1-term
    {
        dim3 grid(CC / BN, (NN + BM - 1) / BM);
        gemm_sp_kernel<<<grid, 256, SMEM_BYTES>>>(p_h1_h, nullptr, p_wfc2,
                                                  fc2_b, p_f2, out, nullptr,
                                                  NN, CC, HIDN, EPI_RES, 0);
    }
}

// round 11
// speedup vs baseline: 2.8019x; 1.0019x over previous
#include <cuda_runtime.h>
#include <cuda_fp16.h>
#include <cstdint>
#include <math.h>

#define NN   50000
#define CC   256
#define HH   8
#define HDIM 32
#define MM   800000
#define HIDN 1024
#define QK_SCALE 0.17677669529663687f
#define LN_EPS 1e-5f

// ---------------- scratch (static device globals; no allocation) -------------
__device__ __align__(16) float g_q  [NN * CC];            // scaled q (fp32)
__device__ __align__(16) __half g_kv[NN * HH * 64];       // [n][h][k32|v32] fp16
__device__ __align__(16) float g_f2 [NN * CC];
__device__ __align__(16) __half g_xn_h[NN * CC],  g_xn_l[NN * CC];
__device__ __align__(16) __half g_at_h[NN * CC];
__device__ __align__(16) __half g_y_h [NN * CC];
__device__ __align__(16) __half g_h1_h[NN * HIDN];
__device__ __align__(16) __half g_wqkv[3*CC*CC];
__device__ __align__(16) __half g_wprj[CC*CC];
__device__ __align__(16) __half g_wfc1[HIDN*CC];
__device__ __align__(16) __half g_wfc2[CC*HIDN];
__device__ int g_cnt[NN];
__device__ int g_rowptr[NN + 1];
__device__ int g_cursor[NN];
__device__ int g_bsums[128];
__device__ int g_nbr[MM];

// ---------------- fp32 -> fp16 weight round ----------------------------------
__global__ void round_kernel(const float* __restrict__ w,
                             __half* __restrict__ wh, int n)
{
    int i = blockIdx.x * blockDim.x + threadIdx.x;
    if (i < n) wh[i] = __float2half_rn(w[i]);
}

// ---------------- CSR build --------------------------------------------------
__global__ void zero_cnt_kernel() {
    int i = blockIdx.x * blockDim.x + threadIdx.x;
    if (i < NN) g_cnt[i] = 0;
}

__global__ void count_kernel(const int* __restrict__ ei) {
    int e = blockIdx.x * blockDim.x + threadIdx.x;
    if (e < MM) atomicAdd(&g_cnt[ei[e]], 1);
}

#define SCAN_B 512
__global__ void scan1_kernel() {
    __shared__ int sh[SCAN_B];
    int tid = threadIdx.x;
    int i = blockIdx.x * SCAN_B + tid;
    int v = (i < NN) ? g_cnt[i] : 0;
    sh[tid] = v;
    __syncthreads();
    for (int off = 1; off < SCAN_B; off <<= 1) {
        int t = (tid >= off) ? sh[tid - off] : 0;
        __syncthreads();
        sh[tid] += t;
        __syncthreads();
    }
    if (i < NN) g_rowptr[i] = sh[tid] - v;
    if (tid == SCAN_B - 1) g_bsums[blockIdx.x] = sh[tid];
}

__global__ void scan2_kernel(int nb) {
    __shared__ int sh[128];
    int tid = threadIdx.x;
    int v = (tid < nb) ? g_bsums[tid] : 0;
    sh[tid] = v;
    __syncthreads();
    for (int off = 1; off < 128; off <<= 1) {
        int t = (tid >= off) ? sh[tid - off] : 0;
        __syncthreads();
        sh[tid] += t;
        __syncthreads();
    }
    if (tid < nb) g_bsums[tid] = sh[tid] - v;   // exclusive
}

__global__ void scan3_kernel() {
    int i = blockIdx.x * SCAN_B + threadIdx.x;
    if (i < NN) {
        int v = g_rowptr[i] + g_bsums[blockIdx.x];
        g_rowptr[i] = v;
        g_cursor[i] = v;
    }
    if (i == 0) g_rowptr[NN] = MM;
}

__global__ void scatter_kernel(const int* __restrict__ ei) {
    int e = blockIdx.x * blockDim.x + threadIdx.x;
    if (e < MM) {
        int n = ei[e];
        int p = atomicAdd(&g_cursor[n], 1);
        g_nbr[p] = ei[MM + e];
    }
}

// ---------------- LayerNorm -> fp16 (optionally split) ------------------------
__global__ void ln_split_kernel(const float* __restrict__ x, const float* __restrict__ g,
                                const float* __restrict__ b,
                                __half* __restrict__ yh, __half* __restrict__ yl)
{
    int row  = blockIdx.x * 8 + (threadIdx.x >> 5);
    int lane = threadIdx.x & 31;
    if (row >= NN) return;
    const float4* xr = (const float4*)(x + (size_t)row * CC);
    float4 a = xr[lane];
    float4 c = xr[lane + 32];
    float s = a.x + a.y + a.z + a.w + c.x + c.y + c.z + c.w;
    float q = a.x*a.x + a.y*a.y + a.z*a.z + a.w*a.w
            + c.x*c.x + c.y*c.y + c.z*c.z + c.w*c.w;
    #pragma unroll
    for (int o = 16; o; o >>= 1) {
        s += __shfl_xor_sync(0xffffffffu, s, o);
        q += __shfl_xor_sync(0xffffffffu, q, o);
    }
    float mean = s * (1.0f / CC);
    float var  = q * (1.0f / CC) - mean * mean;
    float rstd = rsqrtf(var + LN_EPS);
    const float4* gv = (const float4*)g;
    const float4* bv = (const float4*)b;
    float4 g1 = gv[lane], g2 = gv[lane + 32];
    float4 b1 = bv[lane], b2 = bv[lane + 32];
    float o1[4], o2[4];
    o1[0] = (a.x - mean) * rstd * g1.x + b1.x;
    o1[1] = (a.y - mean) * rstd * g1.y + b1.y;
    o1[2] = (a.z - mean) * rstd * g1.z + b1.z;
    o1[3] = (a.w - mean) * rstd * g1.w + b1.w;
    o2[0] = (c.x - mean) * rstd * g2.x + b2.x;
    o2[1] = (c.y - mean) * rstd * g2.y + b2.y;
    o2[2] = (c.z - mean) * rstd * g2.z + b2.z;
    o2[3] = (c.w - mean) * rstd * g2.w + b2.w;

    __half h1[4], h2[4];
    #pragma unroll
    for (int i = 0; i < 4; i++) {
        h1[i] = __float2half_rn(o1[i]);
        h2[i] = __float2half_rn(o2[i]);
    }
    size_t base = (size_t)row * CC;
    *(uint2*)&yh[base + lane * 4]       = *(uint2*)h1;
    *(uint2*)&yh[base + 128 + lane * 4] = *(uint2*)h2;
    if (yl) {
        __half l1[4], l2[4];
        #pragma unroll
        for (int i = 0; i < 4; i++) {
            l1[i] = __float2half_rn(o1[i] - __half2float(h1[i]));
            l2[i] = __float2half_rn(o2[i] - __half2float(h2[i]));
        }
        *(uint2*)&yl[base + lane * 4]       = *(uint2*)l1;
        *(uint2*)&yl[base + 128 + lane * 4] = *(uint2*)l2;
    }
}

// ---------------- fp16 compensated GEMM (1 or 2 mma terms) --------------------
#define BM 128
#define BN 128
#define BK 32
#define BKP 40
#define TILE (BM * BKP)
#define ARRB (TILE * 2)
#define STAGEB (3 * ARRB)

#define EPI_QKV  0
#define EPI_GELU 1
#define EPI_RES  2

__device__ __forceinline__ uint32_t smem_u32(const void* p) {
    uint32_t a;
    asm("{ .reg .u64 t; cvta.to.shared.u64 t, %1; cvt.u32.u64 %0, t; }" : "=r"(a) : "l"(p));
    return a;
}

__device__ __forceinline__ void cp16(uint32_t dst, const void* src) {
    asm volatile("cp.async.cg.shared.global [%0],[%1],16;\n" :: "r"(dst), "l"(src));
}
#define CP_COMMIT() asm volatile("cp.async.commit_group;\n")
#define CP_WAIT(n)  asm volatile("cp.async.wait_group %0;\n" :: "n"(n))

__device__ __forceinline__ void ldsm4(unsigned& r0, unsigned& r1, unsigned& r2,
                                      unsigned& r3, uint32_t addr)
{
    asm volatile("ldmatrix.sync.aligned.m8n8.x4.shared.b16 {%0,%1,%2,%3}, [%4];"
                 : "=r"(r0), "=r"(r1), "=r"(r2), "=r"(r3) : "r"(addr));
}

__device__ __forceinline__ void mma_f16(float4& d,
    unsigned a0, unsigned a1, unsigned a2, unsigned a3,
    unsigned b0, unsigned b1)
{
    asm volatile(
        "mma.sync.aligned.m16n8k16.row.col.f32.f16.f16.f32 "
        "{%0,%1,%2,%3},{%4,%5,%6,%7},{%8,%9},{%0,%1,%2,%3};"
        : "+f"(d.x), "+f"(d.y), "+f"(d.z), "+f"(d.w)
        : "r"(a0), "r"(a1), "r"(a2), "r"(a3), "r"(b0), "r"(b1));
}

__global__ __launch_bounds__(256, 2)
void gemm_sp_kernel(const __half* __restrict__ Ah, const __half* __restrict__ Al,
                    const __half* __restrict__ Bh,
                    const float* __restrict__ bias, const float* __restrict__ resid,
                    float* __restrict__ Cf, __half* __restrict__ Ch,
                    int M, int Nn, int Kk, int epi, int two_term, int col_base)
{
    extern __shared__ __half smem[];
    const uint32_t sb0 = smem_u32(smem);

    const int tid  = threadIdx.x;
    const int row0 = blockIdx.y * BM;
    const int col0 = col_base + blockIdx.x * BN;
    const int warp   = tid >> 5;
    const int lane   = tid & 31;
    const int warp_m = warp >> 2;
    const int warp_n = warp & 3;
    const int g = lane >> 2;
    const int t = lane & 3;

    const int rowA = warp_m * 64 + (lane & 15);
    const int colA = 8 * (lane >> 4);
    const uint32_t offA = (uint32_t)(rowA * BKP + colA) * 2;
    const int rowB = warp_n * 32 + (lane & 7) + 8 * ((lane >> 4) & 1);
    const int colB = 8 * ((lane >> 3) & 1);
    const uint32_t offB = (uint32_t)(rowB * BKP + colB) * 2;

    const int ch0 = tid * 2;
    const int nKiter = Kk / BK;

    float4 acc[4][4];
    #pragma unroll
    for (int i = 0; i < 4; i++)
        #pragma unroll
        for (int j = 0; j < 4; j++) acc[i][j] = make_float4(0.f, 0.f, 0.f, 0.f);

    auto stage = [&](int st, int k0) {
        uint32_t base = sb0 + st * STAGEB;
        #pragma unroll
        for (int q = 0; q < 2; q++) {
            int idx = ch0 + q;
            int r    = idx >> 2;
            int c16  = idx & 3;
            int ar = row0 + r; if (ar >= M) ar = M - 1;
            size_t aoff = (size_t)ar * Kk + k0 + c16 * 8;
            int br = col0 + r;
            size_t boff = (size_t)br * Kk + k0 + c16 * 8;
            uint32_t d = (uint32_t)(r * BKP + c16 * 8) * 2;
            cp16(base + 0 * ARRB + d, Ah + aoff);
            if (two_term) cp16(base + 1 * ARRB + d, Al + aoff);
            cp16(base + 2 * ARRB + d, Bh + boff);
        }
    };

    stage(0, 0);
    CP_COMMIT();

    for (int it = 0; it < nKiter; it++) {
        if (it + 1 < nKiter) {
            stage((it + 1) & 1, (it + 1) * BK);
            CP_COMMIT();
            CP_WAIT(1);
        } else {
            CP_WAIT(0);
        }
        __syncthreads();

        const uint32_t base = sb0 + (it & 1) * STAGEB;
        const uint32_t aAh = base + offA;
        const uint32_t aAl = base + ARRB + offA;
        const uint32_t aBh = base + 2 * ARRB + offB;

        #pragma unroll
        for (int s = 0; s < 2; s++) {
            unsigned bh[4][2];
            ldsm4(bh[0][0], bh[0][1], bh[1][0], bh[1][1], aBh + s * 32);
            ldsm4(bh[2][0], bh[2][1], bh[3][0], bh[3][1], aBh + 16 * BKP * 2 + s * 32);
            #pragma unroll
            for (int mi = 0; mi < 4; mi++) {
                unsigned ah0, ah1, ah2, ah3;
                ldsm4(ah0, ah1, ah2, ah3, aAh + mi * (16 * BKP * 2) + s * 32);
                #pragma unroll
                for (int ni = 0; ni < 4; ni++)
                    mma_f16(acc[mi][ni], ah0, ah1, ah2, ah3, bh[ni][0], bh[ni][1]);
                if (two_term) {
                    unsigned al0, al1, al2, al3;
                    ldsm4(al0, al1, al2, al3, aAl + mi * (16 * BKP * 2) + s * 32);
                    #pragma unroll
                    for (int ni = 0; ni < 4; ni++)
                        mma_f16(acc[mi][ni], al0, al1, al2, al3, bh[ni][0], bh[ni][1]);
                }
            }
        }
        __syncthreads();
    }

    const int region = col0 >> 8;     // for EPI_QKV: 0=q, 1=k, 2=v
    #pragma unroll
    for (int mi = 0; mi < 4; mi++) {
        int r = row0 + warp_m * 64 + mi * 16 + g;
        #pragma unroll
        for (int ni = 0; ni < 4; ni++) {
            int c = col0 + warp_n * 32 + ni * 8 + 2 * t;
            float bx = bias[c], by = bias[c + 1];
            float4 d = acc[mi][ni];
            float v0 = d.x + bx, v1 = d.y + by;
            float v2 = d.z + bx, v3 = d.w + by;
            if (epi == EPI_QKV) {
                int local = c & 255;
                if (region == 0) {
                    if (r < M) {
                        g_q[(size_t)r * CC + local]     = v0 * QK_SCALE;
                        g_q[(size_t)r * CC + local + 1] = v1 * QK_SCALE;
                    }
                    if (r + 8 < M) {
                        g_q[(size_t)(r + 8) * CC + local]     = v2 * QK_SCALE;
                        g_q[(size_t)(r + 8) * CC + local + 1] = v3 * QK_SCALE;
                    }
                } else {
                    int h  = local >> 5;
                    int dd = (local & 31) + (region == 2 ? 32 : 0);
                    if (r < M) {
                        __half2 p; p.x = __float2half_rn(v0); p.y = __float2half_rn(v1);
                        *(__half2*)&g_kv[((size_t)r * HH + h) * 64 + dd] = p;
                    }
                    if (r + 8 < M) {
                        __half2 p; p.x = __float2half_rn(v2); p.y = __float2half_rn(v3);
                        *(__half2*)&g_kv[((size_t)(r + 8) * HH + h) * 64 + dd] = p;
                    }
                }
            } else if (epi == EPI_GELU) {
                v0 = 0.5f * v0 * (1.0f + erff(v0 * 0.70710678f));
                v1 = 0.5f * v1 * (1.0f + erff(v1 * 0.70710678f));
                v2 = 0.5f * v2 * (1.0f + erff(v2 * 0.70710678f));
                v3 = 0.5f * v3 * (1.0f + erff(v3 * 0.70710678f));
                if (r < M) {
                    size_t o = (size_t)r * Nn + c;
                    __half2 p; p.x = __float2half_rn(v0); p.y = __float2half_rn(v1);
                    *(__half2*)&Ch[o] = p;
                }
                if (r + 8 < M) {
                    size_t o = (size_t)(r + 8) * Nn + c;
                    __half2 p; p.x = __float2half_rn(v2); p.y = __float2half_rn(v3);
                    *(__half2*)&Ch[o] = p;
                }
            } else {
                if (r < M) {
                    size_t o = (size_t)r * Nn + c;
                    float r0 = resid[o], r1 = resid[o + 1];
                    Cf[o] = v0 + r0; Cf[o + 1] = v1 + r1;
                }
                if (r + 8 < M) {
                    size_t o = (size_t)(r + 8) * Nn + c;
                    float r2 = resid[o], r3 = resid[o + 1];
                    Cf[o] = v2 + r2; Cf[o + 1] = v3 + r3;
                }
            }
        }
    }
}

// ---------------- Edge-softmax attention -------------------------------------
// warp/(node,head); one coalesced 128B LDG.32 per edge: lane i loads halves
// (2i, 2i+1) of the k|v line -> lanes 0-15 hold k pairs, 16-31 hold v pairs.
__global__ void attn_kernel(__half* __restrict__ oh)
{
    int n    = blockIdx.x;
    int h    = threadIdx.x >> 5;
    int lane = threadIdx.x & 31;
    float2 q2 = make_float2(0.f, 0.f);
    if (lane < 16)
        q2 = *(const float2*)&g_q[(size_t)n * CC + h * HDIM + 2 * lane];
    int s = g_rowptr[n];
    int e = g_rowptr[n + 1];
    float m = -INFINITY, l = 0.0f;
    float2 acc = make_float2(0.f, 0.f);

    int i = s;
    for (; i + 3 < e; i += 4) {
        int j[4];
        float2 fv[4];
        float d[4];
        #pragma unroll
        for (int u = 0; u < 4; u++) j[u] = g_nbr[i + u];
        #pragma unroll
        for (int u = 0; u < 4; u++) {
            __half2 hv = *(const __half2*)&g_kv[((size_t)j[u] * HH + h) * 64 + 2 * lane];
            fv[u] = __half22float2(hv);
        }
        #pragma unroll
        for (int u = 0; u < 4; u++)
            d[u] = (lane < 16) ? (q2.x * fv[u].x + q2.y * fv[u].y) : 0.0f;
        #pragma unroll
        for (int o = 16; o; o >>= 1) {
            #pragma unroll
            for (int u = 0; u < 4; u++)
                d[u] += __shfl_xor_sync(0xffffffffu, d[u], o);
        }
        float mb = fmaxf(fmaxf(d[0], d[1]), fmaxf(d[2], d[3]));
        float mn = fmaxf(m, mb);
        float sc = __expf(m - mn);
        float p0 = __expf(d[0] - mn);
        float p1 = __expf(d[1] - mn);
        float p2 = __expf(d[2] - mn);
        float p3 = __expf(d[3] - mn);
        l = l * sc + (p0 + p1 + p2 + p3);
        acc.x = acc.x * sc + p0 * fv[0].x + p1 * fv[1].x + p2 * fv[2].x + p3 * fv[3].x;
        acc.y = acc.y * sc + p0 * fv[0].y + p1 * fv[1].y + p2 * fv[2].y + p3 * fv[3].y;
        m = mn;
    }
    for (; i < e; i++) {
        int j = g_nbr[i];
        __half2 hv = *(const __half2*)&g_kv[((size_t)j * HH + h) * 64 + 2 * lane];
        float2 f = __half22float2(hv);
        float d = (lane < 16) ? (q2.x * f.x + q2.y * f.y) : 0.0f;
        #pragma unroll
        for (int o = 16; o; o >>= 1) d += __shfl_xor_sync(0xffffffffu, d, o);
        float mn = fmaxf(m, d);
        float sc = __expf(m - mn);
        float p  = __expf(d - mn);
        l = l * sc + p;
        acc.x = acc.x * sc + p * f.x;
        acc.y = acc.y * sc + p * f.y;
        m = mn;
    }
    if (lane >= 16) {
        float inv = (l > 0.0f) ? (1.0f / l) : 0.0f;
        __half2 p;
        p.x = __float2half_rn(acc.x * inv);
        p.y = __float2half_rn(acc.y * inv);
        *(__half2*)&oh[(size_t)n * CC + h * HDIM + 2 * (lane - 16)] = p;
    }
}

// ---------------- host launcher ---------------------------------------------
extern "C" void kernel_launch(void* const* d_in, const int* in_sizes, int n_in,
                              void* d_out, int out_size)
{
    const float* feats  = (const float*)d_in[0];
    const int*   ei     = (const int*)d_in[2];
    const float* ln1_g  = (const float*)d_in[3];
    const float* ln1_b  = (const float*)d_in[4];
    const float* qkv_w  = (const float*)d_in[5];
    const float* qkv_b  = (const float*)d_in[6];
    const float* proj_w = (const float*)d_in[7];
    const float* proj_b = (const float*)d_in[8];
    const float* ln2_g  = (const float*)d_in[9];
    const float* ln2_b  = (const float*)d_in[10];
    const float* fc1_w  = (const float*)d_in[11];
    const float* fc1_b  = (const float*)d_in[12];
    const float* fc2_w  = (const float*)d_in[13];
    const float* fc2_b  = (const float*)d_in[14];
    float* out = (float*)d_out;

    float *p_f2;
    cudaGetSymbolAddress((void**)&p_f2,  g_f2);
    __half *p_xn_h, *p_xn_l, *p_at_h, *p_y_h, *p_h1_h;
    cudaGetSymbolAddress((void**)&p_xn_h, g_xn_h);
    cudaGetSymbolAddress((void**)&p_xn_l, g_xn_l);
    cudaGetSymbolAddress((void**)&p_at_h, g_at_h);
    cudaGetSymbolAddress((void**)&p_y_h,  g_y_h);
    cudaGetSymbolAddress((void**)&p_h1_h, g_h1_h);
    __half *p_wqkv, *p_wprj, *p_wfc1, *p_wfc2;
    cudaGetSymbolAddress((void**)&p_wqkv, g_wqkv);
    cudaGetSymbolAddress((void**)&p_wprj, g_wprj);
    cudaGetSymbolAddress((void**)&p_wfc1, g_wfc1);
    cudaGetSymbolAddress((void**)&p_wfc2, g_wfc2);

    const int SMEM_BYTES = 2 * STAGEB;   // 61440
    static int smem_set = 0;
    if (!smem_set) {
        cudaFuncSetAttribute(gemm_sp_kernel,
                             cudaFuncAttributeMaxDynamicSharedMemorySize, SMEM_BYTES);
        smem_set = 1;
    }

    const int nscan = (NN + SCAN_B - 1) / SCAN_B;
    const int MROWS = (NN + BM - 1) / BM;

    round_kernel<<<(3*CC*CC + 255)/256, 256>>>(qkv_w, p_wqkv, 3*CC*CC);
    round_kernel<<<(CC*CC   + 255)/256, 256>>>(proj_w, p_wprj, CC*CC);
    round_kernel<<<(HIDN*CC + 255)/256, 256>>>(fc1_w, p_wfc1, HIDN*CC);
    round_kernel<<<(CC*HIDN + 255)/256, 256>>>(fc2_w, p_wfc2, CC*HIDN);

    zero_cnt_kernel<<<(NN + 255) / 256, 256>>>();
    count_kernel<<<(MM + 255) / 256, 256>>>(ei);
    scan1_kernel<<<nscan, SCAN_B>>>();
    scan2_kernel<<<1, 128>>>(nscan);
    scan3_kernel<<<nscan, SCAN_B>>>();
    scatter_kernel<<<(MM + 255) / 256, 256>>>(ei);

    // LN1 -> split fp16
    ln_split_kernel<<<(NN + 7) / 8, 256>>>(feats, ln1_g, ln1_b, p_xn_h, p_xn_l);

    // qkv, q columns (0-255): 2-term
    {
        dim3 grid(2, MROWS);
        gemm_sp_kernel<<<grid, 256, SMEM_BYTES>>>(p_xn_h, p_xn_l, p_wqkv,
                                                  qkv_b, nullptr, nullptr, nullptr,
                                                  NN, 768, CC, EPI_QKV, 1, 0);
    }
    // qkv, k/v columns (256-767): 1-term (fp16 output rounding dominates)
    {
        dim3 grid(4, MROWS);
        gemm_sp_kernel<<<grid, 256, SMEM_BYTES>>>(p_xn_h, nullptr, p_wqkv,
                                                  qkv_b, nullptr, nullptr, nullptr,
                                                  NN, 768, CC, EPI_QKV, 0, 256);
    }

    attn_kernel<<<NN, 256>>>(p_at_h);

    // proj: 1-term
    {
        dim3 grid(CC / BN, MROWS);
        gemm_sp_kernel<<<grid, 256, SMEM_BYTES>>>(p_at_h, nullptr, p_wprj,
                                                  proj_b, feats, p_f2, nullptr,
                                                  NN, CC, CC, EPI_RES, 0, 0);
    }

    // LN2 -> fp16 (hi only)
    ln_split_kernel<<<(NN + 7) / 8, 256>>>(p_f2, ln2_g, ln2_b, p_y_h, nullptr);

    // fc1 + gelu: 1-term
    {
        dim3 grid(HIDN / BN, MROWS);
        gemm_sp_kernel<<<grid, 256, SMEM_BYTES>>>(p_y_h, nullptr, p_wfc1,
                                                  fc1_b, nullptr, nullptr, p_h1_h,
                                                  NN, HIDN, CC, EPI_GELU, 0, 0);
    }

    // fc2 + residual: 1-term
    {
        dim3 grid(CC / BN, MROWS);
        gemm_sp_kernel<<<grid, 256, SMEM_BYTES>>>(p_h1_h, nullptr, p_wfc2,
                                                  fc2_b, p_f2, out, nullptr,
                                                  NN, CC, HIDN, EPI_RES, 0, 0);
    }
}

// round 12
// speedup vs baseline: 2.8601x; 1.0207x over previous
#include <cuda_runtime.h>
#include <cuda_fp16.h>
#include <cstdint>
#include <math.h>

#define NN   50000
#define CC   256
#define HH   8
#define HDIM 32
#define MM   800000
#define HIDN 1024
#define QK_SCALE 0.17677669529663687f
#define LN_EPS 1e-5f

// ---------------- scratch (static device globals; no allocation) -------------
__device__ __align__(16) float g_q  [NN * CC];            // scaled q (fp32)
__device__ __align__(16) __half g_kv[NN * HH * 64];       // [n][h][k32|v32] fp16
__device__ __align__(16) float g_f2 [NN * CC];
__device__ __align__(16) __half g_xn_h[NN * CC],  g_xn_l[NN * CC];
__device__ __align__(16) __half g_at_h[NN * CC];
__device__ __align__(16) __half g_y_h [NN * CC];
__device__ __align__(16) __half g_h1_h[NN * HIDN];
__device__ __align__(16) __half g_wqkv[3*CC*CC];
__device__ __align__(16) __half g_wprj[CC*CC];
__device__ __align__(16) __half g_wfc1[HIDN*CC];
__device__ __align__(16) __half g_wfc2[CC*HIDN];
__device__ int g_cnt[NN];
__device__ int g_rowptr[NN + 1];
__device__ int g_cursor[NN];
__device__ int g_bsums[128];
__device__ int g_nbr[MM];

// ---------------- fp32 -> fp16 weight round ----------------------------------
__global__ void round_kernel(const float* __restrict__ w,
                             __half* __restrict__ wh, int n)
{
    int i = blockIdx.x * blockDim.x + threadIdx.x;
    if (i < n) wh[i] = __float2half_rn(w[i]);
}

// ---------------- CSR build --------------------------------------------------
__global__ void zero_cnt_kernel() {
    int i = blockIdx.x * blockDim.x + threadIdx.x;
    if (i < NN) g_cnt[i] = 0;
}

__global__ void count_kernel(const int* __restrict__ ei) {
    int e = blockIdx.x * blockDim.x + threadIdx.x;
    if (e < MM) atomicAdd(&g_cnt[ei[e]], 1);
}

#define SCAN_B 512
__global__ void scan1_kernel() {
    __shared__ int sh[SCAN_B];
    int tid = threadIdx.x;
    int i = blockIdx.x * SCAN_B + tid;
    int v = (i < NN) ? g_cnt[i] : 0;
    sh[tid] = v;
    __syncthreads();
    for (int off = 1; off < SCAN_B; off <<= 1) {
        int t = (tid >= off) ? sh[tid - off] : 0;
        __syncthreads();
        sh[tid] += t;
        __syncthreads();
    }
    if (i < NN) g_rowptr[i] = sh[tid] - v;
    if (tid == SCAN_B - 1) g_bsums[blockIdx.x] = sh[tid];
}

__global__ void scan2_kernel(int nb) {
    __shared__ int sh[128];
    int tid = threadIdx.x;
    int v = (tid < nb) ? g_bsums[tid] : 0;
    sh[tid] = v;
    __syncthreads();
    for (int off = 1; off < 128; off <<= 1) {
        int t = (tid >= off) ? sh[tid - off] : 0;
        __syncthreads();
        sh[tid] += t;
        __syncthreads();
    }
    if (tid < nb) g_bsums[tid] = sh[tid] - v;   // exclusive
}

__global__ void scan3_kernel() {
    int i = blockIdx.x * SCAN_B + threadIdx.x;
    if (i < NN) {
        int v = g_rowptr[i] + g_bsums[blockIdx.x];
        g_rowptr[i] = v;
        g_cursor[i] = v;
    }
    if (i == 0) g_rowptr[NN] = MM;
}

__global__ void scatter_kernel(const int* __restrict__ ei) {
    int e = blockIdx.x * blockDim.x + threadIdx.x;
    if (e < MM) {
        int n = ei[e];
        int p = atomicAdd(&g_cursor[n], 1);
        g_nbr[p] = ei[MM + e];
    }
}

// ---------------- LayerNorm -> fp16 (optionally split) ------------------------
__global__ void ln_split_kernel(const float* __restrict__ x, const float* __restrict__ g,
                                const float* __restrict__ b,
                                __half* __restrict__ yh, __half* __restrict__ yl)
{
    int row  = blockIdx.x * 8 + (threadIdx.x >> 5);
    int lane = threadIdx.x & 31;
    if (row >= NN) return;
    const float4* xr = (const float4*)(x + (size_t)row * CC);
    float4 a = xr[lane];
    float4 c = xr[lane + 32];
    float s = a.x + a.y + a.z + a.w + c.x + c.y + c.z + c.w;
    float q = a.x*a.x + a.y*a.y + a.z*a.z + a.w*a.w
            + c.x*c.x + c.y*c.y + c.z*c.z + c.w*c.w;
    #pragma unroll
    for (int o = 16; o; o >>= 1) {
        s += __shfl_xor_sync(0xffffffffu, s, o);
        q += __shfl_xor_sync(0xffffffffu, q, o);
    }
    float mean = s * (1.0f / CC);
    float var  = q * (1.0f / CC) - mean * mean;
    float rstd = rsqrtf(var + LN_EPS);
    const float4* gv = (const float4*)g;
    const float4* bv = (const float4*)b;
    float4 g1 = gv[lane], g2 = gv[lane + 32];
    float4 b1 = bv[lane], b2 = bv[lane + 32];
    float o1[4], o2[4];
    o1[0] = (a.x - mean) * rstd * g1.x + b1.x;
    o1[1] = (a.y - mean) * rstd * g1.y + b1.y;
    o1[2] = (a.z - mean) * rstd * g1.z + b1.z;
    o1[3] = (a.w - mean) * rstd * g1.w + b1.w;
    o2[0] = (c.x - mean) * rstd * g2.x + b2.x;
    o2[1] = (c.y - mean) * rstd * g2.y + b2.y;
    o2[2] = (c.z - mean) * rstd * g2.z + b2.z;
    o2[3] = (c.w - mean) * rstd * g2.w + b2.w;

    __half h1[4], h2[4];
    #pragma unroll
    for (int i = 0; i < 4; i++) {
        h1[i] = __float2half_rn(o1[i]);
        h2[i] = __float2half_rn(o2[i]);
    }
    size_t base = (size_t)row * CC;
    *(uint2*)&yh[base + lane * 4]       = *(uint2*)h1;
    *(uint2*)&yh[base + 128 + lane * 4] = *(uint2*)h2;
    if (yl) {
        __half l1[4], l2[4];
        #pragma unroll
        for (int i = 0; i < 4; i++) {
            l1[i] = __float2half_rn(o1[i] - __half2float(h1[i]));
            l2[i] = __float2half_rn(o2[i] - __half2float(h2[i]));
        }
        *(uint2*)&yl[base + lane * 4]       = *(uint2*)l1;
        *(uint2*)&yl[base + 128 + lane * 4] = *(uint2*)l2;
    }
}

// ---------------- fp16 compensated GEMM (1 or 2 mma terms) --------------------
#define BM 128
#define BN 128
#define BK 32
#define BKP 40
#define TILE (BM * BKP)
#define ARRB (TILE * 2)
#define STAGEB (3 * ARRB)

#define EPI_QKV  0
#define EPI_GELU 1
#define EPI_RES  2

__device__ __forceinline__ uint32_t smem_u32(const void* p) {
    uint32_t a;
    asm("{ .reg .u64 t; cvta.to.shared.u64 t, %1; cvt.u32.u64 %0, t; }" : "=r"(a) : "l"(p));
    return a;
}

__device__ __forceinline__ void cp16(uint32_t dst, const void* src) {
    asm volatile("cp.async.cg.shared.global [%0],[%1],16;\n" :: "r"(dst), "l"(src));
}
#define CP_COMMIT() asm volatile("cp.async.commit_group;\n")
#define CP_WAIT(n)  asm volatile("cp.async.wait_group %0;\n" :: "n"(n))

__device__ __forceinline__ void ldsm4(unsigned& r0, unsigned& r1, unsigned& r2,
                                      unsigned& r3, uint32_t addr)
{
    asm volatile("ldmatrix.sync.aligned.m8n8.x4.shared.b16 {%0,%1,%2,%3}, [%4];"
                 : "=r"(r0), "=r"(r1), "=r"(r2), "=r"(r3) : "r"(addr));
}

__device__ __forceinline__ void mma_f16(float4& d,
    unsigned a0, unsigned a1, unsigned a2, unsigned a3,
    unsigned b0, unsigned b1)
{
    asm volatile(
        "mma.sync.aligned.m16n8k16.row.col.f32.f16.f16.f32 "
        "{%0,%1,%2,%3},{%4,%5,%6,%7},{%8,%9},{%0,%1,%2,%3};"
        : "+f"(d.x), "+f"(d.y), "+f"(d.z), "+f"(d.w)
        : "r"(a0), "r"(a1), "r"(a2), "r"(a3), "r"(b0), "r"(b1));
}

// two_term: 1 = always, 0 = never, -1 = auto (q columns only, for EPI_QKV)
__global__ __launch_bounds__(256, 2)
void gemm_sp_kernel(const __half* __restrict__ Ah, const __half* __restrict__ Al,
                    const __half* __restrict__ Bh,
                    const float* __restrict__ bias, const float* __restrict__ resid,
                    float* __restrict__ Cf, __half* __restrict__ Ch,
                    int M, int Nn, int Kk, int epi, int two_term)
{
    extern __shared__ __half smem[];
    const uint32_t sb0 = smem_u32(smem);

    const int tid  = threadIdx.x;
    const int row0 = blockIdx.y * BM;
    const int col0 = blockIdx.x * BN;
    const int tt   = (two_term >= 0) ? two_term : ((col0 >> 8) == 0 ? 1 : 0);
    const int warp   = tid >> 5;
    const int lane   = tid & 31;
    const int warp_m = warp >> 2;
    const int warp_n = warp & 3;
    const int g = lane >> 2;
    const int t = lane & 3;

    const int rowA = warp_m * 64 + (lane & 15);
    const int colA = 8 * (lane >> 4);
    const uint32_t offA = (uint32_t)(rowA * BKP + colA) * 2;
    const int rowB = warp_n * 32 + (lane & 7) + 8 * ((lane >> 4) & 1);
    const int colB = 8 * ((lane >> 3) & 1);
    const uint32_t offB = (uint32_t)(rowB * BKP + colB) * 2;

    const int ch0 = tid * 2;
    const int nKiter = Kk / BK;

    float4 acc[4][4];
    #pragma unroll
    for (int i = 0; i < 4; i++)
        #pragma unroll
        for (int j = 0; j < 4; j++) acc[i][j] = make_float4(0.f, 0.f, 0.f, 0.f);

    auto stage = [&](int st, int k0) {
        uint32_t base = sb0 + st * STAGEB;
        #pragma unroll
        for (int q = 0; q < 2; q++) {
            int idx = ch0 + q;
            int r    = idx >> 2;
            int c16  = idx & 3;
            int ar = row0 + r; if (ar >= M) ar = M - 1;
            size_t aoff = (size_t)ar * Kk + k0 + c16 * 8;
            int br = col0 + r;
            size_t boff = (size_t)br * Kk + k0 + c16 * 8;
            uint32_t d = (uint32_t)(r * BKP + c16 * 8) * 2;
            cp16(base + 0 * ARRB + d, Ah + aoff);
            if (tt) cp16(base + 1 * ARRB + d, Al + aoff);
            cp16(base + 2 * ARRB + d, Bh + boff);
        }
    };

    stage(0, 0);
    CP_COMMIT();

    for (int it = 0; it < nKiter; it++) {
        if (it + 1 < nKiter) {
            stage((it + 1) & 1, (it + 1) * BK);
            CP_COMMIT();
            CP_WAIT(1);
        } else {
            CP_WAIT(0);
        }
        __syncthreads();

        const uint32_t base = sb0 + (it & 1) * STAGEB;
        const uint32_t aAh = base + offA;
        const uint32_t aAl = base + ARRB + offA;
        const uint32_t aBh = base + 2 * ARRB + offB;

        #pragma unroll
        for (int s = 0; s < 2; s++) {
            unsigned bh[4][2];
            ldsm4(bh[0][0], bh[0][1], bh[1][0], bh[1][1], aBh + s * 32);
            ldsm4(bh[2][0], bh[2][1], bh[3][0], bh[3][1], aBh + 16 * BKP * 2 + s * 32);
            #pragma unroll
            for (int mi = 0; mi < 4; mi++) {
                unsigned ah0, ah1, ah2, ah3;
                ldsm4(ah0, ah1, ah2, ah3, aAh + mi * (16 * BKP * 2) + s * 32);
                #pragma unroll
                for (int ni = 0; ni < 4; ni++)
                    mma_f16(acc[mi][ni], ah0, ah1, ah2, ah3, bh[ni][0], bh[ni][1]);
                if (tt) {
                    unsigned al0, al1, al2, al3;
                    ldsm4(al0, al1, al2, al3, aAl + mi * (16 * BKP * 2) + s * 32);
                    #pragma unroll
                    for (int ni = 0; ni < 4; ni++)
                        mma_f16(acc[mi][ni], al0, al1, al2, al3, bh[ni][0], bh[ni][1]);
                }
            }
        }
        __syncthreads();
    }

    const int region = col0 >> 8;     // for EPI_QKV: 0=q, 1=k, 2=v
    #pragma unroll
    for (int mi = 0; mi < 4; mi++) {
        int r = row0 + warp_m * 64 + mi * 16 + g;
        #pragma unroll
        for (int ni = 0; ni < 4; ni++) {
            int c = col0 + warp_n * 32 + ni * 8 + 2 * t;
            float bx = bias[c], by = bias[c + 1];
            float4 d = acc[mi][ni];
            float v0 = d.x + bx, v1 = d.y + by;
            float v2 = d.z + bx, v3 = d.w + by;
            if (epi == EPI_QKV) {
                int local = c & 255;
                if (region == 0) {
                    if (r < M) {
                        g_q[(size_t)r * CC + local]     = v0 * QK_SCALE;
                        g_q[(size_t)r * CC + local + 1] = v1 * QK_SCALE;
                    }
                    if (r + 8 < M) {
                        g_q[(size_t)(r + 8) * CC + local]     = v2 * QK_SCALE;
                        g_q[(size_t)(r + 8) * CC + local + 1] = v3 * QK_SCALE;
                    }
                } else {
                    int h  = local >> 5;
                    int dd = (local & 31) + (region == 2 ? 32 : 0);
                    if (r < M) {
                        __half2 p; p.x = __float2half_rn(v0); p.y = __float2half_rn(v1);
                        *(__half2*)&g_kv[((size_t)r * HH + h) * 64 + dd] = p;
                    }
                    if (r + 8 < M) {
                        __half2 p; p.x = __float2half_rn(v2); p.y = __float2half_rn(v3);
                        *(__half2*)&g_kv[((size_t)(r + 8) * HH + h) * 64 + dd] = p;
                    }
                }
            } else if (epi == EPI_GELU) {
                v0 = 0.5f * v0 * (1.0f + erff(v0 * 0.70710678f));
                v1 = 0.5f * v1 * (1.0f + erff(v1 * 0.70710678f));
                v2 = 0.5f * v2 * (1.0f + erff(v2 * 0.70710678f));
                v3 = 0.5f * v3 * (1.0f + erff(v3 * 0.70710678f));
                if (r < M) {
                    size_t o = (size_t)r * Nn + c;
                    __half2 p; p.x = __float2half_rn(v0); p.y = __float2half_rn(v1);
                    *(__half2*)&Ch[o] = p;
                }
                if (r + 8 < M) {
                    size_t o = (size_t)(r + 8) * Nn + c;
                    __half2 p; p.x = __float2half_rn(v2); p.y = __float2half_rn(v3);
                    *(__half2*)&Ch[o] = p;
                }
            } else {
                if (r < M) {
                    size_t o = (size_t)r * Nn + c;
                    float r0 = resid[o], r1 = resid[o + 1];
                    Cf[o] = v0 + r0; Cf[o + 1] = v1 + r1;
                }
                if (r + 8 < M) {
                    size_t o = (size_t)(r + 8) * Nn + c;
                    float r2 = resid[o], r3 = resid[o + 1];
                    Cf[o] = v2 + r2; Cf[o + 1] = v3 + r3;
                }
            }
        }
    }
}

// ---------------- Edge-softmax attention -------------------------------------
// warp/(node,head); one coalesced 128B LDG.32 per edge (lanes 0-15 k, 16-31 v);
// 8-edge batches for deep MLP against L2 latency.
__global__ void attn_kernel(__half* __restrict__ oh)
{
    int n    = blockIdx.x;
    int h    = threadIdx.x >> 5;
    int lane = threadIdx.x & 31;
    float2 q2 = make_float2(0.f, 0.f);
    if (lane < 16)
        q2 = *(const float2*)&g_q[(size_t)n * CC + h * HDIM + 2 * lane];
    int s = g_rowptr[n];
    int e = g_rowptr[n + 1];
    float m = -INFINITY, l = 0.0f;
    float2 acc = make_float2(0.f, 0.f);

    int i = s;
    for (; i + 7 < e; i += 8) {
        int j[8];
        float2 fv[8];
        float d[8];
        #pragma unroll
        for (int u = 0; u < 8; u++) j[u] = g_nbr[i + u];
        #pragma unroll
        for (int u = 0; u < 8; u++) {
            __half2 hv = *(const __half2*)&g_kv[((size_t)j[u] * HH + h) * 64 + 2 * lane];
            fv[u] = __half22float2(hv);
        }
        #pragma unroll
        for (int u = 0; u < 8; u++)
            d[u] = (lane < 16) ? (q2.x * fv[u].x + q2.y * fv[u].y) : 0.0f;
        #pragma unroll
        for (int o = 16; o; o >>= 1) {
            #pragma unroll
            for (int u = 0; u < 8; u++)
                d[u] += __shfl_xor_sync(0xffffffffu, d[u], o);
        }
        float mb = d[0];
        #pragma unroll
        for (int u = 1; u < 8; u++) mb = fmaxf(mb, d[u]);
        float mn = fmaxf(m, mb);
        float sc = __expf(m - mn);
        float p[8], ps = 0.0f;
        #pragma unroll
        for (int u = 0; u < 8; u++) { p[u] = __expf(d[u] - mn); ps += p[u]; }
        l = l * sc + ps;
        float ax = acc.x * sc, ay = acc.y * sc;
        #pragma unroll
        for (int u = 0; u < 8; u++) { ax += p[u] * fv[u].x; ay += p[u] * fv[u].y; }
        acc.x = ax; acc.y = ay;
        m = mn;
    }
    for (; i + 3 < e; i += 4) {
        int j[4];
        float2 fv[4];
        float d[4];
        #pragma unroll
        for (int u = 0; u < 4; u++) j[u] = g_nbr[i + u];
        #pragma unroll
        for (int u = 0; u < 4; u++) {
            __half2 hv = *(const __half2*)&g_kv[((size_t)j[u] * HH + h) * 64 + 2 * lane];
            fv[u] = __half22float2(hv);
        }
        #pragma unroll
        for (int u = 0; u < 4; u++)
            d[u] = (lane < 16) ? (q2.x * fv[u].x + q2.y * fv[u].y) : 0.0f;
        #pragma unroll
        for (int o = 16; o; o >>= 1) {
            #pragma unroll
            for (int u = 0; u < 4; u++)
                d[u] += __shfl_xor_sync(0xffffffffu, d[u], o);
        }
        float mb = fmaxf(fmaxf(d[0], d[1]), fmaxf(d[2], d[3]));
        float mn = fmaxf(m, mb);
        float sc = __expf(m - mn);
        float p0 = __expf(d[0] - mn);
        float p1 = __expf(d[1] - mn);
        float p2 = __expf(d[2] - mn);
        float p3 = __expf(d[3] - mn);
        l = l * sc + (p0 + p1 + p2 + p3);
        acc.x = acc.x * sc + p0 * fv[0].x + p1 * fv[1].x + p2 * fv[2].x + p3 * fv[3].x;
        acc.y = acc.y * sc + p0 * fv[0].y + p1 * fv[1].y + p2 * fv[2].y + p3 * fv[3].y;
        m = mn;
    }
    for (; i < e; i++) {
        int j = g_nbr[i];
        __half2 hv = *(const __half2*)&g_kv[((size_t)j * HH + h) * 64 + 2 * lane];
        float2 f = __half22float2(hv);
        float d = (lane < 16) ? (q2.x * f.x + q2.y * f.y) : 0.0f;
        #pragma unroll
        for (int o = 16; o; o >>= 1) d += __shfl_xor_sync(0xffffffffu, d, o);
        float mn = fmaxf(m, d);
        float sc = __expf(m - mn);
        float p  = __expf(d - mn);
        l = l * sc + p;
        acc.x = acc.x * sc + p * f.x;
        acc.y = acc.y * sc + p * f.y;
        m = mn;
    }
    if (lane >= 16) {
        float inv = (l > 0.0f) ? (1.0f / l) : 0.0f;
        __half2 p;
        p.x = __float2half_rn(acc.x * inv);
        p.y = __float2half_rn(acc.y * inv);
        *(__half2*)&oh[(size_t)n * CC + h * HDIM + 2 * (lane - 16)] = p;
    }
}

// ---------------- host launcher ---------------------------------------------
extern "C" void kernel_launch(void* const* d_in, const int* in_sizes, int n_in,
                              void* d_out, int out_size)
{
    const float* feats  = (const float*)d_in[0];
    const int*   ei     = (const int*)d_in[2];
    const float* ln1_g  = (const float*)d_in[3];
    const float* ln1_b  = (const float*)d_in[4];
    const float* qkv_w  = (const float*)d_in[5];
    const float* qkv_b  = (const float*)d_in[6];
    const float* proj_w = (const float*)d_in[7];
    const float* proj_b = (const float*)d_in[8];
    const float* ln2_g  = (const float*)d_in[9];
    const float* ln2_b  = (const float*)d_in[10];
    const float* fc1_w  = (const float*)d_in[11];
    const float* fc1_b  = (const float*)d_in[12];
    const float* fc2_w  = (const float*)d_in[13];
    const float* fc2_b  = (const float*)d_in[14];
    float* out = (float*)d_out;

    float *p_f2;
    cudaGetSymbolAddress((void**)&p_f2,  g_f2);
    __half *p_xn_h, *p_xn_l, *p_at_h, *p_y_h, *p_h1_h;
    cudaGetSymbolAddress((void**)&p_xn_h, g_xn_h);
    cudaGetSymbolAddress((void**)&p_xn_l, g_xn_l);
    cudaGetSymbolAddress((void**)&p_at_h, g_at_h);
    cudaGetSymbolAddress((void**)&p_y_h,  g_y_h);
    cudaGetSymbolAddress((void**)&p_h1_h, g_h1_h);
    __half *p_wqkv, *p_wprj, *p_wfc1, *p_wfc2;
    cudaGetSymbolAddress((void**)&p_wqkv, g_wqkv);
    cudaGetSymbolAddress((void**)&p_wprj, g_wprj);
    cudaGetSymbolAddress((void**)&p_wfc1, g_wfc1);
    cudaGetSymbolAddress((void**)&p_wfc2, g_wfc2);

    const int SMEM_BYTES = 2 * STAGEB;   // 61440
    static int init_done = 0;
    static cudaStream_t sB;
    static cudaEvent_t evFork, evJoin;
    if (!init_done) {
        cudaFuncSetAttribute(gemm_sp_kernel,
                             cudaFuncAttributeMaxDynamicSharedMemorySize, SMEM_BYTES);
        cudaStreamCreateWithFlags(&sB, cudaStreamNonBlocking);
        cudaEventCreateWithFlags(&evFork, cudaEventDisableTiming);
        cudaEventCreateWithFlags(&evJoin, cudaEventDisableTiming);
        init_done = 1;
    }

    const int nscan = (NN + SCAN_B - 1) / SCAN_B;
    const int MROWS = (NN + BM - 1) / BM;

    // fork side stream
    cudaEventRecord(evFork, 0);
    cudaStreamWaitEvent(sB, evFork, 0);

    // ---- stream B: CSR build + non-qkv weight rounds (independent of LN1/qkv)
    zero_cnt_kernel<<<(NN + 255) / 256, 256, 0, sB>>>();
    count_kernel<<<(MM + 255) / 256, 256, 0, sB>>>(ei);
    scan1_kernel<<<nscan, SCAN_B, 0, sB>>>();
    scan2_kernel<<<1, 128, 0, sB>>>(nscan);
    scan3_kernel<<<nscan, SCAN_B, 0, sB>>>();
    scatter_kernel<<<(MM + 255) / 256, 256, 0, sB>>>(ei);
    round_kernel<<<(CC*CC   + 255)/256, 256, 0, sB>>>(proj_w, p_wprj, CC*CC);
    round_kernel<<<(HIDN*CC + 255)/256, 256, 0, sB>>>(fc1_w, p_wfc1, HIDN*CC);
    round_kernel<<<(CC*HIDN + 255)/256, 256, 0, sB>>>(fc2_w, p_wfc2, CC*HIDN);
    cudaEventRecord(evJoin, sB);

    // ---- main stream: qkv path
    round_kernel<<<(3*CC*CC + 255)/256, 256>>>(qkv_w, p_wqkv, 3*CC*CC);
    ln_split_kernel<<<(NN + 7) / 8, 256>>>(feats, ln1_g, ln1_b, p_xn_h, p_xn_l);

    // qkv merged: q cols 2-term, k/v cols 1-term (auto per block)
    {
        dim3 grid(768 / BN, MROWS);
        gemm_sp_kernel<<<grid, 256, SMEM_BYTES>>>(p_xn_h, p_xn_l, p_wqkv,
                                                  qkv_b, nullptr, nullptr, nullptr,
                                                  NN, 768, CC, EPI_QKV, -1);
    }

    // join: attention needs CSR + qkv
    cudaStreamWaitEvent(0, evJoin, 0);

    attn_kernel<<<NN, 256>>>(p_at_h);

    // proj: 1-term
    {
        dim3 grid(CC / BN, MROWS);
        gemm_sp_kernel<<<grid, 256, SMEM_BYTES>>>(p_at_h, nullptr, p_wprj,
                                                  proj_b, feats, p_f2, nullptr,
                                                  NN, CC, CC, EPI_RES, 0);
    }

    // LN2 -> fp16 (hi only)
    ln_split_kernel<<<(NN + 7) / 8, 256>>>(p_f2, ln2_g, ln2_b, p_y_h, nullptr);

    // fc1 + gelu: 1-term
    {
        dim3 grid(HIDN / BN, MROWS);
        gemm_sp_kernel<<<grid, 256, SMEM_BYTES>>>(p_y_h, nullptr, p_wfc1,
                                                  fc1_b, nullptr, nullptr, p_h1_h,
                                                  NN, HIDN, CC, EPI_GELU, 0);
    }

    // fc2 + residual: 1-term
    {
        dim3 grid(CC / BN, MROWS);
        gemm_sp_kernel<<<grid, 256, SMEM_BYTES>>>(p_h1_h, nullptr, p_wfc2,
                                                  fc2_b, p_f2, out, nullptr,
                                                  NN, CC, HIDN, EPI_RES, 0);
    }
}

// round 13
// speedup vs baseline: 2.9341x; 1.0259x over previous
#include <cuda_runtime.h>
#include <cuda_fp16.h>
#include <cstdint>
#include <math.h>

#define NN   50000
#define CC   256
#define HH   8
#define HDIM 32
#define MM   800000
#define HIDN 1024
#define QK_SCALE 0.17677669529663687f
#define LN_EPS 1e-5f

// ---------------- scratch (static device globals; no allocation) -------------
__device__ __align__(16) float g_q  [NN * CC];            // scaled q (fp32)
__device__ __align__(16) __half g_kv[NN * HH * 64];       // [n][h][k32|v32] fp16
__device__ __align__(16) float g_f2 [NN * CC];
__device__ __align__(16) __half g_xn_h[NN * CC],  g_xn_l[NN * CC];
__device__ __align__(16) __half g_at_h[NN * CC];
__device__ __align__(16) __half g_y_h [NN * CC];
__device__ __align__(16) __half g_h1_h[NN * HIDN];
__device__ __align__(16) __half g_wqkv[3*CC*CC];
__device__ __align__(16) __half g_wprj[CC*CC];
__device__ __align__(16) __half g_wfc1[HIDN*CC];
__device__ __align__(16) __half g_wfc2[CC*HIDN];
__device__ int g_cnt[NN];
__device__ int g_rowptr[NN + 1];
__device__ int g_cursor[NN];
__device__ int g_bsums[128];
__device__ int g_nbr[MM];

// ---------------- common PTX helpers ------------------------------------------
__device__ __forceinline__ uint32_t smem_u32(const void* p) {
    uint32_t a;
    asm("{ .reg .u64 t; cvta.to.shared.u64 t, %1; cvt.u32.u64 %0, t; }" : "=r"(a) : "l"(p));
    return a;
}

__device__ __forceinline__ void cp16(uint32_t dst, const void* src) {
    asm volatile("cp.async.cg.shared.global [%0],[%1],16;\n" :: "r"(dst), "l"(src));
}
#define CP_COMMIT() asm volatile("cp.async.commit_group;\n")
#define CP_WAIT(n)  asm volatile("cp.async.wait_group %0;\n" :: "n"(n))

// ---------------- fp32 -> fp16 weight round ----------------------------------
__global__ void round_kernel(const float* __restrict__ w,
                             __half* __restrict__ wh, int n)
{
    int i = blockIdx.x * blockDim.x + threadIdx.x;
    if (i < n) wh[i] = __float2half_rn(w[i]);
}

// ---------------- CSR build --------------------------------------------------
__global__ void zero_cnt_kernel() {
    int i = blockIdx.x * blockDim.x + threadIdx.x;
    if (i < NN) g_cnt[i] = 0;
}

__global__ void count_kernel(const int* __restrict__ ei) {
    int e = blockIdx.x * blockDim.x + threadIdx.x;
    if (e < MM) atomicAdd(&g_cnt[ei[e]], 1);
}

#define SCAN_B 512
__global__ void scan1_kernel() {
    __shared__ int sh[SCAN_B];
    int tid = threadIdx.x;
    int i = blockIdx.x * SCAN_B + tid;
    int v = (i < NN) ? g_cnt[i] : 0;
    sh[tid] = v;
    __syncthreads();
    for (int off = 1; off < SCAN_B; off <<= 1) {
        int t = (tid >= off) ? sh[tid - off] : 0;
        __syncthreads();
        sh[tid] += t;
        __syncthreads();
    }
    if (i < NN) g_rowptr[i] = sh[tid] - v;
    if (tid == SCAN_B - 1) g_bsums[blockIdx.x] = sh[tid];
}

__global__ void scan2_kernel(int nb) {
    __shared__ int sh[128];
    int tid = threadIdx.x;
    int v = (tid < nb) ? g_bsums[tid] : 0;
    sh[tid] = v;
    __syncthreads();
    for (int off = 1; off < 128; off <<= 1) {
        int t = (tid >= off) ? sh[tid - off] : 0;
        __syncthreads();
        sh[tid] += t;
        __syncthreads();
    }
    if (tid < nb) g_bsums[tid] = sh[tid] - v;   // exclusive
}

__global__ void scan3_kernel() {
    int i = blockIdx.x * SCAN_B + threadIdx.x;
    if (i < NN) {
        int v = g_rowptr[i] + g_bsums[blockIdx.x];
        g_rowptr[i] = v;
        g_cursor[i] = v;
    }
    if (i == 0) g_rowptr[NN] = MM;
}

__global__ void scatter_kernel(const int* __restrict__ ei) {
    int e = blockIdx.x * blockDim.x + threadIdx.x;
    if (e < MM) {
        int n = ei[e];
        int p = atomicAdd(&g_cursor[n], 1);
        g_nbr[p] = ei[MM + e];
    }
}

// ---------------- LayerNorm -> fp16 (optionally split) ------------------------
__global__ void ln_split_kernel(const float* __restrict__ x, const float* __restrict__ g,
                                const float* __restrict__ b,
                                __half* __restrict__ yh, __half* __restrict__ yl)
{
    int row  = blockIdx.x * 8 + (threadIdx.x >> 5);
    int lane = threadIdx.x & 31;
    if (row >= NN) return;
    const float4* xr = (const float4*)(x + (size_t)row * CC);
    float4 a = xr[lane];
    float4 c = xr[lane + 32];
    float s = a.x + a.y + a.z + a.w + c.x + c.y + c.z + c.w;
    float q = a.x*a.x + a.y*a.y + a.z*a.z + a.w*a.w
            + c.x*c.x + c.y*c.y + c.z*c.z + c.w*c.w;
    #pragma unroll
    for (int o = 16; o; o >>= 1) {
        s += __shfl_xor_sync(0xffffffffu, s, o);
        q += __shfl_xor_sync(0xffffffffu, q, o);
    }
    float mean = s * (1.0f / CC);
    float var  = q * (1.0f / CC) - mean * mean;
    float rstd = rsqrtf(var + LN_EPS);
    const float4* gv = (const float4*)g;
    const float4* bv = (const float4*)b;
    float4 g1 = gv[lane], g2 = gv[lane + 32];
    float4 b1 = bv[lane], b2 = bv[lane + 32];
    float o1[4], o2[4];
    o1[0] = (a.x - mean) * rstd * g1.x + b1.x;
    o1[1] = (a.y - mean) * rstd * g1.y + b1.y;
    o1[2] = (a.z - mean) * rstd * g1.z + b1.z;
    o1[3] = (a.w - mean) * rstd * g1.w + b1.w;
    o2[0] = (c.x - mean) * rstd * g2.x + b2.x;
    o2[1] = (c.y - mean) * rstd * g2.y + b2.y;
    o2[2] = (c.z - mean) * rstd * g2.z + b2.z;
    o2[3] = (c.w - mean) * rstd * g2.w + b2.w;

    __half h1[4], h2[4];
    #pragma unroll
    for (int i = 0; i < 4; i++) {
        h1[i] = __float2half_rn(o1[i]);
        h2[i] = __float2half_rn(o2[i]);
    }
    size_t base = (size_t)row * CC;
    *(uint2*)&yh[base + lane * 4]       = *(uint2*)h1;
    *(uint2*)&yh[base + 128 + lane * 4] = *(uint2*)h2;
    if (yl) {
        __half l1[4], l2[4];
        #pragma unroll
        for (int i = 0; i < 4; i++) {
            l1[i] = __float2half_rn(o1[i] - __half2float(h1[i]));
            l2[i] = __float2half_rn(o2[i] - __half2float(h2[i]));
        }
        *(uint2*)&yl[base + lane * 4]       = *(uint2*)l1;
        *(uint2*)&yl[base + 128 + lane * 4] = *(uint2*)l2;
    }
}

// ---------------- fp16 compensated GEMM (1 or 2 mma terms) --------------------
#define BM 128
#define BN 128
#define BK 32
#define BKP 40
#define TILE (BM * BKP)
#define ARRB (TILE * 2)
#define STAGEB (3 * ARRB)

#define EPI_QKV  0
#define EPI_GELU 1
#define EPI_RES  2

__device__ __forceinline__ void ldsm4(unsigned& r0, unsigned& r1, unsigned& r2,
                                      unsigned& r3, uint32_t addr)
{
    asm volatile("ldmatrix.sync.aligned.m8n8.x4.shared.b16 {%0,%1,%2,%3}, [%4];"
                 : "=r"(r0), "=r"(r1), "=r"(r2), "=r"(r3) : "r"(addr));
}

__device__ __forceinline__ void mma_f16(float4& d,
    unsigned a0, unsigned a1, unsigned a2, unsigned a3,
    unsigned b0, unsigned b1)
{
    asm volatile(
        "mma.sync.aligned.m16n8k16.row.col.f32.f16.f16.f32 "
        "{%0,%1,%2,%3},{%4,%5,%6,%7},{%8,%9},{%0,%1,%2,%3};"
        : "+f"(d.x), "+f"(d.y), "+f"(d.z), "+f"(d.w)
        : "r"(a0), "r"(a1), "r"(a2), "r"(a3), "r"(b0), "r"(b1));
}

// fast exact-enough gelu: x*sigmoid(1.59576912*x*(1+0.044715*x^2))
__device__ __forceinline__ float fast_gelu(float x) {
    float w = 1.59576912f * x * (1.0f + 0.044715f * x * x);
    return __fdividef(x, 1.0f + __expf(-w));
}

// two_term: 1 = always, 0 = never, -1 = auto (q columns only, for EPI_QKV)
__global__ __launch_bounds__(256, 2)
void gemm_sp_kernel(const __half* __restrict__ Ah, const __half* __restrict__ Al,
                    const __half* __restrict__ Bh,
                    const float* __restrict__ bias, const float* __restrict__ resid,
                    float* __restrict__ Cf, __half* __restrict__ Ch,
                    int M, int Nn, int Kk, int epi, int two_term)
{
    extern __shared__ __half smem[];
    const uint32_t sb0 = smem_u32(smem);

    const int tid  = threadIdx.x;
    const int row0 = blockIdx.y * BM;
    const int col0 = blockIdx.x * BN;
    const int tt   = (two_term >= 0) ? two_term : ((col0 >> 8) == 0 ? 1 : 0);
    const int warp   = tid >> 5;
    const int lane   = tid & 31;
    const int warp_m = warp >> 2;
    const int warp_n = warp & 3;
    const int g = lane >> 2;
    const int t = lane & 3;

    const int rowA = warp_m * 64 + (lane & 15);
    const int colA = 8 * (lane >> 4);
    const uint32_t offA = (uint32_t)(rowA * BKP + colA) * 2;
    const int rowB = warp_n * 32 + (lane & 7) + 8 * ((lane >> 4) & 1);
    const int colB = 8 * ((lane >> 3) & 1);
    const uint32_t offB = (uint32_t)(rowB * BKP + colB) * 2;

    const int ch0 = tid * 2;
    const int nKiter = Kk / BK;

    float4 acc[4][4];
    #pragma unroll
    for (int i = 0; i < 4; i++)
        #pragma unroll
        for (int j = 0; j < 4; j++) acc[i][j] = make_float4(0.f, 0.f, 0.f, 0.f);

    auto stage = [&](int st, int k0) {
        uint32_t base = sb0 + st * STAGEB;
        #pragma unroll
        for (int q = 0; q < 2; q++) {
            int idx = ch0 + q;
            int r    = idx >> 2;
            int c16  = idx & 3;
            int ar = row0 + r; if (ar >= M) ar = M - 1;
            size_t aoff = (size_t)ar * Kk + k0 + c16 * 8;
            int br = col0 + r;
            size_t boff = (size_t)br * Kk + k0 + c16 * 8;
            uint32_t d = (uint32_t)(r * BKP + c16 * 8) * 2;
            cp16(base + 0 * ARRB + d, Ah + aoff);
            if (tt) cp16(base + 1 * ARRB + d, Al + aoff);
            cp16(base + 2 * ARRB + d, Bh + boff);
        }
    };

    stage(0, 0);
    CP_COMMIT();

    for (int it = 0; it < nKiter; it++) {
        if (it + 1 < nKiter) {
            stage((it + 1) & 1, (it + 1) * BK);
            CP_COMMIT();
            CP_WAIT(1);
        } else {
            CP_WAIT(0);
        }
        __syncthreads();

        const uint32_t base = sb0 + (it & 1) * STAGEB;
        const uint32_t aAh = base + offA;
        const uint32_t aAl = base + ARRB + offA;
        const uint32_t aBh = base + 2 * ARRB + offB;

        #pragma unroll
        for (int s = 0; s < 2; s++) {
            unsigned bh[4][2];
            ldsm4(bh[0][0], bh[0][1], bh[1][0], bh[1][1], aBh + s * 32);
            ldsm4(bh[2][0], bh[2][1], bh[3][0], bh[3][1], aBh + 16 * BKP * 2 + s * 32);
            #pragma unroll
            for (int mi = 0; mi < 4; mi++) {
                unsigned ah0, ah1, ah2, ah3;
                ldsm4(ah0, ah1, ah2, ah3, aAh + mi * (16 * BKP * 2) + s * 32);
                #pragma unroll
                for (int ni = 0; ni < 4; ni++)
                    mma_f16(acc[mi][ni], ah0, ah1, ah2, ah3, bh[ni][0], bh[ni][1]);
                if (tt) {
                    unsigned al0, al1, al2, al3;
                    ldsm4(al0, al1, al2, al3, aAl + mi * (16 * BKP * 2) + s * 32);
                    #pragma unroll
                    for (int ni = 0; ni < 4; ni++)
                        mma_f16(acc[mi][ni], al0, al1, al2, al3, bh[ni][0], bh[ni][1]);
                }
            }
        }
        __syncthreads();
    }

    const int region = col0 >> 8;     // for EPI_QKV: 0=q, 1=k, 2=v
    #pragma unroll
    for (int mi = 0; mi < 4; mi++) {
        int r = row0 + warp_m * 64 + mi * 16 + g;
        #pragma unroll
        for (int ni = 0; ni < 4; ni++) {
            int c = col0 + warp_n * 32 + ni * 8 + 2 * t;
            float bx = bias[c], by = bias[c + 1];
            float4 d = acc[mi][ni];
            float v0 = d.x + bx, v1 = d.y + by;
            float v2 = d.z + bx, v3 = d.w + by;
            if (epi == EPI_QKV) {
                int local = c & 255;
                if (region == 0) {
                    if (r < M) {
                        g_q[(size_t)r * CC + local]     = v0 * QK_SCALE;
                        g_q[(size_t)r * CC + local + 1] = v1 * QK_SCALE;
                    }
                    if (r + 8 < M) {
                        g_q[(size_t)(r + 8) * CC + local]     = v2 * QK_SCALE;
                        g_q[(size_t)(r + 8) * CC + local + 1] = v3 * QK_SCALE;
                    }
                } else {
                    int h  = local >> 5;
                    int dd = (local & 31) + (region == 2 ? 32 : 0);
                    if (r < M) {
                        __half2 p; p.x = __float2half_rn(v0); p.y = __float2half_rn(v1);
                        *(__half2*)&g_kv[((size_t)r * HH + h) * 64 + dd] = p;
                    }
                    if (r + 8 < M) {
                        __half2 p; p.x = __float2half_rn(v2); p.y = __float2half_rn(v3);
                        *(__half2*)&g_kv[((size_t)(r + 8) * HH + h) * 64 + dd] = p;
                    }
                }
            } else if (epi == EPI_GELU) {
                v0 = fast_gelu(v0);
                v1 = fast_gelu(v1);
                v2 = fast_gelu(v2);
                v3 = fast_gelu(v3);
                if (r < M) {
                    size_t o = (size_t)r * Nn + c;
                    __half2 p; p.x = __float2half_rn(v0); p.y = __float2half_rn(v1);
                    *(__half2*)&Ch[o] = p;
                }
                if (r + 8 < M) {
                    size_t o = (size_t)(r + 8) * Nn + c;
                    __half2 p; p.x = __float2half_rn(v2); p.y = __float2half_rn(v3);
                    *(__half2*)&Ch[o] = p;
                }
            } else {
                if (r < M) {
                    size_t o = (size_t)r * Nn + c;
                    float r0 = resid[o], r1 = resid[o + 1];
                    Cf[o] = v0 + r0; Cf[o + 1] = v1 + r1;
                }
                if (r + 8 < M) {
                    size_t o = (size_t)(r + 8) * Nn + c;
                    float r2 = resid[o], r3 = resid[o + 1];
                    Cf[o] = v2 + r2; Cf[o + 1] = v3 + r3;
                }
            }
        }
    }
}

// ---------------- Edge-softmax attention -------------------------------------
// block per node; cp.async stages all neighbor KV lines (1KB each) into smem
// in 32-edge chunks; warp h computes head h from smem (lanes 0-15 k, 16-31 v).
#define ACH 32
__global__ __launch_bounds__(256)
void attn_kernel(__half* __restrict__ oh)
{
    __shared__ __align__(16) __half skv[ACH * 512];
    int n    = blockIdx.x;
    int tid  = threadIdx.x;
    int h    = tid >> 5;
    int lane = tid & 31;
    float2 q2 = make_float2(0.f, 0.f);
    if (lane < 16)
        q2 = *(const float2*)&g_q[(size_t)n * CC + h * HDIM + 2 * lane];
    int s = g_rowptr[n];
    int e = g_rowptr[n + 1];
    float m = -INFINITY, l = 0.0f;
    float2 acc = make_float2(0.f, 0.f);
    const uint32_t sbase = smem_u32(skv);

    for (int c0 = s; c0 < e; c0 += ACH) {
        int cnt = min(ACH, e - c0);
        __syncthreads();                       // smem reuse guard
        for (int idx = tid; idx < cnt * 64; idx += 256) {
            int ed  = idx >> 6;
            int c16 = idx & 63;
            const char* src = (const char*)(g_kv + (size_t)g_nbr[c0 + ed] * 512)
                              + c16 * 16;
            cp16(sbase + (uint32_t)(ed * 1024 + c16 * 16), src);
        }
        CP_COMMIT();
        CP_WAIT(0);
        __syncthreads();

        int u = 0;
        for (; u + 3 < cnt; u += 4) {
            float2 fv[4];
            float d[4];
            #pragma unroll
            for (int k2 = 0; k2 < 4; k2++) {
                __half2 hv = *(const __half2*)&skv[(u + k2) * 512 + h * 64 + 2 * lane];
                fv[k2] = __half22float2(hv);
            }
            #pragma unroll
            for (int k2 = 0; k2 < 4; k2++)
                d[k2] = (lane < 16) ? (q2.x * fv[k2].x + q2.y * fv[k2].y) : 0.0f;
            #pragma unroll
            for (int o = 16; o; o >>= 1) {
                #pragma unroll
                for (int k2 = 0; k2 < 4; k2++)
                    d[k2] += __shfl_xor_sync(0xffffffffu, d[k2], o);
            }
            float mb = fmaxf(fmaxf(d[0], d[1]), fmaxf(d[2], d[3]));
            float mn = fmaxf(m, mb);
            float sc = __expf(m - mn);
            float p0 = __expf(d[0] - mn);
            float p1 = __expf(d[1] - mn);
            float p2 = __expf(d[2] - mn);
            float p3 = __expf(d[3] - mn);
            l = l * sc + (p0 + p1 + p2 + p3);
            acc.x = acc.x * sc + p0 * fv[0].x + p1 * fv[1].x + p2 * fv[2].x + p3 * fv[3].x;
            acc.y = acc.y * sc + p0 * fv[0].y + p1 * fv[1].y + p2 * fv[2].y + p3 * fv[3].y;
            m = mn;
        }
        for (; u < cnt; u++) {
            __half2 hv = *(const __half2*)&skv[u * 512 + h * 64 + 2 * lane];
            float2 f = __half22float2(hv);
            float d = (lane < 16) ? (q2.x * f.x + q2.y * f.y) : 0.0f;
            #pragma unroll
            for (int o = 16; o; o >>= 1) d += __shfl_xor_sync(0xffffffffu, d, o);
            float mn = fmaxf(m, d);
            float sc = __expf(m - mn);
            float p  = __expf(d - mn);
            l = l * sc + p;
            acc.x = acc.x * sc + p * f.x;
            acc.y = acc.y * sc + p * f.y;
            m = mn;
        }
    }
    if (lane >= 16) {
        float inv = (l > 0.0f) ? (1.0f / l) : 0.0f;
        __half2 p;
        p.x = __float2half_rn(acc.x * inv);
        p.y = __float2half_rn(acc.y * inv);
        *(__half2*)&oh[(size_t)n * CC + h * HDIM + 2 * (lane - 16)] = p;
    }
}

// ---------------- host launcher ---------------------------------------------
extern "C" void kernel_launch(void* const* d_in, const int* in_sizes, int n_in,
                              void* d_out, int out_size)
{
    const float* feats  = (const float*)d_in[0];
    const int*   ei     = (const int*)d_in[2];
    const float* ln1_g  = (const float*)d_in[3];
    const float* ln1_b  = (const float*)d_in[4];
    const float* qkv_w  = (const float*)d_in[5];
    const float* qkv_b  = (const float*)d_in[6];
    const float* proj_w = (const float*)d_in[7];
    const float* proj_b = (const float*)d_in[8];
    const float* ln2_g  = (const float*)d_in[9];
    const float* ln2_b  = (const float*)d_in[10];
    const float* fc1_w  = (const float*)d_in[11];
    const float* fc1_b  = (const float*)d_in[12];
    const float* fc2_w  = (const float*)d_in[13];
    const float* fc2_b  = (const float*)d_in[14];
    float* out = (float*)d_out;

    float *p_f2;
    cudaGetSymbolAddress((void**)&p_f2,  g_f2);
    __half *p_xn_h, *p_xn_l, *p_at_h, *p_y_h, *p_h1_h;
    cudaGetSymbolAddress((void**)&p_xn_h, g_xn_h);
    cudaGetSymbolAddress((void**)&p_xn_l, g_xn_l);
    cudaGetSymbolAddress((void**)&p_at_h, g_at_h);
    cudaGetSymbolAddress((void**)&p_y_h,  g_y_h);
    cudaGetSymbolAddress((void**)&p_h1_h, g_h1_h);
    __half *p_wqkv, *p_wprj, *p_wfc1, *p_wfc2;
    cudaGetSymbolAddress((void**)&p_wqkv, g_wqkv);
    cudaGetSymbolAddress((void**)&p_wprj, g_wprj);
    cudaGetSymbolAddress((void**)&p_wfc1, g_wfc1);
    cudaGetSymbolAddress((void**)&p_wfc2, g_wfc2);

    const int SMEM_BYTES = 2 * STAGEB;   // 61440
    static int init_done = 0;
    static cudaStream_t sB;
    static cudaEvent_t evFork, evJoin;
    if (!init_done) {
        cudaFuncSetAttribute(gemm_sp_kernel,
                             cudaFuncAttributeMaxDynamicSharedMemorySize, SMEM_BYTES);
        cudaStreamCreateWithFlags(&sB, cudaStreamNonBlocking);
        cudaEventCreateWithFlags(&evFork, cudaEventDisableTiming);
        cudaEventCreateWithFlags(&evJoin, cudaEventDisableTiming);
        init_done = 1;
    }

    const int nscan = (NN + SCAN_B - 1) / SCAN_B;
    const int MROWS = (NN + BM - 1) / BM;

    // fork side stream
    cudaEventRecord(evFork, 0);
    cudaStreamWaitEvent(sB, evFork, 0);

    // ---- stream B: CSR build + non-qkv weight rounds
    zero_cnt_kernel<<<(NN + 255) / 256, 256, 0, sB>>>();
    count_kernel<<<(MM + 255) / 256, 256, 0, sB>>>(ei);
    scan1_kernel<<<nscan, SCAN_B, 0, sB>>>();
    scan2_kernel<<<1, 128, 0, sB>>>(nscan);
    scan3_kernel<<<nscan, SCAN_B, 0, sB>>>();
    scatter_kernel<<<(MM + 255) / 256, 256, 0, sB>>>(ei);
    round_kernel<<<(CC*CC   + 255)/256, 256, 0, sB>>>(proj_w, p_wprj, CC*CC);
    round_kernel<<<(HIDN*CC + 255)/256, 256, 0, sB>>>(fc1_w, p_wfc1, HIDN*CC);
    round_kernel<<<(CC*HIDN + 255)/256, 256, 0, sB>>>(fc2_w, p_wfc2, CC*HIDN);
    cudaEventRecord(evJoin, sB);

    // ---- main stream: qkv path
    round_kernel<<<(3*CC*CC + 255)/256, 256>>>(qkv_w, p_wqkv, 3*CC*CC);
    ln_split_kernel<<<(NN + 7) / 8, 256>>>(feats, ln1_g, ln1_b, p_xn_h, p_xn_l);

    // qkv merged: q cols 2-term, k/v cols 1-term (auto per block)
    {
        dim3 grid(768 / BN, MROWS);
        gemm_sp_kernel<<<grid, 256, SMEM_BYTES>>>(p_xn_h, p_xn_l, p_wqkv,
                                                  qkv_b, nullptr, nullptr, nullptr,
                                                  NN, 768, CC, EPI_QKV, -1);
    }

    // join: attention needs CSR + qkv
    cudaStreamWaitEvent(0, evJoin, 0);

    attn_kernel<<<NN, 256>>>(p_at_h);

    // proj: 1-term
    {
        dim3 grid(CC / BN, MROWS);
        gemm_sp_kernel<<<grid, 256, SMEM_BYTES>>>(p_at_h, nullptr, p_wprj,
                                                  proj_b, feats, p_f2, nullptr,
                                                  NN, CC, CC, EPI_RES, 0);
    }

    // LN2 -> fp16 (hi only)
    ln_split_kernel<<<(NN + 7) / 8, 256>>>(p_f2, ln2_g, ln2_b, p_y_h, nullptr);

    // fc1 + gelu: 1-term
    {
        dim3 grid(HIDN / BN, MROWS);
        gemm_sp_kernel<<<grid, 256, SMEM_BYTES>>>(p_y_h, nullptr, p_wfc1,
                                                  fc1_b, nullptr, nullptr, p_h1_h,
                                                  NN, HIDN, CC, EPI_GELU, 0);
    }

    // fc2 + residual: 1-term
    {
        dim3 grid(CC / BN, MROWS);
        gemm_sp_kernel<<<grid, 256, SMEM_BYTES>>>(p_h1_h, nullptr, p_wfc2,
                                                  fc2_b, p_f2, out, nullptr,
                                                  NN, CC, HIDN, EPI_RES, 0);
    }
}